// round 5
// baseline (speedup 1.0000x reference)
#include <cuda_runtime.h>
#include <cstdint>

// Problem constants
#define BB   2
#define QQ   1024
#define MEMN 1024
#define UU   1024
#define HH   16
#define DHH  64
#define KL   2048   // MEM + Q

// ---------------------------------------------------------------------------
// Scratch (allocation-free: __device__ globals)
// ---------------------------------------------------------------------------
__device__ float g_full[(size_t)BB * KL * UU];           // rounded concat
__device__ float g_relr[(size_t)BB * KL * UU];           // rounded relatives
__device__ float g_qc  [(size_t)BB * QQ * UU];           // rounded q + bias_c
__device__ float g_qr  [(size_t)BB * QQ * UU];           // rounded q + bias_r
__device__ float g_wkv [(size_t)BB * KL * 2 * UU];       // rounded k|v
__device__ float g_wr  [(size_t)BB * KL * UU];           // rounded w_r
__device__ float g_sr  [(size_t)BB * HH * QQ * KL];      // Sr unshifted (fp32)
__device__ float g_ctx [(size_t)BB * QQ * UU];           // rounded attention out
__device__ float g_wqT [(size_t)UU * UU];
__device__ float g_wkvT[(size_t)2 * UU * UU];
__device__ float g_wrT [(size_t)UU * UU];
__device__ float g_woT [(size_t)UU * UU];
__device__ float g_vt  [(size_t)BB * HH * DHH * KL];     // V^T per head [b,h,d,t]

// ---------------------------------------------------------------------------
// Helpers
// ---------------------------------------------------------------------------
__device__ __forceinline__ uint32_t smem_to_u32(const void* p) {
    uint32_t a;
    asm("{ .reg .u64 t; cvta.to.shared.u64 t, %1; cvt.u32.u64 %0, t; }" : "=r"(a) : "l"(p));
    return a;
}
__device__ __forceinline__ float tf32r(float x) {
    float y;
    asm("cvt.rna.tf32.f32 %0, %1;" : "=f"(y) : "f"(x));
    return y;
}
__device__ __forceinline__ void cp_async16(uint32_t saddr, const void* gaddr) {
    asm volatile("cp.async.cg.shared.global [%0], [%1], 16;" :: "r"(saddr), "l"(gaddr));
}
#define CP_COMMIT() asm volatile("cp.async.commit_group;" ::: "memory")
#define CP_WAIT1()  asm volatile("cp.async.wait_group 1;" ::: "memory")

__device__ __forceinline__ void mma_tf32(float acc[4], const uint32_t a[4], const uint32_t b[2]) {
    asm volatile("mma.sync.aligned.m16n8k8.row.col.f32.tf32.tf32.f32 "
        "{%0,%1,%2,%3}, {%4,%5,%6,%7}, {%8,%9}, {%0,%1,%2,%3};"
        : "+f"(acc[0]), "+f"(acc[1]), "+f"(acc[2]), "+f"(acc[3])
        : "r"(a[0]), "r"(a[1]), "r"(a[2]), "r"(a[3]), "r"(b[0]), "r"(b[1]));
}

// ---------------------------------------------------------------------------
// concat(memories, inputs) -> g_full (tf32-rounded)
// ---------------------------------------------------------------------------
__global__ void concat_kernel(const float* __restrict__ mem,
                              const float* __restrict__ inp) {
    size_t i = (size_t)blockIdx.x * blockDim.x + threadIdx.x;
    const size_t total4 = (size_t)BB * KL * UU / 4;
    if (i >= total4) return;
    size_t elem = i * 4;
    int b = (int)(elem / ((size_t)KL * UU));
    size_t rem = elem % ((size_t)KL * UU);
    int t = (int)(rem / UU);
    int u = (int)(rem % UU);
    float4 v;
    if (t < MEMN) v = *(const float4*)(mem + ((size_t)b * MEMN + t) * UU + u);
    else          v = *(const float4*)(inp + ((size_t)b * QQ + (t - MEMN)) * UU + u);
    v.x = tf32r(v.x); v.y = tf32r(v.y); v.z = tf32r(v.z); v.w = tf32r(v.w);
    ((float4*)g_full)[i] = v;
}

__global__ void roundcopy_kernel(const float* __restrict__ in, float* __restrict__ out,
                                 size_t total4) {
    size_t i = (size_t)blockIdx.x * blockDim.x + threadIdx.x;
    if (i >= total4) return;
    float4 v = ((const float4*)in)[i];
    v.x = tf32r(v.x); v.y = tf32r(v.y); v.z = tf32r(v.z); v.w = tf32r(v.w);
    ((float4*)out)[i] = v;
}

// ---------------------------------------------------------------------------
// Batched strided transpose with tf32 rounding: out[c, r] = tf32(in[r, c])
// ---------------------------------------------------------------------------
__global__ void transpose_kernel(const float* __restrict__ in, float* __restrict__ out,
                                 int ld_in, int ld_out,
                                 long long sIn1, long long sIn2,
                                 long long sOut1, long long sOut2, int innerB) {
    __shared__ float t[32][33];
    int z = blockIdx.z, z1 = z / innerB, z2 = z % innerB;
    in  += (size_t)z1 * sIn1  + (size_t)z2 * sIn2;
    out += (size_t)z1 * sOut1 + (size_t)z2 * sOut2;
    int r0 = blockIdx.y * 32, c0 = blockIdx.x * 32;
    int tx = threadIdx.x, ty = threadIdx.y;
#pragma unroll
    for (int i = 0; i < 32; i += 8)
        t[ty + i][tx] = in[(size_t)(r0 + ty + i) * ld_in + c0 + tx];
    __syncthreads();
#pragma unroll
    for (int i = 0; i < 32; i += 8)
        out[(size_t)(c0 + ty + i) * ld_out + r0 + tx] = tf32r(t[tx][ty + i]);
}

// ---------------------------------------------------------------------------
// tf32 mma.sync GEMM:  C[m,n] = sum_k A[m,k] * B[n,k]
//   EPI: 0 = plain fp32 out, 1 = tf32-rounded out,
//        2 = dual output: C = tf32(acc + bc[n]), C2 = tf32(acc + br[n])
// ---------------------------------------------------------------------------
template <int BM, int BN, int WM, int WN, int EPI>
__global__ void __launch_bounds__(256)
mma_gemm(const float* __restrict__ A, int lda, long long sA1, long long sA2,
         const float* __restrict__ B, int ldb, long long sB1, long long sB2,
         float* __restrict__ C, int ldc, long long sC1, long long sC2,
         int K, int innerB,
         float* __restrict__ C2, const float* __restrict__ bc, const float* __restrict__ br) {
    constexpr int KC = 16;
    constexpr int LDSS = 20;
    constexpr int WARPS_M = BM / WM;
    constexpr int MFRAG = WM / 16;
    constexpr int NFRAG = WN / 8;
    static_assert((BM / WM) * (BN / WN) * 32 == 256, "warp layout");

    extern __shared__ float sm[];
    float* As = sm;
    float* Bs = sm + 3 * BM * LDSS;
    const uint32_t sA_base = smem_to_u32(As);
    const uint32_t sB_base = smem_to_u32(Bs);

    const int tid = threadIdx.x;
    const int lane = tid & 31;
    const int warp = tid >> 5;
    const int wm = warp % WARPS_M;
    const int wn = warp / WARPS_M;

    const int z = blockIdx.z;
    const int z1 = z / innerB, z2 = z % innerB;
    A += (size_t)z1 * sA1 + (size_t)z2 * sA2;
    B += (size_t)z1 * sB1 + (size_t)z2 * sB2;
    C += (size_t)z1 * sC1 + (size_t)z2 * sC2;
    if (EPI == 2) C2 += (size_t)z1 * sC1 + (size_t)z2 * sC2;
    const int bm = blockIdx.y * BM;
    const int bn = blockIdx.x * BN;
    const float* Ag = A + (size_t)bm * lda;
    const float* Bg = B + (size_t)bn * ldb;

    const int nIter = K / KC;

    auto load_stage = [&](int stage, int buf) {
#pragma unroll
        for (int i = 0; i < (BM * 4) / 256; i++) {
            int idx = tid + i * 256;
            int row = idx >> 2, ch = idx & 3;
            uint32_t s = sA_base + (uint32_t)(buf * BM * LDSS + row * LDSS + ch * 4) * 4u;
            cp_async16(s, Ag + (size_t)row * lda + stage * KC + ch * 4);
        }
#pragma unroll
        for (int i = 0; i < (BN * 4) / 256; i++) {
            int idx = tid + i * 256;
            int row = idx >> 2, ch = idx & 3;
            uint32_t s = sB_base + (uint32_t)(buf * BN * LDSS + row * LDSS + ch * 4) * 4u;
            cp_async16(s, Bg + (size_t)row * ldb + stage * KC + ch * 4);
        }
    };

    float acc[MFRAG][NFRAG][4];
#pragma unroll
    for (int i = 0; i < MFRAG; i++)
#pragma unroll
        for (int j = 0; j < NFRAG; j++)
#pragma unroll
            for (int v = 0; v < 4; v++) acc[i][j][v] = 0.0f;

    load_stage(0, 0); CP_COMMIT();
    if (nIter > 1) load_stage(1, 1);
    CP_COMMIT();

    const int r4 = lane >> 2;
    const int c4 = lane & 3;

    for (int it = 0; it < nIter; ++it) {
        CP_WAIT1();
        __syncthreads();
        if (it + 2 < nIter) load_stage(it + 2, (it + 2) % 3);
        CP_COMMIT();

        const float* a_ = As + (it % 3) * BM * LDSS + (wm * WM) * LDSS;
        const float* b_ = Bs + (it % 3) * BN * LDSS + (wn * WN) * LDSS;

#pragma unroll
        for (int k8 = 0; k8 < KC; k8 += 8) {
            uint32_t af[MFRAG][4];
            uint32_t bf[NFRAG][2];
#pragma unroll
            for (int fm = 0; fm < MFRAG; fm++) {
                const float* ap = a_ + (fm * 16 + r4) * LDSS + k8 + c4;
                af[fm][0] = __float_as_uint(ap[0]);
                af[fm][1] = __float_as_uint(ap[8 * LDSS]);
                af[fm][2] = __float_as_uint(ap[4]);
                af[fm][3] = __float_as_uint(ap[8 * LDSS + 4]);
            }
#pragma unroll
            for (int fn = 0; fn < NFRAG; fn++) {
                const float* bp = b_ + (fn * 8 + r4) * LDSS + k8 + c4;
                bf[fn][0] = __float_as_uint(bp[0]);
                bf[fn][1] = __float_as_uint(bp[4]);
            }
#pragma unroll
            for (int fm = 0; fm < MFRAG; fm++)
#pragma unroll
                for (int fn = 0; fn < NFRAG; fn++)
                    mma_tf32(acc[fm][fn], af[fm], bf[fn]);
        }
    }

    const int m0 = bm + wm * WM;
    const int n0 = bn + wn * WN;
#pragma unroll
    for (int fm = 0; fm < MFRAG; fm++) {
#pragma unroll
        for (int fn = 0; fn < NFRAG; fn++) {
            int r = m0 + fm * 16 + r4;
            int cidx = n0 + fn * 8 + c4 * 2;
            float a0 = acc[fm][fn][0], a1 = acc[fm][fn][1];
            float a2 = acc[fm][fn][2], a3 = acc[fm][fn][3];
            if (EPI == 0) {
                *(float2*)(C + (size_t)r * ldc + cidx) = make_float2(a0, a1);
                *(float2*)(C + (size_t)(r + 8) * ldc + cidx) = make_float2(a2, a3);
            } else if (EPI == 1) {
                *(float2*)(C + (size_t)r * ldc + cidx) = make_float2(tf32r(a0), tf32r(a1));
                *(float2*)(C + (size_t)(r + 8) * ldc + cidx) = make_float2(tf32r(a2), tf32r(a3));
            } else {
                float b0 = bc[cidx], b1 = bc[cidx + 1];
                float r0 = br[cidx], r1 = br[cidx + 1];
                *(float2*)(C  + (size_t)r * ldc + cidx) = make_float2(tf32r(a0 + b0), tf32r(a1 + b1));
                *(float2*)(C  + (size_t)(r + 8) * ldc + cidx) = make_float2(tf32r(a2 + b0), tf32r(a3 + b1));
                *(float2*)(C2 + (size_t)r * ldc + cidx) = make_float2(tf32r(a0 + r0), tf32r(a1 + r1));
                *(float2*)(C2 + (size_t)(r + 8) * ldc + cidx) = make_float2(tf32r(a2 + r0), tf32r(a3 + r1));
            }
        }
    }
}

// ---------------------------------------------------------------------------
// Fused flash attention: Sc = Qc K^T (mma), + Sr (shifted gmem read),
// online softmax, O += P V (mma). Never materializes Sc or P in HBM.
// Grid (8 qtiles, H, B), 256 threads = 8 warps x 16 rows each.
// ---------------------------------------------------------------------------
__global__ void __launch_bounds__(256) flash_kernel() {
    extern __shared__ float sm[];
    float* sQ  = sm;                    // [128][68]
    float* sKa = sQ  + 128 * 68;        // [128][68]
    float* sKb = sKa + 128 * 68;        // [128][68]
    float* sV  = sKb + 128 * 68;        // [64][132]
    float* sP  = sV  + 64 * 132;        // [128][132]
    const uint32_t uQ  = smem_to_u32(sQ);
    const uint32_t uKa = smem_to_u32(sKa);
    const uint32_t uKb = smem_to_u32(sKb);
    const uint32_t uV  = smem_to_u32(sV);

    const int tid = threadIdx.x, lane = tid & 31, warp = tid >> 5;
    const int r4 = lane >> 2, c4 = lane & 3;
    const int qt = 7 - (int)blockIdx.x;        // heavy tiles first
    const int h = blockIdx.y, b = blockIdx.z;
    const int q0 = qt * 128;
    const int nT = 9 + qt;                     // causal key tiles

    const float* gQ = g_qc  + ((size_t)b * QQ + q0) * UU + h * 64;
    const float* gK = g_wkv + (size_t)b * KL * 2 * UU + h * 64;
    const float* gV = g_vt  + ((size_t)b * HH + h) * DHH * KL;
    const float* gS = g_sr  + ((size_t)b * HH + h) * QQ * KL;

    // group 0: Q tile + K tile 0 (each 128 rows x 64 floats = 2048 float4)
    // group 1: V tile 0 (64 rows x 128 floats = 2048 float4)
    {
        int i = tid;
#pragma unroll
        for (int rep = 0; rep < 8; rep++, i += 256) {
            int r = i >> 4, c = i & 15;
            cp_async16(uQ + (uint32_t)(r * 68 + c * 4) * 4u, gQ + (size_t)r * UU + c * 4);
        }
        i = tid;
#pragma unroll
        for (int rep = 0; rep < 8; rep++, i += 256) {
            int r = i >> 4, c = i & 15;
            cp_async16(uKa + (uint32_t)(r * 68 + c * 4) * 4u, gK + (size_t)r * 2 * UU + c * 4);
        }
        CP_COMMIT();
        i = tid;
#pragma unroll
        for (int rep = 0; rep < 8; rep++, i += 256) {
            int r = i >> 5, c = i & 31;
            cp_async16(uV + (uint32_t)(r * 132 + c * 4) * 4u, gV + (size_t)r * KL + c * 4);
        }
        CP_COMMIT();
    }

    const int lr0 = warp * 16 + r4;            // local row 0 of this lane
    const int qg0 = q0 + lr0, qg1 = qg0 + 8;   // global query rows
    const float* sr0 = gS + (size_t)qg0 * KL + (QQ - 1 - qg0);
    const float* sr1 = gS + (size_t)qg1 * KL + (QQ - 1 - qg1);

    float m0 = -1e30f, m1 = -1e30f, l0 = 0.f, l1 = 0.f;
    float accO[8][4];
#pragma unroll
    for (int f = 0; f < 8; f++)
#pragma unroll
        for (int v = 0; v < 4; v++) accO[f][v] = 0.f;

    for (int it = 0; it < nT; ++it) {
        const float* sK = (it & 1) ? sKb : sKa;
        CP_WAIT1();
        __syncthreads();

        // ---- phase 1: Sc = Qc @ K^T ----
        float accS[16][4];
#pragma unroll
        for (int f = 0; f < 16; f++)
#pragma unroll
            for (int v = 0; v < 4; v++) accS[f][v] = 0.f;
#pragma unroll
        for (int k8 = 0; k8 < 64; k8 += 8) {
            uint32_t a[4];
            const float* ap = sQ + lr0 * 68 + k8 + c4;
            a[0] = __float_as_uint(ap[0]);
            a[1] = __float_as_uint(ap[8 * 68]);
            a[2] = __float_as_uint(ap[4]);
            a[3] = __float_as_uint(ap[8 * 68 + 4]);
#pragma unroll
            for (int fn = 0; fn < 16; fn++) {
                const float* bp = sK + (fn * 8 + r4) * 68 + k8 + c4;
                uint32_t bb[2] = {__float_as_uint(bp[0]), __float_as_uint(bp[4])};
                mma_tf32(accS[fn], a, bb);
            }
        }

        // ---- prefetch next K into the other buffer ----
        {
            int kn = (it + 1 < nT) ? (it + 1) : (nT - 1);
            uint32_t dK = ((it + 1) & 1) ? uKb : uKa;
            const float* src = gK + (size_t)kn * 128 * 2 * UU;
            int i = tid;
#pragma unroll
            for (int rep = 0; rep < 8; rep++, i += 256) {
                int r = i >> 4, c = i & 15;
                cp_async16(dK + (uint32_t)(r * 68 + c * 4) * 4u, src + (size_t)r * 2 * UU + c * 4);
            }
            CP_COMMIT();
        }

        // ---- add shifted Sr, scale, mask; online softmax ----
        const int k0 = it * 128;
        const bool lastT = (it == nT - 1);
        const int lim0 = MEMN + qg0 - k0;      // local col limit (inclusive)
        const int lim1 = lim0 + 8;

        float rm0 = -1e30f, rm1 = -1e30f;
#pragma unroll
        for (int fn = 0; fn < 16; fn++) {
            int kc = fn * 8 + 2 * c4;
            float s0, s1, s2, s3;
            s0 = (!lastT || kc     <= lim0) ? (accS[fn][0] + __ldg(sr0 + k0 + kc))     * 0.125f : -1e30f;
            s1 = (!lastT || kc + 1 <= lim0) ? (accS[fn][1] + __ldg(sr0 + k0 + kc + 1)) * 0.125f : -1e30f;
            s2 = (!lastT || kc     <= lim1) ? (accS[fn][2] + __ldg(sr1 + k0 + kc))     * 0.125f : -1e30f;
            s3 = (!lastT || kc + 1 <= lim1) ? (accS[fn][3] + __ldg(sr1 + k0 + kc + 1)) * 0.125f : -1e30f;
            accS[fn][0] = s0; accS[fn][1] = s1; accS[fn][2] = s2; accS[fn][3] = s3;
            rm0 = fmaxf(rm0, fmaxf(s0, s1));
            rm1 = fmaxf(rm1, fmaxf(s2, s3));
        }
        rm0 = fmaxf(rm0, __shfl_xor_sync(~0u, rm0, 1));
        rm0 = fmaxf(rm0, __shfl_xor_sync(~0u, rm0, 2));
        rm1 = fmaxf(rm1, __shfl_xor_sync(~0u, rm1, 1));
        rm1 = fmaxf(rm1, __shfl_xor_sync(~0u, rm1, 2));
        float mN0 = fmaxf(m0, rm0), mN1 = fmaxf(m1, rm1);
        float al0 = __expf(m0 - mN0), al1 = __expf(m1 - mN1);
        m0 = mN0; m1 = mN1;

        float ps0 = 0.f, ps1 = 0.f;
        float* p0 = sP + lr0 * 132;
        float* p1 = p0 + 8 * 132;
#pragma unroll
        for (int fn = 0; fn < 16; fn++) {
            int kc = fn * 8 + 2 * c4;
            float e0 = __expf(accS[fn][0] - m0);
            float e1 = __expf(accS[fn][1] - m0);
            float e2 = __expf(accS[fn][2] - m1);
            float e3 = __expf(accS[fn][3] - m1);
            ps0 += e0 + e1; ps1 += e2 + e3;
            *(float2*)(p0 + kc) = make_float2(tf32r(e0), tf32r(e1));
            *(float2*)(p1 + kc) = make_float2(tf32r(e2), tf32r(e3));
        }
        ps0 += __shfl_xor_sync(~0u, ps0, 1); ps0 += __shfl_xor_sync(~0u, ps0, 2);
        ps1 += __shfl_xor_sync(~0u, ps1, 1); ps1 += __shfl_xor_sync(~0u, ps1, 2);
        l0 = l0 * al0 + ps0;
        l1 = l1 * al1 + ps1;
#pragma unroll
        for (int f = 0; f < 8; f++) {
            accO[f][0] *= al0; accO[f][1] *= al0;
            accO[f][2] *= al1; accO[f][3] *= al1;
        }
        __syncwarp();          // P rows are per-warp private

        CP_WAIT1();            // V tile ready
        __syncthreads();

        // ---- phase 2: O += P @ V ----
#pragma unroll
        for (int k8 = 0; k8 < 128; k8 += 8) {
            uint32_t a[4];
            const float* ap = sP + lr0 * 132 + k8 + c4;
            a[0] = __float_as_uint(ap[0]);
            a[1] = __float_as_uint(ap[8 * 132]);
            a[2] = __float_as_uint(ap[4]);
            a[3] = __float_as_uint(ap[8 * 132 + 4]);
#pragma unroll
            for (int fn = 0; fn < 8; fn++) {
                const float* bp = sV + (fn * 8 + r4) * 132 + k8 + c4;
                uint32_t bb[2] = {__float_as_uint(bp[0]), __float_as_uint(bp[4])};
                mma_tf32(accO[fn], a, bb);
            }
        }
        __syncthreads();       // everyone done reading sV

        // ---- prefetch next V (single buffer) ----
        {
            int vn = (it + 1 < nT) ? (it + 1) : (nT - 1);
            const float* src = gV + vn * 128;
            int i = tid;
#pragma unroll
            for (int rep = 0; rep < 8; rep++, i += 256) {
                int r = i >> 5, c = i & 31;
                cp_async16(uV + (uint32_t)(r * 132 + c * 4) * 4u, src + (size_t)r * KL + c * 4);
            }
            CP_COMMIT();
        }
    }

    // ---- epilogue: ctx = tf32(O / l) ----
    float i0 = 1.f / l0, i1 = 1.f / l1;
    float* gC0 = g_ctx + ((size_t)b * QQ + qg0) * UU + h * 64;
    float* gC1 = g_ctx + ((size_t)b * QQ + qg1) * UU + h * 64;
#pragma unroll
    for (int fn = 0; fn < 8; fn++) {
        int col = fn * 8 + 2 * c4;
        *(float2*)(gC0 + col) = make_float2(tf32r(accO[fn][0] * i0), tf32r(accO[fn][1] * i0));
        *(float2*)(gC1 + col) = make_float2(tf32r(accO[fn][2] * i1), tf32r(accO[fn][3] * i1));
    }
}

// ---------------------------------------------------------------------------
// Launch
// ---------------------------------------------------------------------------
extern "C" void kernel_launch(void* const* d_in, const int* in_sizes, int n_in,
                              void* d_out, int out_size) {
    const float* inputs    = (const float*)d_in[0];
    const float* relatives = (const float*)d_in[1];
    const float* memories  = (const float*)d_in[2];
    const float* bias_c    = (const float*)d_in[3];
    const float* bias_r    = (const float*)d_in[4];
    const float* Wq        = (const float*)d_in[5];
    const float* Wkv       = (const float*)d_in[6];
    const float* Wr        = (const float*)d_in[7];
    const float* Wo        = (const float*)d_in[8];
    float* out             = (float*)d_out;

    float *p_full, *p_relr, *p_qc, *p_qr, *p_wkv, *p_wr, *p_sr, *p_ctx;
    float *p_wqT, *p_wkvT, *p_wrT, *p_woT, *p_vt;
    cudaGetSymbolAddress((void**)&p_full, g_full);
    cudaGetSymbolAddress((void**)&p_relr, g_relr);
    cudaGetSymbolAddress((void**)&p_qc,   g_qc);
    cudaGetSymbolAddress((void**)&p_qr,   g_qr);
    cudaGetSymbolAddress((void**)&p_wkv,  g_wkv);
    cudaGetSymbolAddress((void**)&p_wr,   g_wr);
    cudaGetSymbolAddress((void**)&p_sr,   g_sr);
    cudaGetSymbolAddress((void**)&p_ctx,  g_ctx);
    cudaGetSymbolAddress((void**)&p_wqT,  g_wqT);
    cudaGetSymbolAddress((void**)&p_wkvT, g_wkvT);
    cudaGetSymbolAddress((void**)&p_wrT,  g_wrT);
    cudaGetSymbolAddress((void**)&p_woT,  g_woT);
    cudaGetSymbolAddress((void**)&p_vt,   g_vt);

    constexpr int SMEM_G = 3 * (128 + 128) * 20 * 4;              // 61440
    constexpr int SMEM_F = (3 * 128 * 68 + 64 * 132 + 128 * 132) * 4;  // 205824
    cudaFuncSetAttribute((const void*)mma_gemm<128,128,64,32,0>,
                         cudaFuncAttributeMaxDynamicSharedMemorySize, SMEM_G);
    cudaFuncSetAttribute((const void*)mma_gemm<128,128,64,32,1>,
                         cudaFuncAttributeMaxDynamicSharedMemorySize, SMEM_G);
    cudaFuncSetAttribute((const void*)mma_gemm<128,128,64,32,2>,
                         cudaFuncAttributeMaxDynamicSharedMemorySize, SMEM_G);
    cudaFuncSetAttribute((const void*)flash_kernel,
                         cudaFuncAttributeMaxDynamicSharedMemorySize, SMEM_F);

    dim3 tblk(32, 8);

    // 0. rounded transposed weights -> [N, K] K-major
    transpose_kernel<<<dim3(UU / 32, UU / 32, 1), tblk>>>(Wq, p_wqT, UU, UU, 0, 0, 0, 0, 1);
    transpose_kernel<<<dim3((2 * UU) / 32, UU / 32, 1), tblk>>>(Wkv, p_wkvT, 2 * UU, UU, 0, 0, 0, 0, 1);
    transpose_kernel<<<dim3(UU / 32, UU / 32, 1), tblk>>>(Wr, p_wrT, UU, UU, 0, 0, 0, 0, 1);
    transpose_kernel<<<dim3(UU / 32, UU / 32, 1), tblk>>>(Wo, p_woT, UU, UU, 0, 0, 0, 0, 1);

    // 1. full = tf32(concat);  relr = tf32(relatives)
    {
        size_t total4 = (size_t)BB * KL * UU / 4;
        concat_kernel<<<(unsigned)((total4 + 255) / 256), 256>>>(memories, inputs);
        roundcopy_kernel<<<(unsigned)((total4 + 255) / 256), 256>>>(relatives, p_relr, total4);
    }

    // 2. qc/qr = tf32(inputs @ Wq + bias_{c,r})  — bias fused in epilogue
    mma_gemm<128,128,64,32,2><<<dim3(UU/128, QQ/128, BB), 256, SMEM_G>>>(
        p_full + (size_t)MEMN * UU, UU, (long long)KL * UU, 0,
        p_wqT, UU, 0, 0,
        p_qc, UU, (long long)QQ * UU, 0, UU, 1,
        p_qr, bias_c, bias_r);

    // 3. w_kv = full @ Wkv  (rounded)
    mma_gemm<128,128,64,32,1><<<dim3((2*UU)/128, (BB*KL)/128, 1), 256, SMEM_G>>>(
        p_full, UU, 0, 0, p_wkvT, UU, 0, 0, p_wkv, 2*UU, 0, 0, UU, 1,
        nullptr, nullptr, nullptr);

    // 4. w_r = relatives @ Wr  (rounded)
    mma_gemm<128,128,64,32,1><<<dim3(UU/128, (BB*KL)/128, 1), 256, SMEM_G>>>(
        p_relr, UU, 0, 0, p_wrT, UU, 0, 0, p_wr, UU, 0, 0, UU, 1,
        nullptr, nullptr, nullptr);

    // 5. V^T per head: g_vt[b,h,d,t] = wkv[b, t, U + h*64 + d]
    transpose_kernel<<<dim3(DHH / 32, KL / 32, BB * HH), tblk>>>(
        p_wkv + UU, p_vt, 2 * UU, KL,
        (long long)KL * 2 * UU, 64,
        (long long)HH * DHH * KL, (long long)DHH * KL, HH);

    // 6. Sr[b,h] = qr(b,h) @ R(b,h)^T   (fp32 out, read shifted by flash)
    mma_gemm<128,128,64,32,0><<<dim3(KL/128, QQ/128, BB*HH), 256, SMEM_G>>>(
        p_qr, UU, (long long)QQ * UU, 64,
        p_wr, UU, (long long)KL * UU, 64,
        p_sr, KL, (long long)HH * QQ * KL, (long long)QQ * KL,
        DHH, HH, nullptr, nullptr, nullptr);

    // 7. fused Sc + shift + softmax + PV -> ctx (rounded)
    flash_kernel<<<dim3(8, HH, BB), 256, SMEM_F>>>();

    // 8. out = ctx @ Wo
    mma_gemm<128,128,64,32,0><<<dim3(UU/128, (BB*QQ)/128, 1), 256, SMEM_G>>>(
        p_ctx, UU, 0, 0, p_woT, UU, 0, 0, out, UU, 0, 0, UU, 1,
        nullptr, nullptr, nullptr);
}

// round 6
// speedup vs baseline: 1.0867x; 1.0867x over previous
#include <cuda_runtime.h>
#include <cstdint>

// Problem constants
#define BB   2
#define QQ   1024
#define MEMN 1024
#define UU   1024
#define HH   16
#define DHH  64
#define KL   2048   // MEM + Q
#define KSPLIT 3

// ---------------------------------------------------------------------------
// Scratch (allocation-free: __device__ globals)
// ---------------------------------------------------------------------------
__device__ float g_full[(size_t)BB * KL * UU];           // rounded concat
__device__ float g_relr[(size_t)BB * KL * UU];           // rounded relatives
__device__ float g_qc  [(size_t)BB * QQ * UU];           // rounded q + bias_c
__device__ float g_qr  [(size_t)BB * QQ * UU];           // rounded q + bias_r
__device__ float g_wkv [(size_t)BB * KL * 2 * UU];       // rounded k|v
__device__ float g_wr  [(size_t)BB * KL * UU];           // rounded w_r
__device__ float g_sr  [(size_t)BB * HH * QQ * KL];      // Sr unshifted (fp32)
__device__ float g_ctx [(size_t)BB * QQ * UU];           // rounded attention out
__device__ float g_wqT [(size_t)UU * UU];
__device__ float g_wkvT[(size_t)2 * UU * UU];
__device__ float g_wrT [(size_t)UU * UU];
__device__ float g_woT [(size_t)UU * UU];
__device__ float g_vt  [(size_t)BB * HH * DHH * KL];     // V^T per head [b,h,d,t]
__device__ float g_opart[(size_t)BB * HH * QQ * KSPLIT * DHH];  // 25 MB
__device__ float g_ml   [(size_t)BB * HH * QQ * KSPLIT * 2];    // 1.5 MB

// ---------------------------------------------------------------------------
// Helpers
// ---------------------------------------------------------------------------
__device__ __forceinline__ uint32_t smem_to_u32(const void* p) {
    uint32_t a;
    asm("{ .reg .u64 t; cvta.to.shared.u64 t, %1; cvt.u32.u64 %0, t; }" : "=r"(a) : "l"(p));
    return a;
}
__device__ __forceinline__ float tf32r(float x) {
    float y;
    asm("cvt.rna.tf32.f32 %0, %1;" : "=f"(y) : "f"(x));
    return y;
}
__device__ __forceinline__ void cp_async16(uint32_t saddr, const void* gaddr) {
    asm volatile("cp.async.cg.shared.global [%0], [%1], 16;" :: "r"(saddr), "l"(gaddr));
}
#define CP_COMMIT() asm volatile("cp.async.commit_group;" ::: "memory")
#define CP_WAIT1()  asm volatile("cp.async.wait_group 1;" ::: "memory")

__device__ __forceinline__ void mma_tf32(float acc[4], const uint32_t a[4], const uint32_t b[2]) {
    asm volatile("mma.sync.aligned.m16n8k8.row.col.f32.tf32.tf32.f32 "
        "{%0,%1,%2,%3}, {%4,%5,%6,%7}, {%8,%9}, {%0,%1,%2,%3};"
        : "+f"(acc[0]), "+f"(acc[1]), "+f"(acc[2]), "+f"(acc[3])
        : "r"(a[0]), "r"(a[1]), "r"(a[2]), "r"(a[3]), "r"(b[0]), "r"(b[1]));
}

// ---------------------------------------------------------------------------
// concat(memories, inputs) -> g_full (tf32-rounded)
// ---------------------------------------------------------------------------
__global__ void concat_kernel(const float* __restrict__ mem,
                              const float* __restrict__ inp) {
    size_t i = (size_t)blockIdx.x * blockDim.x + threadIdx.x;
    const size_t total4 = (size_t)BB * KL * UU / 4;
    if (i >= total4) return;
    size_t elem = i * 4;
    int b = (int)(elem / ((size_t)KL * UU));
    size_t rem = elem % ((size_t)KL * UU);
    int t = (int)(rem / UU);
    int u = (int)(rem % UU);
    float4 v;
    if (t < MEMN) v = *(const float4*)(mem + ((size_t)b * MEMN + t) * UU + u);
    else          v = *(const float4*)(inp + ((size_t)b * QQ + (t - MEMN)) * UU + u);
    v.x = tf32r(v.x); v.y = tf32r(v.y); v.z = tf32r(v.z); v.w = tf32r(v.w);
    ((float4*)g_full)[i] = v;
}

__global__ void roundcopy_kernel(const float* __restrict__ in, float* __restrict__ out,
                                 size_t total4) {
    size_t i = (size_t)blockIdx.x * blockDim.x + threadIdx.x;
    if (i >= total4) return;
    float4 v = ((const float4*)in)[i];
    v.x = tf32r(v.x); v.y = tf32r(v.y); v.z = tf32r(v.z); v.w = tf32r(v.w);
    ((float4*)out)[i] = v;
}

// ---------------------------------------------------------------------------
// Batched strided transpose with tf32 rounding: out[c, r] = tf32(in[r, c])
// ---------------------------------------------------------------------------
__global__ void transpose_kernel(const float* __restrict__ in, float* __restrict__ out,
                                 int ld_in, int ld_out,
                                 long long sIn1, long long sIn2,
                                 long long sOut1, long long sOut2, int innerB) {
    __shared__ float t[32][33];
    int z = blockIdx.z, z1 = z / innerB, z2 = z % innerB;
    in  += (size_t)z1 * sIn1  + (size_t)z2 * sIn2;
    out += (size_t)z1 * sOut1 + (size_t)z2 * sOut2;
    int r0 = blockIdx.y * 32, c0 = blockIdx.x * 32;
    int tx = threadIdx.x, ty = threadIdx.y;
#pragma unroll
    for (int i = 0; i < 32; i += 8)
        t[ty + i][tx] = in[(size_t)(r0 + ty + i) * ld_in + c0 + tx];
    __syncthreads();
#pragma unroll
    for (int i = 0; i < 32; i += 8)
        out[(size_t)(c0 + ty + i) * ld_out + r0 + tx] = tf32r(t[tx][ty + i]);
}

// ---------------------------------------------------------------------------
// tf32 mma.sync GEMM:  C[m,n] = sum_k A[m,k] * B[n,k]
//   EPI: 0 = plain fp32 out, 1 = tf32-rounded out,
//        2 = dual output: C = tf32(acc + bc[n]), C2 = tf32(acc + br[n])
// ---------------------------------------------------------------------------
template <int BM, int BN, int WM, int WN, int EPI>
__global__ void __launch_bounds__(256)
mma_gemm(const float* __restrict__ A, int lda, long long sA1, long long sA2,
         const float* __restrict__ B, int ldb, long long sB1, long long sB2,
         float* __restrict__ C, int ldc, long long sC1, long long sC2,
         int K, int innerB,
         float* __restrict__ C2, const float* __restrict__ bc, const float* __restrict__ br) {
    constexpr int KC = 16;
    constexpr int LDSS = 20;
    constexpr int WARPS_M = BM / WM;
    constexpr int MFRAG = WM / 16;
    constexpr int NFRAG = WN / 8;
    static_assert((BM / WM) * (BN / WN) * 32 == 256, "warp layout");

    extern __shared__ float sm[];
    float* As = sm;
    float* Bs = sm + 3 * BM * LDSS;
    const uint32_t sA_base = smem_to_u32(As);
    const uint32_t sB_base = smem_to_u32(Bs);

    const int tid = threadIdx.x;
    const int lane = tid & 31;
    const int warp = tid >> 5;
    const int wm = warp % WARPS_M;
    const int wn = warp / WARPS_M;

    const int z = blockIdx.z;
    const int z1 = z / innerB, z2 = z % innerB;
    A += (size_t)z1 * sA1 + (size_t)z2 * sA2;
    B += (size_t)z1 * sB1 + (size_t)z2 * sB2;
    C += (size_t)z1 * sC1 + (size_t)z2 * sC2;
    if (EPI == 2) C2 += (size_t)z1 * sC1 + (size_t)z2 * sC2;
    const int bm = blockIdx.y * BM;
    const int bn = blockIdx.x * BN;
    const float* Ag = A + (size_t)bm * lda;
    const float* Bg = B + (size_t)bn * ldb;

    const int nIter = K / KC;

    auto load_stage = [&](int stage, int buf) {
#pragma unroll
        for (int i = 0; i < (BM * 4) / 256; i++) {
            int idx = tid + i * 256;
            int row = idx >> 2, ch = idx & 3;
            uint32_t s = sA_base + (uint32_t)(buf * BM * LDSS + row * LDSS + ch * 4) * 4u;
            cp_async16(s, Ag + (size_t)row * lda + stage * KC + ch * 4);
        }
#pragma unroll
        for (int i = 0; i < (BN * 4) / 256; i++) {
            int idx = tid + i * 256;
            int row = idx >> 2, ch = idx & 3;
            uint32_t s = sB_base + (uint32_t)(buf * BN * LDSS + row * LDSS + ch * 4) * 4u;
            cp_async16(s, Bg + (size_t)row * ldb + stage * KC + ch * 4);
        }
    };

    float acc[MFRAG][NFRAG][4];
#pragma unroll
    for (int i = 0; i < MFRAG; i++)
#pragma unroll
        for (int j = 0; j < NFRAG; j++)
#pragma unroll
            for (int v = 0; v < 4; v++) acc[i][j][v] = 0.0f;

    load_stage(0, 0); CP_COMMIT();
    if (nIter > 1) load_stage(1, 1);
    CP_COMMIT();

    const int r4 = lane >> 2;
    const int c4 = lane & 3;

    for (int it = 0; it < nIter; ++it) {
        CP_WAIT1();
        __syncthreads();
        if (it + 2 < nIter) load_stage(it + 2, (it + 2) % 3);
        CP_COMMIT();

        const float* a_ = As + (it % 3) * BM * LDSS + (wm * WM) * LDSS;
        const float* b_ = Bs + (it % 3) * BN * LDSS + (wn * WN) * LDSS;

#pragma unroll
        for (int k8 = 0; k8 < KC; k8 += 8) {
            uint32_t af[MFRAG][4];
            uint32_t bf[NFRAG][2];
#pragma unroll
            for (int fm = 0; fm < MFRAG; fm++) {
                const float* ap = a_ + (fm * 16 + r4) * LDSS + k8 + c4;
                af[fm][0] = __float_as_uint(ap[0]);
                af[fm][1] = __float_as_uint(ap[8 * LDSS]);
                af[fm][2] = __float_as_uint(ap[4]);
                af[fm][3] = __float_as_uint(ap[8 * LDSS + 4]);
            }
#pragma unroll
            for (int fn = 0; fn < NFRAG; fn++) {
                const float* bp = b_ + (fn * 8 + r4) * LDSS + k8 + c4;
                bf[fn][0] = __float_as_uint(bp[0]);
                bf[fn][1] = __float_as_uint(bp[4]);
            }
#pragma unroll
            for (int fm = 0; fm < MFRAG; fm++)
#pragma unroll
                for (int fn = 0; fn < NFRAG; fn++)
                    mma_tf32(acc[fm][fn], af[fm], bf[fn]);
        }
    }

    const int m0 = bm + wm * WM;
    const int n0 = bn + wn * WN;
#pragma unroll
    for (int fm = 0; fm < MFRAG; fm++) {
#pragma unroll
        for (int fn = 0; fn < NFRAG; fn++) {
            int r = m0 + fm * 16 + r4;
            int cidx = n0 + fn * 8 + c4 * 2;
            float a0 = acc[fm][fn][0], a1 = acc[fm][fn][1];
            float a2 = acc[fm][fn][2], a3 = acc[fm][fn][3];
            if (EPI == 0) {
                *(float2*)(C + (size_t)r * ldc + cidx) = make_float2(a0, a1);
                *(float2*)(C + (size_t)(r + 8) * ldc + cidx) = make_float2(a2, a3);
            } else if (EPI == 1) {
                *(float2*)(C + (size_t)r * ldc + cidx) = make_float2(tf32r(a0), tf32r(a1));
                *(float2*)(C + (size_t)(r + 8) * ldc + cidx) = make_float2(tf32r(a2), tf32r(a3));
            } else {
                float b0 = bc[cidx], b1 = bc[cidx + 1];
                float r0 = br[cidx], r1 = br[cidx + 1];
                *(float2*)(C  + (size_t)r * ldc + cidx) = make_float2(tf32r(a0 + b0), tf32r(a1 + b1));
                *(float2*)(C  + (size_t)(r + 8) * ldc + cidx) = make_float2(tf32r(a2 + b0), tf32r(a3 + b1));
                *(float2*)(C2 + (size_t)r * ldc + cidx) = make_float2(tf32r(a0 + r0), tf32r(a1 + r1));
                *(float2*)(C2 + (size_t)(r + 8) * ldc + cidx) = make_float2(tf32r(a2 + r0), tf32r(a3 + r1));
            }
        }
    }
}

// ---------------------------------------------------------------------------
// Split-K fused flash attention. Each CTA handles key tiles [t0, t1) of one
// (b, h, q-tile); writes unnormalized O and per-row (m, l) to scratch.
// Grid (8 * KSPLIT, H, B), 256 threads.
// ---------------------------------------------------------------------------
__global__ void __launch_bounds__(256) flash_kernel() {
    extern __shared__ float sm[];
    float* sQ  = sm;                    // [128][68]
    float* sKa = sQ  + 128 * 68;        // [128][68]
    float* sKb = sKa + 128 * 68;        // [128][68]
    float* sV  = sKb + 128 * 68;        // [64][132]
    float* sP  = sV  + 64 * 132;        // [128][132]
    const uint32_t uQ  = smem_to_u32(sQ);
    const uint32_t uKa = smem_to_u32(sKa);
    const uint32_t uKb = smem_to_u32(sKb);
    const uint32_t uV  = smem_to_u32(sV);

    const int tid = threadIdx.x, lane = tid & 31, warp = tid >> 5;
    const int r4 = lane >> 2, c4 = lane & 3;
    const int qs = (int)blockIdx.x;
    const int qt = 7 - (qs / KSPLIT);          // heavy q-tiles first
    const int split = qs % KSPLIT;
    const int h = blockIdx.y, b = blockIdx.z;
    const int q0 = qt * 128;
    const int nT = 9 + qt;                     // causal key tiles for this q-tile
    const int t0 = (split * nT) / KSPLIT;
    const int t1 = ((split + 1) * nT) / KSPLIT;

    const float* gQ = g_qc  + ((size_t)b * QQ + q0) * UU + h * 64;
    const float* gK = g_wkv + (size_t)b * KL * 2 * UU + h * 64;
    const float* gV = g_vt  + ((size_t)b * HH + h) * DHH * KL;
    const float* gS = g_sr  + ((size_t)b * HH + h) * QQ * KL;

    // group 0: Q tile + K tile t0 ; group 1: V tile t0
    {
        int i = tid;
#pragma unroll
        for (int rep = 0; rep < 8; rep++, i += 256) {
            int r = i >> 4, c = i & 15;
            cp_async16(uQ + (uint32_t)(r * 68 + c * 4) * 4u, gQ + (size_t)r * UU + c * 4);
        }
        const float* srcK = gK + (size_t)t0 * 128 * 2 * UU;
        i = tid;
#pragma unroll
        for (int rep = 0; rep < 8; rep++, i += 256) {
            int r = i >> 4, c = i & 15;
            cp_async16(uKa + (uint32_t)(r * 68 + c * 4) * 4u, srcK + (size_t)r * 2 * UU + c * 4);
        }
        CP_COMMIT();
        const float* srcV = gV + (size_t)t0 * 128;
        i = tid;
#pragma unroll
        for (int rep = 0; rep < 8; rep++, i += 256) {
            int r = i >> 5, c = i & 31;
            cp_async16(uV + (uint32_t)(r * 132 + c * 4) * 4u, srcV + (size_t)r * KL + c * 4);
        }
        CP_COMMIT();
    }

    const int lr0 = warp * 16 + r4;            // local row 0 of this lane
    const int qg0 = q0 + lr0, qg1 = qg0 + 8;   // global query rows
    const float* sr0 = gS + (size_t)qg0 * KL + (QQ - 1 - qg0);
    const float* sr1 = gS + (size_t)qg1 * KL + (QQ - 1 - qg1);

    float m0 = -1e30f, m1 = -1e30f, l0 = 0.f, l1 = 0.f;
    float accO[8][4];
#pragma unroll
    for (int f = 0; f < 8; f++)
#pragma unroll
        for (int v = 0; v < 4; v++) accO[f][v] = 0.f;

    for (int it = t0; it < t1; ++it) {
        const int li = it - t0;                // local index drives buffer parity
        const float* sK = (li & 1) ? sKb : sKa;
        CP_WAIT1();
        __syncthreads();

        // ---- phase 1: Sc = Qc @ K^T ----
        float accS[16][4];
#pragma unroll
        for (int f = 0; f < 16; f++)
#pragma unroll
            for (int v = 0; v < 4; v++) accS[f][v] = 0.f;
#pragma unroll
        for (int k8 = 0; k8 < 64; k8 += 8) {
            uint32_t a[4];
            const float* ap = sQ + lr0 * 68 + k8 + c4;
            a[0] = __float_as_uint(ap[0]);
            a[1] = __float_as_uint(ap[8 * 68]);
            a[2] = __float_as_uint(ap[4]);
            a[3] = __float_as_uint(ap[8 * 68 + 4]);
#pragma unroll
            for (int fn = 0; fn < 16; fn++) {
                const float* bp = sK + (fn * 8 + r4) * 68 + k8 + c4;
                uint32_t bb[2] = {__float_as_uint(bp[0]), __float_as_uint(bp[4])};
                mma_tf32(accS[fn], a, bb);
            }
        }

        // ---- prefetch next K into the other buffer ----
        {
            int kn = (it + 1 < t1) ? (it + 1) : (t1 - 1);
            uint32_t dK = ((li + 1) & 1) ? uKb : uKa;
            const float* src = gK + (size_t)kn * 128 * 2 * UU;
            int i = tid;
#pragma unroll
            for (int rep = 0; rep < 8; rep++, i += 256) {
                int r = i >> 4, c = i & 15;
                cp_async16(dK + (uint32_t)(r * 68 + c * 4) * 4u, src + (size_t)r * 2 * UU + c * 4);
            }
            CP_COMMIT();
        }

        // ---- add shifted Sr, scale, mask; online softmax ----
        const int k0 = it * 128;
        const bool lastT = (it == nT - 1);
        const int lim0 = MEMN + qg0 - k0;      // local col limit (inclusive)
        const int lim1 = lim0 + 8;

        float rm0 = -1e30f, rm1 = -1e30f;
#pragma unroll
        for (int fn = 0; fn < 16; fn++) {
            int kc = fn * 8 + 2 * c4;
            float s0, s1, s2, s3;
            s0 = (!lastT || kc     <= lim0) ? (accS[fn][0] + __ldg(sr0 + k0 + kc))     * 0.125f : -1e30f;
            s1 = (!lastT || kc + 1 <= lim0) ? (accS[fn][1] + __ldg(sr0 + k0 + kc + 1)) * 0.125f : -1e30f;
            s2 = (!lastT || kc     <= lim1) ? (accS[fn][2] + __ldg(sr1 + k0 + kc))     * 0.125f : -1e30f;
            s3 = (!lastT || kc + 1 <= lim1) ? (accS[fn][3] + __ldg(sr1 + k0 + kc + 1)) * 0.125f : -1e30f;
            accS[fn][0] = s0; accS[fn][1] = s1; accS[fn][2] = s2; accS[fn][3] = s3;
            rm0 = fmaxf(rm0, fmaxf(s0, s1));
            rm1 = fmaxf(rm1, fmaxf(s2, s3));
        }
        rm0 = fmaxf(rm0, __shfl_xor_sync(~0u, rm0, 1));
        rm0 = fmaxf(rm0, __shfl_xor_sync(~0u, rm0, 2));
        rm1 = fmaxf(rm1, __shfl_xor_sync(~0u, rm1, 1));
        rm1 = fmaxf(rm1, __shfl_xor_sync(~0u, rm1, 2));
        float mN0 = fmaxf(m0, rm0), mN1 = fmaxf(m1, rm1);
        float al0 = __expf(m0 - mN0), al1 = __expf(m1 - mN1);
        m0 = mN0; m1 = mN1;

        float ps0 = 0.f, ps1 = 0.f;
        float* p0 = sP + lr0 * 132;
        float* p1 = p0 + 8 * 132;
#pragma unroll
        for (int fn = 0; fn < 16; fn++) {
            int kc = fn * 8 + 2 * c4;
            float e0 = __expf(accS[fn][0] - m0);
            float e1 = __expf(accS[fn][1] - m0);
            float e2 = __expf(accS[fn][2] - m1);
            float e3 = __expf(accS[fn][3] - m1);
            ps0 += e0 + e1; ps1 += e2 + e3;
            *(float2*)(p0 + kc) = make_float2(tf32r(e0), tf32r(e1));
            *(float2*)(p1 + kc) = make_float2(tf32r(e2), tf32r(e3));
        }
        ps0 += __shfl_xor_sync(~0u, ps0, 1); ps0 += __shfl_xor_sync(~0u, ps0, 2);
        ps1 += __shfl_xor_sync(~0u, ps1, 1); ps1 += __shfl_xor_sync(~0u, ps1, 2);
        l0 = l0 * al0 + ps0;
        l1 = l1 * al1 + ps1;
#pragma unroll
        for (int f = 0; f < 8; f++) {
            accO[f][0] *= al0; accO[f][1] *= al0;
            accO[f][2] *= al1; accO[f][3] *= al1;
        }
        __syncwarp();          // P rows are per-warp private

        CP_WAIT1();            // V tile ready
        __syncthreads();

        // ---- phase 2: O += P @ V ----
#pragma unroll
        for (int k8 = 0; k8 < 128; k8 += 8) {
            uint32_t a[4];
            const float* ap = sP + lr0 * 132 + k8 + c4;
            a[0] = __float_as_uint(ap[0]);
            a[1] = __float_as_uint(ap[8 * 132]);
            a[2] = __float_as_uint(ap[4]);
            a[3] = __float_as_uint(ap[8 * 132 + 4]);
#pragma unroll
            for (int fn = 0; fn < 8; fn++) {
                const float* bp = sV + (fn * 8 + r4) * 132 + k8 + c4;
                uint32_t bb[2] = {__float_as_uint(bp[0]), __float_as_uint(bp[4])};
                mma_tf32(accO[fn], a, bb);
            }
        }
        __syncthreads();       // everyone done reading sV

        // ---- prefetch next V (single buffer) ----
        {
            int vn = (it + 1 < t1) ? (it + 1) : (t1 - 1);
            const float* src = gV + (size_t)vn * 128;
            int i = tid;
#pragma unroll
            for (int rep = 0; rep < 8; rep++, i += 256) {
                int r = i >> 5, c = i & 31;
                cp_async16(uV + (uint32_t)(r * 132 + c * 4) * 4u, src + (size_t)r * KL + c * 4);
            }
            CP_COMMIT();
        }
    }

    // ---- epilogue: write unnormalized O, (m, l) per row ----
    const size_t base0 = ((size_t)b * HH + h) * QQ + qg0;
    const size_t base1 = base0 + 8;
    float* o0 = g_opart + (base0 * KSPLIT + split) * DHH;
    float* o1 = g_opart + (base1 * KSPLIT + split) * DHH;
#pragma unroll
    for (int fn = 0; fn < 8; fn++) {
        int col = fn * 8 + 2 * c4;
        *(float2*)(o0 + col) = make_float2(accO[fn][0], accO[fn][1]);
        *(float2*)(o1 + col) = make_float2(accO[fn][2], accO[fn][3]);
    }
    if (c4 == 0) {
        float* ml0 = g_ml + (base0 * KSPLIT + split) * 2;
        float* ml1 = g_ml + (base1 * KSPLIT + split) * 2;
        ml0[0] = m0; ml0[1] = l0;
        ml1[0] = m1; ml1[1] = l1;
    }
}

// ---------------------------------------------------------------------------
// Combine split-K partials: ctx = tf32( sum_s O_s e^{m_s-m*} / L )
// Block 256 = 4 rows x 64 cols; grid (QQ/4, HH, BB).
// ---------------------------------------------------------------------------
__global__ void __launch_bounds__(256) combine_kernel() {
    const int col = threadIdx.x & 63;
    const int rloc = threadIdx.x >> 6;
    const int q = blockIdx.x * 4 + rloc;
    const int h = blockIdx.y, b = blockIdx.z;
    const size_t base = ((size_t)b * HH + h) * QQ + q;

    float m[KSPLIT], l[KSPLIT];
#pragma unroll
    for (int s = 0; s < KSPLIT; s++) {
        m[s] = g_ml[(base * KSPLIT + s) * 2 + 0];
        l[s] = g_ml[(base * KSPLIT + s) * 2 + 1];
    }
    float mx = m[0];
#pragma unroll
    for (int s = 1; s < KSPLIT; s++) mx = fmaxf(mx, m[s]);
    float w[KSPLIT], L = 0.f;
#pragma unroll
    for (int s = 0; s < KSPLIT; s++) { w[s] = __expf(m[s] - mx); L += l[s] * w[s]; }
    const float inv = 1.0f / L;

    float o = 0.f;
#pragma unroll
    for (int s = 0; s < KSPLIT; s++)
        o += g_opart[(base * KSPLIT + s) * DHH + col] * w[s];
    g_ctx[((size_t)b * QQ + q) * UU + h * 64 + col] = tf32r(o * inv);
}

// ---------------------------------------------------------------------------
// Launch
// ---------------------------------------------------------------------------
extern "C" void kernel_launch(void* const* d_in, const int* in_sizes, int n_in,
                              void* d_out, int out_size) {
    const float* inputs    = (const float*)d_in[0];
    const float* relatives = (const float*)d_in[1];
    const float* memories  = (const float*)d_in[2];
    const float* bias_c    = (const float*)d_in[3];
    const float* bias_r    = (const float*)d_in[4];
    const float* Wq        = (const float*)d_in[5];
    const float* Wkv       = (const float*)d_in[6];
    const float* Wr        = (const float*)d_in[7];
    const float* Wo        = (const float*)d_in[8];
    float* out             = (float*)d_out;

    float *p_full, *p_relr, *p_qc, *p_qr, *p_wkv, *p_wr, *p_sr, *p_ctx;
    float *p_wqT, *p_wkvT, *p_wrT, *p_woT, *p_vt;
    cudaGetSymbolAddress((void**)&p_full, g_full);
    cudaGetSymbolAddress((void**)&p_relr, g_relr);
    cudaGetSymbolAddress((void**)&p_qc,   g_qc);
    cudaGetSymbolAddress((void**)&p_qr,   g_qr);
    cudaGetSymbolAddress((void**)&p_wkv,  g_wkv);
    cudaGetSymbolAddress((void**)&p_wr,   g_wr);
    cudaGetSymbolAddress((void**)&p_sr,   g_sr);
    cudaGetSymbolAddress((void**)&p_ctx,  g_ctx);
    cudaGetSymbolAddress((void**)&p_wqT,  g_wqT);
    cudaGetSymbolAddress((void**)&p_wkvT, g_wkvT);
    cudaGetSymbolAddress((void**)&p_wrT,  g_wrT);
    cudaGetSymbolAddress((void**)&p_woT,  g_woT);
    cudaGetSymbolAddress((void**)&p_vt,   g_vt);

    constexpr int SMEM_G = 3 * (128 + 128) * 20 * 4;              // 61440
    constexpr int SMEM_F = (3 * 128 * 68 + 64 * 132 + 128 * 132) * 4;  // 205824
    cudaFuncSetAttribute((const void*)mma_gemm<128,128,64,32,0>,
                         cudaFuncAttributeMaxDynamicSharedMemorySize, SMEM_G);
    cudaFuncSetAttribute((const void*)mma_gemm<128,128,64,32,1>,
                         cudaFuncAttributeMaxDynamicSharedMemorySize, SMEM_G);
    cudaFuncSetAttribute((const void*)mma_gemm<128,128,64,32,2>,
                         cudaFuncAttributeMaxDynamicSharedMemorySize, SMEM_G);
    cudaFuncSetAttribute((const void*)flash_kernel,
                         cudaFuncAttributeMaxDynamicSharedMemorySize, SMEM_F);

    dim3 tblk(32, 8);

    // 0. rounded transposed weights -> [N, K] K-major
    transpose_kernel<<<dim3(UU / 32, UU / 32, 1), tblk>>>(Wq, p_wqT, UU, UU, 0, 0, 0, 0, 1);
    transpose_kernel<<<dim3((2 * UU) / 32, UU / 32, 1), tblk>>>(Wkv, p_wkvT, 2 * UU, UU, 0, 0, 0, 0, 1);
    transpose_kernel<<<dim3(UU / 32, UU / 32, 1), tblk>>>(Wr, p_wrT, UU, UU, 0, 0, 0, 0, 1);
    transpose_kernel<<<dim3(UU / 32, UU / 32, 1), tblk>>>(Wo, p_woT, UU, UU, 0, 0, 0, 0, 1);

    // 1. full = tf32(concat);  relr = tf32(relatives)
    {
        size_t total4 = (size_t)BB * KL * UU / 4;
        concat_kernel<<<(unsigned)((total4 + 255) / 256), 256>>>(memories, inputs);
        roundcopy_kernel<<<(unsigned)((total4 + 255) / 256), 256>>>(relatives, p_relr, total4);
    }

    // 2. qc/qr = tf32(inputs @ Wq + bias_{c,r})  — bias fused in epilogue
    mma_gemm<128,128,64,32,2><<<dim3(UU/128, QQ/128, BB), 256, SMEM_G>>>(
        p_full + (size_t)MEMN * UU, UU, (long long)KL * UU, 0,
        p_wqT, UU, 0, 0,
        p_qc, UU, (long long)QQ * UU, 0, UU, 1,
        p_qr, bias_c, bias_r);

    // 3. w_kv = full @ Wkv  (rounded)
    mma_gemm<128,128,64,32,1><<<dim3((2*UU)/128, (BB*KL)/128, 1), 256, SMEM_G>>>(
        p_full, UU, 0, 0, p_wkvT, UU, 0, 0, p_wkv, 2*UU, 0, 0, UU, 1,
        nullptr, nullptr, nullptr);

    // 4. w_r = relatives @ Wr  (rounded)
    mma_gemm<128,128,64,32,1><<<dim3(UU/128, (BB*KL)/128, 1), 256, SMEM_G>>>(
        p_relr, UU, 0, 0, p_wrT, UU, 0, 0, p_wr, UU, 0, 0, UU, 1,
        nullptr, nullptr, nullptr);

    // 5. V^T per head: g_vt[b,h,d,t] = wkv[b, t, U + h*64 + d]
    transpose_kernel<<<dim3(DHH / 32, KL / 32, BB * HH), tblk>>>(
        p_wkv + UU, p_vt, 2 * UU, KL,
        (long long)KL * 2 * UU, 64,
        (long long)HH * DHH * KL, (long long)DHH * KL, HH);

    // 6. Sr[b,h] = qr(b,h) @ R(b,h)^T   (fp32 out, read shifted by flash)
    mma_gemm<128,128,64,32,0><<<dim3(KL/128, QQ/128, BB*HH), 256, SMEM_G>>>(
        p_qr, UU, (long long)QQ * UU, 64,
        p_wr, UU, (long long)KL * UU, 64,
        p_sr, KL, (long long)HH * QQ * KL, (long long)QQ * KL,
        DHH, HH, nullptr, nullptr, nullptr);

    // 7. split-K fused Sc + shift + softmax + PV -> partials
    flash_kernel<<<dim3(8 * KSPLIT, HH, BB), 256, SMEM_F>>>();

    // 8. combine partials -> ctx (rounded)
    combine_kernel<<<dim3(QQ / 4, HH, BB), 256>>>();

    // 9. out = ctx @ Wo
    mma_gemm<128,128,64,32,0><<<dim3(UU/128, (BB*QQ)/128, 1), 256, SMEM_G>>>(
        p_ctx, UU, 0, 0, p_woT, UU, 0, 0, out, UU, 0, 0, UU, 1,
        nullptr, nullptr, nullptr);
}

// round 7
// speedup vs baseline: 1.2584x; 1.1580x over previous
#include <cuda_runtime.h>
#include <cuda_fp16.h>
#include <cstdint>

// Problem constants
#define BB   2
#define QQ   1024
#define MEMN 1024
#define UU   1024
#define HH   16
#define DHH  64
#define KL   2048   // MEM + Q
#define KSPLIT 3

// ---------------------------------------------------------------------------
// Scratch (allocation-free: __device__ globals)
// ---------------------------------------------------------------------------
__device__ float  g_full[(size_t)BB * KL * UU];           // rounded concat
__device__ float  g_relr[(size_t)BB * KL * UU];           // rounded relatives
__device__ float  g_qr  [(size_t)BB * QQ * UU];           // tf32 q + bias_r (fp32)
__device__ __half g_qch [(size_t)BB * QQ * UU];           // fp16 q + bias_c
__device__ __half g_kh  [(size_t)BB * KL * UU];           // fp16 K
__device__ float  g_v   [(size_t)BB * KL * UU];           // fp32 V (pre-transpose)
__device__ float  g_wr  [(size_t)BB * KL * UU];           // tf32 w_r
__device__ __half g_srh [(size_t)BB * HH * QQ * KL];      // fp16 Sr unshifted (128 MB)
__device__ float  g_ctx [(size_t)BB * QQ * UU];           // rounded attention out
__device__ float  g_wqT [(size_t)UU * UU];
__device__ float  g_wkvT[(size_t)2 * UU * UU];
__device__ float  g_wrT [(size_t)UU * UU];
__device__ float  g_woT [(size_t)UU * UU];
__device__ __half g_vth [(size_t)BB * HH * DHH * KL];     // fp16 V^T [b,h,d,t]
__device__ float  g_opart[(size_t)BB * HH * QQ * KSPLIT * DHH];
__device__ float  g_ml   [(size_t)BB * HH * QQ * KSPLIT * 2];

// ---------------------------------------------------------------------------
// Helpers
// ---------------------------------------------------------------------------
__device__ __forceinline__ uint32_t smem_to_u32(const void* p) {
    uint32_t a;
    asm("{ .reg .u64 t; cvta.to.shared.u64 t, %1; cvt.u32.u64 %0, t; }" : "=r"(a) : "l"(p));
    return a;
}
__device__ __forceinline__ float tf32r(float x) {
    float y;
    asm("cvt.rna.tf32.f32 %0, %1;" : "=f"(y) : "f"(x));
    return y;
}
__device__ __forceinline__ void cp_async16(uint32_t saddr, const void* gaddr) {
    asm volatile("cp.async.cg.shared.global [%0], [%1], 16;" :: "r"(saddr), "l"(gaddr));
}
#define CP_COMMIT() asm volatile("cp.async.commit_group;" ::: "memory")
#define CP_WAIT1()  asm volatile("cp.async.wait_group 1;" ::: "memory")

__device__ __forceinline__ void mma_tf32(float acc[4], const uint32_t a[4], const uint32_t b[2]) {
    asm volatile("mma.sync.aligned.m16n8k8.row.col.f32.tf32.tf32.f32 "
        "{%0,%1,%2,%3}, {%4,%5,%6,%7}, {%8,%9}, {%0,%1,%2,%3};"
        : "+f"(acc[0]), "+f"(acc[1]), "+f"(acc[2]), "+f"(acc[3])
        : "r"(a[0]), "r"(a[1]), "r"(a[2]), "r"(a[3]), "r"(b[0]), "r"(b[1]));
}
__device__ __forceinline__ void mma_f16(float acc[4], const uint32_t a[4], const uint32_t b[2]) {
    asm volatile("mma.sync.aligned.m16n8k16.row.col.f32.f16.f16.f32 "
        "{%0,%1,%2,%3}, {%4,%5,%6,%7}, {%8,%9}, {%0,%1,%2,%3};"
        : "+f"(acc[0]), "+f"(acc[1]), "+f"(acc[2]), "+f"(acc[3])
        : "r"(a[0]), "r"(a[1]), "r"(a[2]), "r"(a[3]), "r"(b[0]), "r"(b[1]));
}

// ---------------------------------------------------------------------------
// concat(memories, inputs) -> g_full (tf32-rounded)
// ---------------------------------------------------------------------------
__global__ void concat_kernel(const float* __restrict__ mem,
                              const float* __restrict__ inp) {
    size_t i = (size_t)blockIdx.x * blockDim.x + threadIdx.x;
    const size_t total4 = (size_t)BB * KL * UU / 4;
    if (i >= total4) return;
    size_t elem = i * 4;
    int b = (int)(elem / ((size_t)KL * UU));
    size_t rem = elem % ((size_t)KL * UU);
    int t = (int)(rem / UU);
    int u = (int)(rem % UU);
    float4 v;
    if (t < MEMN) v = *(const float4*)(mem + ((size_t)b * MEMN + t) * UU + u);
    else          v = *(const float4*)(inp + ((size_t)b * QQ + (t - MEMN)) * UU + u);
    v.x = tf32r(v.x); v.y = tf32r(v.y); v.z = tf32r(v.z); v.w = tf32r(v.w);
    ((float4*)g_full)[i] = v;
}

__global__ void roundcopy_kernel(const float* __restrict__ in, float* __restrict__ out,
                                 size_t total4) {
    size_t i = (size_t)blockIdx.x * blockDim.x + threadIdx.x;
    if (i >= total4) return;
    float4 v = ((const float4*)in)[i];
    v.x = tf32r(v.x); v.y = tf32r(v.y); v.z = tf32r(v.z); v.w = tf32r(v.w);
    ((float4*)out)[i] = v;
}

// ---------------------------------------------------------------------------
// Batched strided transpose: out[c, r] = cvt(in[r, c]); HALF selects fp16 out
// ---------------------------------------------------------------------------
template <bool HALF>
__global__ void transpose_kernel(const float* __restrict__ in, void* __restrict__ outv,
                                 int ld_in, int ld_out,
                                 long long sIn1, long long sIn2,
                                 long long sOut1, long long sOut2, int innerB) {
    __shared__ float t[32][33];
    int z = blockIdx.z, z1 = z / innerB, z2 = z % innerB;
    in += (size_t)z1 * sIn1 + (size_t)z2 * sIn2;
    int r0 = blockIdx.y * 32, c0 = blockIdx.x * 32;
    int tx = threadIdx.x, ty = threadIdx.y;
#pragma unroll
    for (int i = 0; i < 32; i += 8)
        t[ty + i][tx] = in[(size_t)(r0 + ty + i) * ld_in + c0 + tx];
    __syncthreads();
    if (HALF) {
        __half* out = (__half*)outv + (size_t)z1 * sOut1 + (size_t)z2 * sOut2;
#pragma unroll
        for (int i = 0; i < 32; i += 8)
            out[(size_t)(c0 + ty + i) * ld_out + r0 + tx] = __float2half(t[tx][ty + i]);
    } else {
        float* out = (float*)outv + (size_t)z1 * sOut1 + (size_t)z2 * sOut2;
#pragma unroll
        for (int i = 0; i < 32; i += 8)
            out[(size_t)(c0 + ty + i) * ld_out + r0 + tx] = tf32r(t[tx][ty + i]);
    }
}

// ---------------------------------------------------------------------------
// tf32 mma.sync GEMM:  C[m,n] = sum_k A[m,k] * B[n,k]
//  EPI: 0 plain fp32 | 1 tf32r fp32 | 2 qr=f32 tf32r(acc+br) & qc=f16 (acc+bc)
//       3 fp16 out   | 4 kv-split: col<U -> fp16 K (C2), col>=U -> fp32 V (C)
// ---------------------------------------------------------------------------
template <int BM, int BN, int WM, int WN, int EPI>
__global__ void __launch_bounds__(256)
mma_gemm(const float* __restrict__ A, int lda, long long sA1, long long sA2,
         const float* __restrict__ B, int ldb, long long sB1, long long sB2,
         float* __restrict__ C, int ldc, long long sC1, long long sC2,
         int K, int innerB,
         float* __restrict__ C2, const float* __restrict__ bc, const float* __restrict__ br) {
    constexpr int KC = 16;
    constexpr int LDSS = 20;
    constexpr int WARPS_M = BM / WM;
    constexpr int MFRAG = WM / 16;
    constexpr int NFRAG = WN / 8;
    static_assert((BM / WM) * (BN / WN) * 32 == 256, "warp layout");

    extern __shared__ float sm[];
    float* As = sm;
    float* Bs = sm + 3 * BM * LDSS;
    const uint32_t sA_base = smem_to_u32(As);
    const uint32_t sB_base = smem_to_u32(Bs);

    const int tid = threadIdx.x;
    const int lane = tid & 31;
    const int warp = tid >> 5;
    const int wm = warp % WARPS_M;
    const int wn = warp / WARPS_M;

    const int z = blockIdx.z;
    const int z1 = z / innerB, z2 = z % innerB;
    A += (size_t)z1 * sA1 + (size_t)z2 * sA2;
    B += (size_t)z1 * sB1 + (size_t)z2 * sB2;
    __half* Ch = nullptr;
    __half* C2h = nullptr;
    if (EPI == 3) {
        Ch = (__half*)C + (size_t)z1 * sC1 + (size_t)z2 * sC2;
    } else {
        C += (size_t)z1 * sC1 + (size_t)z2 * sC2;
    }
    if (EPI == 2) C2h = (__half*)C2 + (size_t)z1 * sC1 + (size_t)z2 * sC2;
    if (EPI == 4) C2h = (__half*)C2;
    const int bm = blockIdx.y * BM;
    const int bn = blockIdx.x * BN;
    const float* Ag = A + (size_t)bm * lda;
    const float* Bg = B + (size_t)bn * ldb;

    const int nIter = K / KC;

    auto load_stage = [&](int stage, int buf) {
#pragma unroll
        for (int i = 0; i < (BM * 4) / 256; i++) {
            int idx = tid + i * 256;
            int row = idx >> 2, ch = idx & 3;
            uint32_t s = sA_base + (uint32_t)(buf * BM * LDSS + row * LDSS + ch * 4) * 4u;
            cp_async16(s, Ag + (size_t)row * lda + stage * KC + ch * 4);
        }
#pragma unroll
        for (int i = 0; i < (BN * 4) / 256; i++) {
            int idx = tid + i * 256;
            int row = idx >> 2, ch = idx & 3;
            uint32_t s = sB_base + (uint32_t)(buf * BN * LDSS + row * LDSS + ch * 4) * 4u;
            cp_async16(s, Bg + (size_t)row * ldb + stage * KC + ch * 4);
        }
    };

    float acc[MFRAG][NFRAG][4];
#pragma unroll
    for (int i = 0; i < MFRAG; i++)
#pragma unroll
        for (int j = 0; j < NFRAG; j++)
#pragma unroll
            for (int v = 0; v < 4; v++) acc[i][j][v] = 0.0f;

    load_stage(0, 0); CP_COMMIT();
    if (nIter > 1) load_stage(1, 1);
    CP_COMMIT();

    const int r4 = lane >> 2;
    const int c4 = lane & 3;

    for (int it = 0; it < nIter; ++it) {
        CP_WAIT1();
        __syncthreads();
        if (it + 2 < nIter) load_stage(it + 2, (it + 2) % 3);
        CP_COMMIT();

        const float* a_ = As + (it % 3) * BM * LDSS + (wm * WM) * LDSS;
        const float* b_ = Bs + (it % 3) * BN * LDSS + (wn * WN) * LDSS;

#pragma unroll
        for (int k8 = 0; k8 < KC; k8 += 8) {
            uint32_t af[MFRAG][4];
            uint32_t bf[NFRAG][2];
#pragma unroll
            for (int fm = 0; fm < MFRAG; fm++) {
                const float* ap = a_ + (fm * 16 + r4) * LDSS + k8 + c4;
                af[fm][0] = __float_as_uint(ap[0]);
                af[fm][1] = __float_as_uint(ap[8 * LDSS]);
                af[fm][2] = __float_as_uint(ap[4]);
                af[fm][3] = __float_as_uint(ap[8 * LDSS + 4]);
            }
#pragma unroll
            for (int fn = 0; fn < NFRAG; fn++) {
                const float* bp = b_ + (fn * 8 + r4) * LDSS + k8 + c4;
                bf[fn][0] = __float_as_uint(bp[0]);
                bf[fn][1] = __float_as_uint(bp[4]);
            }
#pragma unroll
            for (int fm = 0; fm < MFRAG; fm++)
#pragma unroll
                for (int fn = 0; fn < NFRAG; fn++)
                    mma_tf32(acc[fm][fn], af[fm], bf[fn]);
        }
    }

    const int m0 = bm + wm * WM;
    const int n0 = bn + wn * WN;
#pragma unroll
    for (int fm = 0; fm < MFRAG; fm++) {
#pragma unroll
        for (int fn = 0; fn < NFRAG; fn++) {
            int r = m0 + fm * 16 + r4;
            int cidx = n0 + fn * 8 + c4 * 2;
            float a0 = acc[fm][fn][0], a1 = acc[fm][fn][1];
            float a2 = acc[fm][fn][2], a3 = acc[fm][fn][3];
            if (EPI == 0) {
                *(float2*)(C + (size_t)r * ldc + cidx) = make_float2(a0, a1);
                *(float2*)(C + (size_t)(r + 8) * ldc + cidx) = make_float2(a2, a3);
            } else if (EPI == 1) {
                *(float2*)(C + (size_t)r * ldc + cidx) = make_float2(tf32r(a0), tf32r(a1));
                *(float2*)(C + (size_t)(r + 8) * ldc + cidx) = make_float2(tf32r(a2), tf32r(a3));
            } else if (EPI == 2) {
                float b0 = bc[cidx], b1 = bc[cidx + 1];
                float r0 = br[cidx], r1 = br[cidx + 1];
                *(float2*)(C + (size_t)r * ldc + cidx) = make_float2(tf32r(a0 + r0), tf32r(a1 + r1));
                *(float2*)(C + (size_t)(r + 8) * ldc + cidx) = make_float2(tf32r(a2 + r0), tf32r(a3 + r1));
                *(__half2*)(C2h + (size_t)r * ldc + cidx) = __floats2half2_rn(a0 + b0, a1 + b1);
                *(__half2*)(C2h + (size_t)(r + 8) * ldc + cidx) = __floats2half2_rn(a2 + b0, a3 + b1);
            } else if (EPI == 3) {
                *(__half2*)(Ch + (size_t)r * ldc + cidx) = __floats2half2_rn(a0, a1);
                *(__half2*)(Ch + (size_t)(r + 8) * ldc + cidx) = __floats2half2_rn(a2, a3);
            } else {   // EPI == 4: kv split, ldc = UU
                if (cidx < UU) {
                    *(__half2*)(C2h + (size_t)r * UU + cidx) = __floats2half2_rn(a0, a1);
                    *(__half2*)(C2h + (size_t)(r + 8) * UU + cidx) = __floats2half2_rn(a2, a3);
                } else {
                    *(float2*)(C + (size_t)r * UU + cidx - UU) = make_float2(a0, a1);
                    *(float2*)(C + (size_t)(r + 8) * UU + cidx - UU) = make_float2(a2, a3);
                }
            }
        }
    }
}

// ---------------------------------------------------------------------------
// Split-K fused fp16 flash attention. Grid (8*KSPLIT, H, B), 256 threads.
// SMEM ~105 KB -> 2 CTAs/SM.
// ---------------------------------------------------------------------------
__global__ void __launch_bounds__(256, 2) flash_kernel() {
    extern __shared__ __half smh[];
    __half* sQ  = smh;                  // [128][72]
    __half* sKa = sQ  + 128 * 72;       // [128][72]
    __half* sKb = sKa + 128 * 72;       // [128][72]
    __half* sV  = sKb + 128 * 72;       // [64][136]
    __half* sP  = sV  + 64 * 136;       // [128][136]
    const uint32_t uQ  = smem_to_u32(sQ);
    const uint32_t uKa = smem_to_u32(sKa);
    const uint32_t uKb = smem_to_u32(sKb);
    const uint32_t uV  = smem_to_u32(sV);

    const int tid = threadIdx.x, lane = tid & 31, warp = tid >> 5;
    const int r4 = lane >> 2, c4 = lane & 3;
    const int qs = (int)blockIdx.x;
    const int qt = 7 - (qs / KSPLIT);
    const int split = qs % KSPLIT;
    const int h = blockIdx.y, b = blockIdx.z;
    const int q0 = qt * 128;
    const int nT = 9 + qt;
    const int t0 = (split * nT) / KSPLIT;
    const int t1 = ((split + 1) * nT) / KSPLIT;

    const __half* gQ = g_qch + ((size_t)b * QQ + q0) * UU + h * 64;
    const __half* gK = g_kh  + (size_t)b * KL * UU + h * 64;
    const __half* gV = g_vth + ((size_t)b * HH + h) * DHH * KL;
    const __half* gS = g_srh + ((size_t)b * HH + h) * QQ * KL;

    // group 0: Q tile + K tile t0 (128 rows x 64 halfs = 8 chunks/row)
    // group 1: V tile t0 (64 rows x 128 halfs = 16 chunks/row)
    {
        int i = tid;
#pragma unroll
        for (int rep = 0; rep < 4; rep++, i += 256) {
            int r = i >> 3, c = i & 7;
            cp_async16(uQ + (uint32_t)(r * 72 + c * 8) * 2u, gQ + (size_t)r * UU + c * 8);
        }
        const __half* srcK = gK + (size_t)t0 * 128 * UU;
        i = tid;
#pragma unroll
        for (int rep = 0; rep < 4; rep++, i += 256) {
            int r = i >> 3, c = i & 7;
            cp_async16(uKa + (uint32_t)(r * 72 + c * 8) * 2u, srcK + (size_t)r * UU + c * 8);
        }
        CP_COMMIT();
        const __half* srcV = gV + (size_t)t0 * 128;
        i = tid;
#pragma unroll
        for (int rep = 0; rep < 4; rep++, i += 256) {
            int r = i >> 4, c = i & 15;
            cp_async16(uV + (uint32_t)(r * 136 + c * 8) * 2u, srcV + (size_t)r * KL + c * 8);
        }
        CP_COMMIT();
    }

    const int lr0 = warp * 16 + r4;
    const int qg0 = q0 + lr0, qg1 = qg0 + 8;
    const __half* sr0 = gS + (size_t)qg0 * KL + (QQ - 1 - qg0);
    const __half* sr1 = gS + (size_t)qg1 * KL + (QQ - 1 - qg1);

    float m0 = -1e30f, m1 = -1e30f, l0 = 0.f, l1 = 0.f;
    float accO[8][4];
#pragma unroll
    for (int f = 0; f < 8; f++)
#pragma unroll
        for (int v = 0; v < 4; v++) accO[f][v] = 0.f;

    for (int it = t0; it < t1; ++it) {
        const int li = it - t0;
        const __half* sK = (li & 1) ? sKb : sKa;
        CP_WAIT1();
        __syncthreads();

        // ---- phase 1: Sc = Qc @ K^T (fp16 mma, K=64 -> 4 ksteps) ----
        float accS[16][4];
#pragma unroll
        for (int f = 0; f < 16; f++)
#pragma unroll
            for (int v = 0; v < 4; v++) accS[f][v] = 0.f;
#pragma unroll
        for (int ks = 0; ks < 4; ks++) {
            uint32_t a[4];
            const __half* ap = sQ + lr0 * 72 + ks * 16 + 2 * c4;
            a[0] = *(const uint32_t*)(ap);
            a[1] = *(const uint32_t*)(ap + 8 * 72);
            a[2] = *(const uint32_t*)(ap + 8);
            a[3] = *(const uint32_t*)(ap + 8 * 72 + 8);
#pragma unroll
            for (int fn = 0; fn < 16; fn++) {
                const __half* bp = sK + (fn * 8 + r4) * 72 + ks * 16 + 2 * c4;
                uint32_t bb[2] = {*(const uint32_t*)(bp), *(const uint32_t*)(bp + 8)};
                mma_f16(accS[fn], a, bb);
            }
        }

        // ---- prefetch next K ----
        {
            int kn = (it + 1 < t1) ? (it + 1) : (t1 - 1);
            uint32_t dK = ((li + 1) & 1) ? uKb : uKa;
            const __half* src = gK + (size_t)kn * 128 * UU;
            int i = tid;
#pragma unroll
            for (int rep = 0; rep < 4; rep++, i += 256) {
                int r = i >> 3, c = i & 7;
                cp_async16(dK + (uint32_t)(r * 72 + c * 8) * 2u, src + (size_t)r * UU + c * 8);
            }
            CP_COMMIT();
        }

        // ---- add shifted Sr (fp16), scale, mask; online softmax ----
        const int k0 = it * 128;
        const bool lastT = (it == nT - 1);
        const int lim0 = MEMN + qg0 - k0;
        const int lim1 = lim0 + 8;

        float rm0 = -1e30f, rm1 = -1e30f;
#pragma unroll
        for (int fn = 0; fn < 16; fn++) {
            int kc = fn * 8 + 2 * c4;
            float s0, s1, s2, s3;
            s0 = (!lastT || kc     <= lim0) ? (accS[fn][0] + __half2float(__ldg(sr0 + k0 + kc)))     * 0.125f : -1e30f;
            s1 = (!lastT || kc + 1 <= lim0) ? (accS[fn][1] + __half2float(__ldg(sr0 + k0 + kc + 1))) * 0.125f : -1e30f;
            s2 = (!lastT || kc     <= lim1) ? (accS[fn][2] + __half2float(__ldg(sr1 + k0 + kc)))     * 0.125f : -1e30f;
            s3 = (!lastT || kc + 1 <= lim1) ? (accS[fn][3] + __half2float(__ldg(sr1 + k0 + kc + 1))) * 0.125f : -1e30f;
            accS[fn][0] = s0; accS[fn][1] = s1; accS[fn][2] = s2; accS[fn][3] = s3;
            rm0 = fmaxf(rm0, fmaxf(s0, s1));
            rm1 = fmaxf(rm1, fmaxf(s2, s3));
        }
        rm0 = fmaxf(rm0, __shfl_xor_sync(~0u, rm0, 1));
        rm0 = fmaxf(rm0, __shfl_xor_sync(~0u, rm0, 2));
        rm1 = fmaxf(rm1, __shfl_xor_sync(~0u, rm1, 1));
        rm1 = fmaxf(rm1, __shfl_xor_sync(~0u, rm1, 2));
        float mN0 = fmaxf(m0, rm0), mN1 = fmaxf(m1, rm1);
        float al0 = __expf(m0 - mN0), al1 = __expf(m1 - mN1);
        m0 = mN0; m1 = mN1;

        float ps0 = 0.f, ps1 = 0.f;
        __half* p0 = sP + lr0 * 136;
        __half* p1 = p0 + 8 * 136;
#pragma unroll
        for (int fn = 0; fn < 16; fn++) {
            int kc = fn * 8 + 2 * c4;
            float e0 = __expf(accS[fn][0] - m0);
            float e1 = __expf(accS[fn][1] - m0);
            float e2 = __expf(accS[fn][2] - m1);
            float e3 = __expf(accS[fn][3] - m1);
            ps0 += e0 + e1; ps1 += e2 + e3;
            *(__half2*)(p0 + kc) = __floats2half2_rn(e0, e1);
            *(__half2*)(p1 + kc) = __floats2half2_rn(e2, e3);
        }
        ps0 += __shfl_xor_sync(~0u, ps0, 1); ps0 += __shfl_xor_sync(~0u, ps0, 2);
        ps1 += __shfl_xor_sync(~0u, ps1, 1); ps1 += __shfl_xor_sync(~0u, ps1, 2);
        l0 = l0 * al0 + ps0;
        l1 = l1 * al1 + ps1;
#pragma unroll
        for (int f = 0; f < 8; f++) {
            accO[f][0] *= al0; accO[f][1] *= al0;
            accO[f][2] *= al1; accO[f][3] *= al1;
        }
        __syncwarp();

        CP_WAIT1();            // V tile ready
        __syncthreads();

        // ---- phase 2: O += P @ V (fp16 mma, K=128 -> 8 ksteps) ----
#pragma unroll
        for (int ks = 0; ks < 8; ks++) {
            uint32_t a[4];
            const __half* ap = sP + lr0 * 136 + ks * 16 + 2 * c4;
            a[0] = *(const uint32_t*)(ap);
            a[1] = *(const uint32_t*)(ap + 8 * 136);
            a[2] = *(const uint32_t*)(ap + 8);
            a[3] = *(const uint32_t*)(ap + 8 * 136 + 8);
#pragma unroll
            for (int fn = 0; fn < 8; fn++) {
                const __half* bp = sV + (fn * 8 + r4) * 136 + ks * 16 + 2 * c4;
                uint32_t bb[2] = {*(const uint32_t*)(bp), *(const uint32_t*)(bp + 8)};
                mma_f16(accO[fn], a, bb);
            }
        }
        __syncthreads();

        // ---- prefetch next V ----
        {
            int vn = (it + 1 < t1) ? (it + 1) : (t1 - 1);
            const __half* src = gV + (size_t)vn * 128;
            int i = tid;
#pragma unroll
            for (int rep = 0; rep < 4; rep++, i += 256) {
                int r = i >> 4, c = i & 15;
                cp_async16(uV + (uint32_t)(r * 136 + c * 8) * 2u, src + (size_t)r * KL + c * 8);
            }
            CP_COMMIT();
        }
    }

    // ---- epilogue: write unnormalized O, (m, l) per row ----
    const size_t base0 = ((size_t)b * HH + h) * QQ + qg0;
    const size_t base1 = base0 + 8;
    float* o0 = g_opart + (base0 * KSPLIT + split) * DHH;
    float* o1 = g_opart + (base1 * KSPLIT + split) * DHH;
#pragma unroll
    for (int fn = 0; fn < 8; fn++) {
        int col = fn * 8 + 2 * c4;
        *(float2*)(o0 + col) = make_float2(accO[fn][0], accO[fn][1]);
        *(float2*)(o1 + col) = make_float2(accO[fn][2], accO[fn][3]);
    }
    if (c4 == 0) {
        float* ml0 = g_ml + (base0 * KSPLIT + split) * 2;
        float* ml1 = g_ml + (base1 * KSPLIT + split) * 2;
        ml0[0] = m0; ml0[1] = l0;
        ml1[0] = m1; ml1[1] = l1;
    }
}

// ---------------------------------------------------------------------------
// Combine split-K partials -> ctx (tf32-rounded)
// ---------------------------------------------------------------------------
__global__ void __launch_bounds__(256) combine_kernel() {
    const int col = threadIdx.x & 63;
    const int rloc = threadIdx.x >> 6;
    const int q = blockIdx.x * 4 + rloc;
    const int h = blockIdx.y, b = blockIdx.z;
    const size_t base = ((size_t)b * HH + h) * QQ + q;

    float m[KSPLIT], l[KSPLIT];
#pragma unroll
    for (int s = 0; s < KSPLIT; s++) {
        m[s] = g_ml[(base * KSPLIT + s) * 2 + 0];
        l[s] = g_ml[(base * KSPLIT + s) * 2 + 1];
    }
    float mx = m[0];
#pragma unroll
    for (int s = 1; s < KSPLIT; s++) mx = fmaxf(mx, m[s]);
    float w[KSPLIT], L = 0.f;
#pragma unroll
    for (int s = 0; s < KSPLIT; s++) { w[s] = __expf(m[s] - mx); L += l[s] * w[s]; }
    const float inv = 1.0f / L;

    float o = 0.f;
#pragma unroll
    for (int s = 0; s < KSPLIT; s++)
        o += g_opart[(base * KSPLIT + s) * DHH + col] * w[s];
    g_ctx[((size_t)b * QQ + q) * UU + h * 64 + col] = tf32r(o * inv);
}

// ---------------------------------------------------------------------------
// Launch
// ---------------------------------------------------------------------------
extern "C" void kernel_launch(void* const* d_in, const int* in_sizes, int n_in,
                              void* d_out, int out_size) {
    const float* inputs    = (const float*)d_in[0];
    const float* relatives = (const float*)d_in[1];
    const float* memories  = (const float*)d_in[2];
    const float* bias_c    = (const float*)d_in[3];
    const float* bias_r    = (const float*)d_in[4];
    const float* Wq        = (const float*)d_in[5];
    const float* Wkv       = (const float*)d_in[6];
    const float* Wr        = (const float*)d_in[7];
    const float* Wo        = (const float*)d_in[8];
    float* out             = (float*)d_out;

    float *p_full, *p_relr, *p_qr, *p_v, *p_wr, *p_ctx;
    float *p_wqT, *p_wkvT, *p_wrT, *p_woT;
    __half *p_qch, *p_kh, *p_srh, *p_vth;
    cudaGetSymbolAddress((void**)&p_full, g_full);
    cudaGetSymbolAddress((void**)&p_relr, g_relr);
    cudaGetSymbolAddress((void**)&p_qr,   g_qr);
    cudaGetSymbolAddress((void**)&p_qch,  g_qch);
    cudaGetSymbolAddress((void**)&p_kh,   g_kh);
    cudaGetSymbolAddress((void**)&p_v,    g_v);
    cudaGetSymbolAddress((void**)&p_wr,   g_wr);
    cudaGetSymbolAddress((void**)&p_srh,  g_srh);
    cudaGetSymbolAddress((void**)&p_ctx,  g_ctx);
    cudaGetSymbolAddress((void**)&p_wqT,  g_wqT);
    cudaGetSymbolAddress((void**)&p_wkvT, g_wkvT);
    cudaGetSymbolAddress((void**)&p_wrT,  g_wrT);
    cudaGetSymbolAddress((void**)&p_woT,  g_woT);
    cudaGetSymbolAddress((void**)&p_vth,  g_vth);

    constexpr int SMEM_G = 3 * (128 + 128) * 20 * 4;                        // 61440
    constexpr int SMEM_F = (3 * 128 * 72 + 64 * 136 + 128 * 136) * 2;       // 107520
    cudaFuncSetAttribute((const void*)mma_gemm<128,128,64,32,0>,
                         cudaFuncAttributeMaxDynamicSharedMemorySize, SMEM_G);
    cudaFuncSetAttribute((const void*)mma_gemm<128,128,64,32,1>,
                         cudaFuncAttributeMaxDynamicSharedMemorySize, SMEM_G);
    cudaFuncSetAttribute((const void*)mma_gemm<128,128,64,32,2>,
                         cudaFuncAttributeMaxDynamicSharedMemorySize, SMEM_G);
    cudaFuncSetAttribute((const void*)mma_gemm<128,128,64,32,3>,
                         cudaFuncAttributeMaxDynamicSharedMemorySize, SMEM_G);
    cudaFuncSetAttribute((const void*)mma_gemm<128,128,64,32,4>,
                         cudaFuncAttributeMaxDynamicSharedMemorySize, SMEM_G);
    cudaFuncSetAttribute((const void*)flash_kernel,
                         cudaFuncAttributeMaxDynamicSharedMemorySize, SMEM_F);

    dim3 tblk(32, 8);

    // 0. rounded transposed weights -> [N, K] K-major
    transpose_kernel<false><<<dim3(UU / 32, UU / 32, 1), tblk>>>(Wq, p_wqT, UU, UU, 0, 0, 0, 0, 1);
    transpose_kernel<false><<<dim3((2 * UU) / 32, UU / 32, 1), tblk>>>(Wkv, p_wkvT, 2 * UU, UU, 0, 0, 0, 0, 1);
    transpose_kernel<false><<<dim3(UU / 32, UU / 32, 1), tblk>>>(Wr, p_wrT, UU, UU, 0, 0, 0, 0, 1);
    transpose_kernel<false><<<dim3(UU / 32, UU / 32, 1), tblk>>>(Wo, p_woT, UU, UU, 0, 0, 0, 0, 1);

    // 1. full = tf32(concat);  relr = tf32(relatives)
    {
        size_t total4 = (size_t)BB * KL * UU / 4;
        concat_kernel<<<(unsigned)((total4 + 255) / 256), 256>>>(memories, inputs);
        roundcopy_kernel<<<(unsigned)((total4 + 255) / 256), 256>>>(relatives, p_relr, total4);
    }

    // 2. qr(f32) / qc(f16) = inputs @ Wq + bias
    mma_gemm<128,128,64,32,2><<<dim3(UU/128, QQ/128, BB), 256, SMEM_G>>>(
        p_full + (size_t)MEMN * UU, UU, (long long)KL * UU, 0,
        p_wqT, UU, 0, 0,
        p_qr, UU, (long long)QQ * UU, 0, UU, 1,
        (float*)p_qch, bias_c, bias_r);

    // 3. w_kv = full @ Wkv : K -> fp16 g_kh, V -> fp32 g_v
    mma_gemm<128,128,64,32,4><<<dim3((2*UU)/128, (BB*KL)/128, 1), 256, SMEM_G>>>(
        p_full, UU, 0, 0, p_wkvT, UU, 0, 0,
        p_v, UU, 0, 0, UU, 1,
        (float*)p_kh, nullptr, nullptr);

    // 4. w_r = relatives @ Wr  (tf32r fp32)
    mma_gemm<128,128,64,32,1><<<dim3(UU/128, (BB*KL)/128, 1), 256, SMEM_G>>>(
        p_relr, UU, 0, 0, p_wrT, UU, 0, 0, p_wr, UU, 0, 0, UU, 1,
        nullptr, nullptr, nullptr);

    // 5. V^T per head (fp16): g_vth[b,h,d,t] = half(g_v[b, t, h*64 + d])
    transpose_kernel<true><<<dim3(DHH / 32, KL / 32, BB * HH), tblk>>>(
        p_v, p_vth, UU, KL,
        (long long)KL * UU, 64,
        (long long)HH * DHH * KL, (long long)DHH * KL, HH);

    // 6. Sr[b,h] = qr(b,h) @ R(b,h)^T  (fp16 out)
    mma_gemm<128,128,64,32,3><<<dim3(KL/128, QQ/128, BB*HH), 256, SMEM_G>>>(
        p_qr, UU, (long long)QQ * UU, 64,
        p_wr, UU, (long long)KL * UU, 64,
        (float*)p_srh, KL, (long long)HH * QQ * KL, (long long)QQ * KL,
        DHH, HH, nullptr, nullptr, nullptr);

    // 7. split-K fused fp16 flash -> partials
    flash_kernel<<<dim3(8 * KSPLIT, HH, BB), 256, SMEM_F>>>();

    // 8. combine partials -> ctx
    combine_kernel<<<dim3(QQ / 4, HH, BB), 256>>>();

    // 9. out = ctx @ Wo
    mma_gemm<128,128,64,32,0><<<dim3(UU/128, (BB*QQ)/128, 1), 256, SMEM_G>>>(
        p_ctx, UU, 0, 0, p_woT, UU, 0, 0, out, UU, 0, 0, UU, 1,
        nullptr, nullptr, nullptr);
}

// round 8
// speedup vs baseline: 1.7791x; 1.4138x over previous
#include <cuda_runtime.h>
#include <cuda_fp16.h>
#include <cstdint>

// Problem constants
#define BB   2
#define QQ   1024
#define MEMN 1024
#define UU   1024
#define HH   16
#define DHH  64
#define KL   2048   // MEM + Q
#define KSPLIT 3

// ---------------------------------------------------------------------------
// Scratch (allocation-free: __device__ globals, 16B-aligned for cp.async)
// ---------------------------------------------------------------------------
__device__ __align__(16) __half g_fullh[(size_t)BB * KL * UU];     // fp16 concat
__device__ __align__(16) __half g_relrh[(size_t)BB * KL * UU];     // fp16 relatives
__device__ __align__(16) __half g_qch [(size_t)BB * QQ * UU];      // fp16 q + bias_c
__device__ __align__(16) __half g_qrh [(size_t)BB * QQ * UU];      // fp16 q + bias_r
__device__ __align__(16) __half g_kh  [(size_t)BB * KL * UU];      // fp16 K
__device__ __align__(16) __half g_vh  [(size_t)BB * KL * UU];      // fp16 V
__device__ __align__(16) __half g_wrh [(size_t)BB * KL * UU];      // fp16 w_r
__device__ __align__(16) __half g_srh [(size_t)BB * HH * QQ * KL]; // fp16 Sr unshifted
__device__ __align__(16) __half g_ctxh[(size_t)BB * QQ * UU];      // fp16 attention out
__device__ __align__(16) __half g_wqTh [(size_t)UU * UU];
__device__ __align__(16) __half g_wkvTh[(size_t)2 * UU * UU];
__device__ __align__(16) __half g_wrTh [(size_t)UU * UU];
__device__ __align__(16) __half g_woTh [(size_t)UU * UU];
__device__ __align__(16) __half g_vth [(size_t)BB * HH * DHH * KL]; // fp16 V^T [b,h,d,t]
__device__ float g_opart[(size_t)BB * HH * QQ * KSPLIT * DHH];
__device__ float g_ml   [(size_t)BB * HH * QQ * KSPLIT * 2];

// ---------------------------------------------------------------------------
// Helpers
// ---------------------------------------------------------------------------
__device__ __forceinline__ uint32_t smem_to_u32(const void* p) {
    uint32_t a;
    asm("{ .reg .u64 t; cvta.to.shared.u64 t, %1; cvt.u32.u64 %0, t; }" : "=r"(a) : "l"(p));
    return a;
}
__device__ __forceinline__ void cp_async16(uint32_t saddr, const void* gaddr) {
    asm volatile("cp.async.cg.shared.global [%0], [%1], 16;" :: "r"(saddr), "l"(gaddr));
}
#define CP_COMMIT() asm volatile("cp.async.commit_group;" ::: "memory")
#define CP_WAIT1()  asm volatile("cp.async.wait_group 1;" ::: "memory")

__device__ __forceinline__ void mma_f16(float acc[4], const uint32_t a[4], const uint32_t b[2]) {
    asm volatile("mma.sync.aligned.m16n8k16.row.col.f32.f16.f16.f32 "
        "{%0,%1,%2,%3}, {%4,%5,%6,%7}, {%8,%9}, {%0,%1,%2,%3};"
        : "+f"(acc[0]), "+f"(acc[1]), "+f"(acc[2]), "+f"(acc[3])
        : "r"(a[0]), "r"(a[1]), "r"(a[2]), "r"(a[3]), "r"(b[0]), "r"(b[1]));
}

// ---------------------------------------------------------------------------
// concat(memories, inputs) -> g_fullh (fp16)
// ---------------------------------------------------------------------------
__global__ void concat_kernel(const float* __restrict__ mem,
                              const float* __restrict__ inp) {
    size_t i = (size_t)blockIdx.x * blockDim.x + threadIdx.x;   // float4 index
    const size_t total4 = (size_t)BB * KL * UU / 4;
    if (i >= total4) return;
    size_t elem = i * 4;
    int b = (int)(elem / ((size_t)KL * UU));
    size_t rem = elem % ((size_t)KL * UU);
    int t = (int)(rem / UU);
    int u = (int)(rem % UU);
    float4 v;
    if (t < MEMN) v = *(const float4*)(mem + ((size_t)b * MEMN + t) * UU + u);
    else          v = *(const float4*)(inp + ((size_t)b * QQ + (t - MEMN)) * UU + u);
    __half2* o = (__half2*)(g_fullh + elem);
    o[0] = __floats2half2_rn(v.x, v.y);
    o[1] = __floats2half2_rn(v.z, v.w);
}

__global__ void tohalf_kernel(const float* __restrict__ in, __half* __restrict__ out,
                              size_t total4) {
    size_t i = (size_t)blockIdx.x * blockDim.x + threadIdx.x;
    if (i >= total4) return;
    float4 v = ((const float4*)in)[i];
    __half2* o = (__half2*)(out + i * 4);
    o[0] = __floats2half2_rn(v.x, v.y);
    o[1] = __floats2half2_rn(v.z, v.w);
}

// ---------------------------------------------------------------------------
// Batched strided transpose: out[c, r] = cvt(in[r, c])
// ---------------------------------------------------------------------------
template <typename Tin>
__global__ void transpose_kernel(const Tin* __restrict__ in, __half* __restrict__ out,
                                 int ld_in, int ld_out,
                                 long long sIn1, long long sIn2,
                                 long long sOut1, long long sOut2, int innerB) {
    __shared__ float t[32][33];
    int z = blockIdx.z, z1 = z / innerB, z2 = z % innerB;
    in  += (size_t)z1 * sIn1  + (size_t)z2 * sIn2;
    out += (size_t)z1 * sOut1 + (size_t)z2 * sOut2;
    int r0 = blockIdx.y * 32, c0 = blockIdx.x * 32;
    int tx = threadIdx.x, ty = threadIdx.y;
#pragma unroll
    for (int i = 0; i < 32; i += 8)
        t[ty + i][tx] = (float)in[(size_t)(r0 + ty + i) * ld_in + c0 + tx];
    __syncthreads();
#pragma unroll
    for (int i = 0; i < 32; i += 8)
        out[(size_t)(c0 + ty + i) * ld_out + r0 + tx] = __float2half(t[tx][ty + i]);
}

// ---------------------------------------------------------------------------
// fp16 mma.sync GEMM:  C[m,n] = sum_k A[m,k] * B[n,k]; fp32 accumulate.
//   A row-major [M,K] fp16 (lda), B row-major [N,K] fp16 (ldb).
//   KC=32, 3-stage cp.async pipeline, 8 warps, warp tile WM x WN (m16n8k16).
//   EPI: 0 fp32 out | 2 dual fp16 +bias (C=qc bc, C2=qr br) | 3 fp16 out
//        4 kv-split: col<U -> fp16 K (C2), col>=U -> fp16 V (C)
// ---------------------------------------------------------------------------
template <int BM, int BN, int WM, int WN, int EPI>
__global__ void __launch_bounds__(256)
hgemm(const __half* __restrict__ A, int lda, long long sA1, long long sA2,
      const __half* __restrict__ B, int ldb, long long sB1, long long sB2,
      void* __restrict__ Cv, int ldc, long long sC1, long long sC2,
      int K, int innerB,
      void* __restrict__ C2v, const float* __restrict__ bc, const float* __restrict__ br) {
    constexpr int KC = 32;
    constexpr int LDSS = 40;   // halfs; bank = (20*r4 + c4) % 32 -> conflict-free
    constexpr int WARPS_M = BM / WM;
    constexpr int MFRAG = WM / 16;
    constexpr int NFRAG = WN / 8;
    static_assert((BM / WM) * (BN / WN) * 32 == 256, "warp layout");

    extern __shared__ __half smh[];
    __half* As = smh;
    __half* Bs = smh + 3 * BM * LDSS;
    const uint32_t sA_base = smem_to_u32(As);
    const uint32_t sB_base = smem_to_u32(Bs);

    const int tid = threadIdx.x;
    const int lane = tid & 31;
    const int warp = tid >> 5;
    const int wm = warp % WARPS_M;
    const int wn = warp / WARPS_M;

    const int z = blockIdx.z;
    const int z1 = z / innerB, z2 = z % innerB;
    A += (size_t)z1 * sA1 + (size_t)z2 * sA2;
    B += (size_t)z1 * sB1 + (size_t)z2 * sB2;
    float* C = nullptr;
    __half* Ch = nullptr;
    __half* C2h = nullptr;
    if (EPI == 0) C = (float*)Cv + (size_t)z1 * sC1 + (size_t)z2 * sC2;
    else          Ch = (__half*)Cv + (size_t)z1 * sC1 + (size_t)z2 * sC2;
    if (EPI == 2) C2h = (__half*)C2v + (size_t)z1 * sC1 + (size_t)z2 * sC2;
    if (EPI == 4) C2h = (__half*)C2v;
    const int bm = blockIdx.y * BM;
    const int bn = blockIdx.x * BN;
    const __half* Ag = A + (size_t)bm * lda;
    const __half* Bg = B + (size_t)bn * ldb;

    const int nIter = K / KC;

    auto load_stage = [&](int stage, int buf) {
#pragma unroll
        for (int i = 0; i < (BM * 4) / 256; i++) {
            int idx = tid + i * 256;
            int row = idx >> 2, ch = idx & 3;        // 4 chunks x 8 halfs = 32
            uint32_t s = sA_base + (uint32_t)(buf * BM * LDSS + row * LDSS + ch * 8) * 2u;
            cp_async16(s, Ag + (size_t)row * lda + stage * KC + ch * 8);
        }
#pragma unroll
        for (int i = 0; i < (BN * 4) / 256; i++) {
            int idx = tid + i * 256;
            int row = idx >> 2, ch = idx & 3;
            uint32_t s = sB_base + (uint32_t)(buf * BN * LDSS + row * LDSS + ch * 8) * 2u;
            cp_async16(s, Bg + (size_t)row * ldb + stage * KC + ch * 8);
        }
    };

    float acc[MFRAG][NFRAG][4];
#pragma unroll
    for (int i = 0; i < MFRAG; i++)
#pragma unroll
        for (int j = 0; j < NFRAG; j++)
#pragma unroll
            for (int v = 0; v < 4; v++) acc[i][j][v] = 0.0f;

    load_stage(0, 0); CP_COMMIT();
    if (nIter > 1) load_stage(1, 1);
    CP_COMMIT();

    const int r4 = lane >> 2;
    const int c4 = lane & 3;

    for (int it = 0; it < nIter; ++it) {
        CP_WAIT1();
        __syncthreads();
        if (it + 2 < nIter) load_stage(it + 2, (it + 2) % 3);
        CP_COMMIT();

        const __half* a_ = As + (it % 3) * BM * LDSS + (wm * WM) * LDSS;
        const __half* b_ = Bs + (it % 3) * BN * LDSS + (wn * WN) * LDSS;

#pragma unroll
        for (int ks = 0; ks < 2; ks++) {            // 2 x k16 per KC=32
            uint32_t af[MFRAG][4];
            uint32_t bf[NFRAG][2];
#pragma unroll
            for (int fm = 0; fm < MFRAG; fm++) {
                const __half* ap = a_ + (fm * 16 + r4) * LDSS + ks * 16 + 2 * c4;
                af[fm][0] = *(const uint32_t*)(ap);
                af[fm][1] = *(const uint32_t*)(ap + 8 * LDSS);
                af[fm][2] = *(const uint32_t*)(ap + 8);
                af[fm][3] = *(const uint32_t*)(ap + 8 * LDSS + 8);
            }
#pragma unroll
            for (int fn = 0; fn < NFRAG; fn++) {
                const __half* bp = b_ + (fn * 8 + r4) * LDSS + ks * 16 + 2 * c4;
                bf[fn][0] = *(const uint32_t*)(bp);
                bf[fn][1] = *(const uint32_t*)(bp + 8);
            }
#pragma unroll
            for (int fm = 0; fm < MFRAG; fm++)
#pragma unroll
                for (int fn = 0; fn < NFRAG; fn++)
                    mma_f16(acc[fm][fn], af[fm], bf[fn]);
        }
    }

    const int m0 = bm + wm * WM;
    const int n0 = bn + wn * WN;
#pragma unroll
    for (int fm = 0; fm < MFRAG; fm++) {
#pragma unroll
        for (int fn = 0; fn < NFRAG; fn++) {
            int r = m0 + fm * 16 + r4;
            int cidx = n0 + fn * 8 + c4 * 2;
            float a0 = acc[fm][fn][0], a1 = acc[fm][fn][1];
            float a2 = acc[fm][fn][2], a3 = acc[fm][fn][3];
            if (EPI == 0) {
                *(float2*)(C + (size_t)r * ldc + cidx) = make_float2(a0, a1);
                *(float2*)(C + (size_t)(r + 8) * ldc + cidx) = make_float2(a2, a3);
            } else if (EPI == 2) {
                float b0 = bc[cidx], b1 = bc[cidx + 1];
                float r0 = br[cidx], r1 = br[cidx + 1];
                *(__half2*)(Ch + (size_t)r * ldc + cidx) = __floats2half2_rn(a0 + b0, a1 + b1);
                *(__half2*)(Ch + (size_t)(r + 8) * ldc + cidx) = __floats2half2_rn(a2 + b0, a3 + b1);
                *(__half2*)(C2h + (size_t)r * ldc + cidx) = __floats2half2_rn(a0 + r0, a1 + r1);
                *(__half2*)(C2h + (size_t)(r + 8) * ldc + cidx) = __floats2half2_rn(a2 + r0, a3 + r1);
            } else if (EPI == 3) {
                *(__half2*)(Ch + (size_t)r * ldc + cidx) = __floats2half2_rn(a0, a1);
                *(__half2*)(Ch + (size_t)(r + 8) * ldc + cidx) = __floats2half2_rn(a2, a3);
            } else {   // EPI == 4: kv split, row stride UU for both halves
                if (cidx < UU) {
                    *(__half2*)(C2h + (size_t)r * UU + cidx) = __floats2half2_rn(a0, a1);
                    *(__half2*)(C2h + (size_t)(r + 8) * UU + cidx) = __floats2half2_rn(a2, a3);
                } else {
                    *(__half2*)(Ch + (size_t)r * UU + cidx - UU) = __floats2half2_rn(a0, a1);
                    *(__half2*)(Ch + (size_t)(r + 8) * UU + cidx - UU) = __floats2half2_rn(a2, a3);
                }
            }
        }
    }
}

// ---------------------------------------------------------------------------
// Split-K fused fp16 flash attention. Grid (8*KSPLIT, H, B), 256 threads.
// ---------------------------------------------------------------------------
__global__ void __launch_bounds__(256, 2) flash_kernel() {
    extern __shared__ __half smh[];
    __half* sQ  = smh;                  // [128][72]
    __half* sKa = sQ  + 128 * 72;       // [128][72]
    __half* sKb = sKa + 128 * 72;       // [128][72]
    __half* sV  = sKb + 128 * 72;       // [64][136]
    __half* sP  = sV  + 64 * 136;       // [128][136]
    const uint32_t uQ  = smem_to_u32(sQ);
    const uint32_t uKa = smem_to_u32(sKa);
    const uint32_t uKb = smem_to_u32(sKb);
    const uint32_t uV  = smem_to_u32(sV);

    const int tid = threadIdx.x, lane = tid & 31, warp = tid >> 5;
    const int r4 = lane >> 2, c4 = lane & 3;
    const int qs = (int)blockIdx.x;
    const int qt = 7 - (qs / KSPLIT);
    const int split = qs % KSPLIT;
    const int h = blockIdx.y, b = blockIdx.z;
    const int q0 = qt * 128;
    const int nT = 9 + qt;
    const int t0 = (split * nT) / KSPLIT;
    const int t1 = ((split + 1) * nT) / KSPLIT;

    const __half* gQ = g_qch + ((size_t)b * QQ + q0) * UU + h * 64;
    const __half* gK = g_kh  + (size_t)b * KL * UU + h * 64;
    const __half* gV = g_vth + ((size_t)b * HH + h) * DHH * KL;
    const __half* gS = g_srh + ((size_t)b * HH + h) * QQ * KL;

    {
        int i = tid;
#pragma unroll
        for (int rep = 0; rep < 4; rep++, i += 256) {
            int r = i >> 3, c = i & 7;
            cp_async16(uQ + (uint32_t)(r * 72 + c * 8) * 2u, gQ + (size_t)r * UU + c * 8);
        }
        const __half* srcK = gK + (size_t)t0 * 128 * UU;
        i = tid;
#pragma unroll
        for (int rep = 0; rep < 4; rep++, i += 256) {
            int r = i >> 3, c = i & 7;
            cp_async16(uKa + (uint32_t)(r * 72 + c * 8) * 2u, srcK + (size_t)r * UU + c * 8);
        }
        CP_COMMIT();
        const __half* srcV = gV + (size_t)t0 * 128;
        i = tid;
#pragma unroll
        for (int rep = 0; rep < 4; rep++, i += 256) {
            int r = i >> 4, c = i & 15;
            cp_async16(uV + (uint32_t)(r * 136 + c * 8) * 2u, srcV + (size_t)r * KL + c * 8);
        }
        CP_COMMIT();
    }

    const int lr0 = warp * 16 + r4;
    const int qg0 = q0 + lr0, qg1 = qg0 + 8;
    const __half* sr0 = gS + (size_t)qg0 * KL + (QQ - 1 - qg0);
    const __half* sr1 = gS + (size_t)qg1 * KL + (QQ - 1 - qg1);

    float m0 = -1e30f, m1 = -1e30f, l0 = 0.f, l1 = 0.f;
    float accO[8][4];
#pragma unroll
    for (int f = 0; f < 8; f++)
#pragma unroll
        for (int v = 0; v < 4; v++) accO[f][v] = 0.f;

    for (int it = t0; it < t1; ++it) {
        const int li = it - t0;
        const __half* sK = (li & 1) ? sKb : sKa;
        CP_WAIT1();
        __syncthreads();

        // ---- phase 1: Sc = Qc @ K^T ----
        float accS[16][4];
#pragma unroll
        for (int f = 0; f < 16; f++)
#pragma unroll
            for (int v = 0; v < 4; v++) accS[f][v] = 0.f;
#pragma unroll
        for (int ks = 0; ks < 4; ks++) {
            uint32_t a[4];
            const __half* ap = sQ + lr0 * 72 + ks * 16 + 2 * c4;
            a[0] = *(const uint32_t*)(ap);
            a[1] = *(const uint32_t*)(ap + 8 * 72);
            a[2] = *(const uint32_t*)(ap + 8);
            a[3] = *(const uint32_t*)(ap + 8 * 72 + 8);
#pragma unroll
            for (int fn = 0; fn < 16; fn++) {
                const __half* bp = sK + (fn * 8 + r4) * 72 + ks * 16 + 2 * c4;
                uint32_t bb[2] = {*(const uint32_t*)(bp), *(const uint32_t*)(bp + 8)};
                mma_f16(accS[fn], a, bb);
            }
        }

        // ---- prefetch next K ----
        {
            int kn = (it + 1 < t1) ? (it + 1) : (t1 - 1);
            uint32_t dK = ((li + 1) & 1) ? uKb : uKa;
            const __half* src = gK + (size_t)kn * 128 * UU;
            int i = tid;
#pragma unroll
            for (int rep = 0; rep < 4; rep++, i += 256) {
                int r = i >> 3, c = i & 7;
                cp_async16(dK + (uint32_t)(r * 72 + c * 8) * 2u, src + (size_t)r * UU + c * 8);
            }
            CP_COMMIT();
        }

        // ---- add shifted Sr, scale, mask; online softmax ----
        const int k0 = it * 128;
        const bool lastT = (it == nT - 1);
        const int lim0 = MEMN + qg0 - k0;
        const int lim1 = lim0 + 8;

        float rm0 = -1e30f, rm1 = -1e30f;
#pragma unroll
        for (int fn = 0; fn < 16; fn++) {
            int kc = fn * 8 + 2 * c4;
            float s0, s1, s2, s3;
            s0 = (!lastT || kc     <= lim0) ? (accS[fn][0] + __half2float(__ldg(sr0 + k0 + kc)))     * 0.125f : -1e30f;
            s1 = (!lastT || kc + 1 <= lim0) ? (accS[fn][1] + __half2float(__ldg(sr0 + k0 + kc + 1))) * 0.125f : -1e30f;
            s2 = (!lastT || kc     <= lim1) ? (accS[fn][2] + __half2float(__ldg(sr1 + k0 + kc)))     * 0.125f : -1e30f;
            s3 = (!lastT || kc + 1 <= lim1) ? (accS[fn][3] + __half2float(__ldg(sr1 + k0 + kc + 1))) * 0.125f : -1e30f;
            accS[fn][0] = s0; accS[fn][1] = s1; accS[fn][2] = s2; accS[fn][3] = s3;
            rm0 = fmaxf(rm0, fmaxf(s0, s1));
            rm1 = fmaxf(rm1, fmaxf(s2, s3));
        }
        rm0 = fmaxf(rm0, __shfl_xor_sync(~0u, rm0, 1));
        rm0 = fmaxf(rm0, __shfl_xor_sync(~0u, rm0, 2));
        rm1 = fmaxf(rm1, __shfl_xor_sync(~0u, rm1, 1));
        rm1 = fmaxf(rm1, __shfl_xor_sync(~0u, rm1, 2));
        float mN0 = fmaxf(m0, rm0), mN1 = fmaxf(m1, rm1);
        float al0 = __expf(m0 - mN0), al1 = __expf(m1 - mN1);
        m0 = mN0; m1 = mN1;

        float ps0 = 0.f, ps1 = 0.f;
        __half* p0 = sP + lr0 * 136;
        __half* p1 = p0 + 8 * 136;
#pragma unroll
        for (int fn = 0; fn < 16; fn++) {
            int kc = fn * 8 + 2 * c4;
            float e0 = __expf(accS[fn][0] - m0);
            float e1 = __expf(accS[fn][1] - m0);
            float e2 = __expf(accS[fn][2] - m1);
            float e3 = __expf(accS[fn][3] - m1);
            ps0 += e0 + e1; ps1 += e2 + e3;
            *(__half2*)(p0 + kc) = __floats2half2_rn(e0, e1);
            *(__half2*)(p1 + kc) = __floats2half2_rn(e2, e3);
        }
        ps0 += __shfl_xor_sync(~0u, ps0, 1); ps0 += __shfl_xor_sync(~0u, ps0, 2);
        ps1 += __shfl_xor_sync(~0u, ps1, 1); ps1 += __shfl_xor_sync(~0u, ps1, 2);
        l0 = l0 * al0 + ps0;
        l1 = l1 * al1 + ps1;
#pragma unroll
        for (int f = 0; f < 8; f++) {
            accO[f][0] *= al0; accO[f][1] *= al0;
            accO[f][2] *= al1; accO[f][3] *= al1;
        }
        __syncwarp();

        CP_WAIT1();
        __syncthreads();

        // ---- phase 2: O += P @ V ----
#pragma unroll
        for (int ks = 0; ks < 8; ks++) {
            uint32_t a[4];
            const __half* ap = sP + lr0 * 136 + ks * 16 + 2 * c4;
            a[0] = *(const uint32_t*)(ap);
            a[1] = *(const uint32_t*)(ap + 8 * 136);
            a[2] = *(const uint32_t*)(ap + 8);
            a[3] = *(const uint32_t*)(ap + 8 * 136 + 8);
#pragma unroll
            for (int fn = 0; fn < 8; fn++) {
                const __half* bp = sV + (fn * 8 + r4) * 136 + ks * 16 + 2 * c4;
                uint32_t bb[2] = {*(const uint32_t*)(bp), *(const uint32_t*)(bp + 8)};
                mma_f16(accO[fn], a, bb);
            }
        }
        __syncthreads();

        // ---- prefetch next V ----
        {
            int vn = (it + 1 < t1) ? (it + 1) : (t1 - 1);
            const __half* src = gV + (size_t)vn * 128;
            int i = tid;
#pragma unroll
            for (int rep = 0; rep < 4; rep++, i += 256) {
                int r = i >> 4, c = i & 15;
                cp_async16(uV + (uint32_t)(r * 136 + c * 8) * 2u, src + (size_t)r * KL + c * 8);
            }
            CP_COMMIT();
        }
    }

    // ---- epilogue ----
    const size_t base0 = ((size_t)b * HH + h) * QQ + qg0;
    const size_t base1 = base0 + 8;
    float* o0 = g_opart + (base0 * KSPLIT + split) * DHH;
    float* o1 = g_opart + (base1 * KSPLIT + split) * DHH;
#pragma unroll
    for (int fn = 0; fn < 8; fn++) {
        int col = fn * 8 + 2 * c4;
        *(float2*)(o0 + col) = make_float2(accO[fn][0], accO[fn][1]);
        *(float2*)(o1 + col) = make_float2(accO[fn][2], accO[fn][3]);
    }
    if (c4 == 0) {
        float* ml0 = g_ml + (base0 * KSPLIT + split) * 2;
        float* ml1 = g_ml + (base1 * KSPLIT + split) * 2;
        ml0[0] = m0; ml0[1] = l0;
        ml1[0] = m1; ml1[1] = l1;
    }
}

// ---------------------------------------------------------------------------
// Combine split-K partials -> ctx (fp16)
// ---------------------------------------------------------------------------
__global__ void __launch_bounds__(256) combine_kernel() {
    const int col = threadIdx.x & 63;
    const int rloc = threadIdx.x >> 6;
    const int q = blockIdx.x * 4 + rloc;
    const int h = blockIdx.y, b = blockIdx.z;
    const size_t base = ((size_t)b * HH + h) * QQ + q;

    float m[KSPLIT], l[KSPLIT];
#pragma unroll
    for (int s = 0; s < KSPLIT; s++) {
        m[s] = g_ml[(base * KSPLIT + s) * 2 + 0];
        l[s] = g_ml[(base * KSPLIT + s) * 2 + 1];
    }
    float mx = m[0];
#pragma unroll
    for (int s = 1; s < KSPLIT; s++) mx = fmaxf(mx, m[s]);
    float w[KSPLIT], L = 0.f;
#pragma unroll
    for (int s = 0; s < KSPLIT; s++) { w[s] = __expf(m[s] - mx); L += l[s] * w[s]; }
    const float inv = 1.0f / L;

    float o = 0.f;
#pragma unroll
    for (int s = 0; s < KSPLIT; s++)
        o += g_opart[(base * KSPLIT + s) * DHH + col] * w[s];
    g_ctxh[((size_t)b * QQ + q) * UU + h * 64 + col] = __float2half(o * inv);
}

// ---------------------------------------------------------------------------
// Launch
// ---------------------------------------------------------------------------
extern "C" void kernel_launch(void* const* d_in, const int* in_sizes, int n_in,
                              void* d_out, int out_size) {
    const float* inputs    = (const float*)d_in[0];
    const float* relatives = (const float*)d_in[1];
    const float* memories  = (const float*)d_in[2];
    const float* bias_c    = (const float*)d_in[3];
    const float* bias_r    = (const float*)d_in[4];
    const float* Wq        = (const float*)d_in[5];
    const float* Wkv       = (const float*)d_in[6];
    const float* Wr        = (const float*)d_in[7];
    const float* Wo        = (const float*)d_in[8];
    float* out             = (float*)d_out;

    __half *p_fullh, *p_relrh, *p_qch, *p_qrh, *p_kh, *p_vh, *p_wrh, *p_srh, *p_ctxh;
    __half *p_wqTh, *p_wkvTh, *p_wrTh, *p_woTh, *p_vth;
    cudaGetSymbolAddress((void**)&p_fullh, g_fullh);
    cudaGetSymbolAddress((void**)&p_relrh, g_relrh);
    cudaGetSymbolAddress((void**)&p_qch,   g_qch);
    cudaGetSymbolAddress((void**)&p_qrh,   g_qrh);
    cudaGetSymbolAddress((void**)&p_kh,    g_kh);
    cudaGetSymbolAddress((void**)&p_vh,    g_vh);
    cudaGetSymbolAddress((void**)&p_wrh,   g_wrh);
    cudaGetSymbolAddress((void**)&p_srh,   g_srh);
    cudaGetSymbolAddress((void**)&p_ctxh,  g_ctxh);
    cudaGetSymbolAddress((void**)&p_wqTh,  g_wqTh);
    cudaGetSymbolAddress((void**)&p_wkvTh, g_wkvTh);
    cudaGetSymbolAddress((void**)&p_wrTh,  g_wrTh);
    cudaGetSymbolAddress((void**)&p_woTh,  g_woTh);
    cudaGetSymbolAddress((void**)&p_vth,   g_vth);

    constexpr int SMEM_G = 3 * (128 + 128) * 40 * 2;                   // 61440
    constexpr int SMEM_F = (3 * 128 * 72 + 64 * 136 + 128 * 136) * 2;  // 107520
    cudaFuncSetAttribute((const void*)hgemm<128,128,64,32,0>,
                         cudaFuncAttributeMaxDynamicSharedMemorySize, SMEM_G);
    cudaFuncSetAttribute((const void*)hgemm<128,128,64,32,2>,
                         cudaFuncAttributeMaxDynamicSharedMemorySize, SMEM_G);
    cudaFuncSetAttribute((const void*)hgemm<128,128,64,32,3>,
                         cudaFuncAttributeMaxDynamicSharedMemorySize, SMEM_G);
    cudaFuncSetAttribute((const void*)hgemm<128,128,64,32,4>,
                         cudaFuncAttributeMaxDynamicSharedMemorySize, SMEM_G);
    cudaFuncSetAttribute((const void*)flash_kernel,
                         cudaFuncAttributeMaxDynamicSharedMemorySize, SMEM_F);

    dim3 tblk(32, 8);

    // 0. transposed fp16 weights -> [N, K] K-major
    transpose_kernel<float><<<dim3(UU / 32, UU / 32, 1), tblk>>>(Wq, p_wqTh, UU, UU, 0, 0, 0, 0, 1);
    transpose_kernel<float><<<dim3((2 * UU) / 32, UU / 32, 1), tblk>>>(Wkv, p_wkvTh, 2 * UU, UU, 0, 0, 0, 0, 1);
    transpose_kernel<float><<<dim3(UU / 32, UU / 32, 1), tblk>>>(Wr, p_wrTh, UU, UU, 0, 0, 0, 0, 1);
    transpose_kernel<float><<<dim3(UU / 32, UU / 32, 1), tblk>>>(Wo, p_woTh, UU, UU, 0, 0, 0, 0, 1);

    // 1. fullh = fp16(concat);  relrh = fp16(relatives)
    {
        size_t total4 = (size_t)BB * KL * UU / 4;
        concat_kernel<<<(unsigned)((total4 + 255) / 256), 256>>>(memories, inputs);
        tohalf_kernel<<<(unsigned)((total4 + 255) / 256), 256>>>(relatives, p_relrh, total4);
    }

    // 2. qc / qr = fp16(inputs @ Wq + bias_{c,r})
    hgemm<128,128,64,32,2><<<dim3(UU/128, QQ/128, BB), 256, SMEM_G>>>(
        p_fullh + (size_t)MEMN * UU, UU, (long long)KL * UU, 0,
        p_wqTh, UU, 0, 0,
        p_qch, UU, (long long)QQ * UU, 0, UU, 1,
        p_qrh, bias_c, bias_r);

    // 3. w_kv = full @ Wkv : K -> g_kh, V -> g_vh
    hgemm<128,128,64,32,4><<<dim3((2*UU)/128, (BB*KL)/128, 1), 256, SMEM_G>>>(
        p_fullh, UU, 0, 0, p_wkvTh, UU, 0, 0,
        p_vh, UU, 0, 0, UU, 1,
        p_kh, nullptr, nullptr);

    // 4. w_r = relatives @ Wr  (fp16)
    hgemm<128,128,64,32,3><<<dim3(UU/128, (BB*KL)/128, 1), 256, SMEM_G>>>(
        p_relrh, UU, 0, 0, p_wrTh, UU, 0, 0, p_wrh, UU, 0, 0, UU, 1,
        nullptr, nullptr, nullptr);

    // 5. V^T per head (fp16): g_vth[b,h,d,t] = g_vh[b, t, h*64 + d]
    transpose_kernel<__half><<<dim3(DHH / 32, KL / 32, BB * HH), tblk>>>(
        p_vh, p_vth, UU, KL,
        (long long)KL * UU, 64,
        (long long)HH * DHH * KL, (long long)DHH * KL, HH);

    // 6. Sr[b,h] = qr(b,h) @ R(b,h)^T  (fp16 out)
    hgemm<128,128,64,32,3><<<dim3(KL/128, QQ/128, BB*HH), 256, SMEM_G>>>(
        p_qrh, UU, (long long)QQ * UU, 64,
        p_wrh, UU, (long long)KL * UU, 64,
        p_srh, KL, (long long)HH * QQ * KL, (long long)QQ * KL,
        DHH, HH, nullptr, nullptr, nullptr);

    // 7. split-K fused fp16 flash -> partials
    flash_kernel<<<dim3(8 * KSPLIT, HH, BB), 256, SMEM_F>>>();

    // 8. combine partials -> ctx (fp16)
    combine_kernel<<<dim3(QQ / 4, HH, BB), 256>>>();

    // 9. out = ctx @ Wo (fp32 out)
    hgemm<128,128,64,32,0><<<dim3(UU/128, (BB*QQ)/128, 1), 256, SMEM_G>>>(
        p_ctxh, UU, 0, 0, p_woTh, UU, 0, 0, out, UU, 0, 0, UU, 1,
        nullptr, nullptr, nullptr);
}

// round 9
// speedup vs baseline: 1.8921x; 1.0635x over previous
#include <cuda_runtime.h>
#include <cuda_fp16.h>
#include <cstdint>

// Problem constants
#define BB   2
#define QQ   1024
#define MEMN 1024
#define UU   1024
#define HH   16
#define DHH  64
#define KL   2048   // MEM + Q
#define KSPLIT 3

// ---------------------------------------------------------------------------
// Scratch (allocation-free: __device__ globals, 16B-aligned for cp.async)
// ---------------------------------------------------------------------------
__device__ __align__(16) __half g_fullh[(size_t)BB * KL * UU];     // fp16 concat
__device__ __align__(16) __half g_relrh[(size_t)BB * KL * UU];     // fp16 relatives
__device__ __align__(16) __half g_qch [(size_t)BB * QQ * UU];      // fp16 q + bias_c
__device__ __align__(16) __half g_qrh [(size_t)BB * QQ * UU];      // fp16 q + bias_r
__device__ __align__(16) __half g_kh  [(size_t)BB * KL * UU];      // fp16 K
__device__ __align__(16) __half g_vh  [(size_t)BB * KL * UU];      // fp16 V
__device__ __align__(16) __half g_wrh [(size_t)BB * KL * UU];      // fp16 w_r
__device__ __align__(16) __half g_srh [(size_t)BB * HH * QQ * KL]; // fp16 Sr SHIFTED
__device__ __align__(16) __half g_ctxh[(size_t)BB * QQ * UU];      // fp16 attention out
__device__ __align__(16) __half g_wqTh [(size_t)UU * UU];
__device__ __align__(16) __half g_wkvTh[(size_t)2 * UU * UU];
__device__ __align__(16) __half g_wrTh [(size_t)UU * UU];
__device__ __align__(16) __half g_woTh [(size_t)UU * UU];
__device__ __align__(16) __half g_vth [(size_t)BB * HH * DHH * KL]; // fp16 V^T [b,h,d,t]
__device__ float g_opart[(size_t)BB * HH * QQ * KSPLIT * DHH];
__device__ float g_ml   [(size_t)BB * HH * QQ * KSPLIT * 2];

// ---------------------------------------------------------------------------
// Helpers
// ---------------------------------------------------------------------------
__device__ __forceinline__ uint32_t smem_to_u32(const void* p) {
    uint32_t a;
    asm("{ .reg .u64 t; cvta.to.shared.u64 t, %1; cvt.u32.u64 %0, t; }" : "=r"(a) : "l"(p));
    return a;
}
__device__ __forceinline__ void cp_async16(uint32_t saddr, const void* gaddr) {
    asm volatile("cp.async.cg.shared.global [%0], [%1], 16;" :: "r"(saddr), "l"(gaddr));
}
#define CP_COMMIT() asm volatile("cp.async.commit_group;" ::: "memory")
#define CP_WAIT1()  asm volatile("cp.async.wait_group 1;" ::: "memory")

__device__ __forceinline__ void mma_f16(float acc[4], const uint32_t a[4], const uint32_t b[2]) {
    asm volatile("mma.sync.aligned.m16n8k16.row.col.f32.f16.f16.f32 "
        "{%0,%1,%2,%3}, {%4,%5,%6,%7}, {%8,%9}, {%0,%1,%2,%3};"
        : "+f"(acc[0]), "+f"(acc[1]), "+f"(acc[2]), "+f"(acc[3])
        : "r"(a[0]), "r"(a[1]), "r"(a[2]), "r"(a[3]), "r"(b[0]), "r"(b[1]));
}

// ---------------------------------------------------------------------------
// concat(memories, inputs) -> g_fullh (fp16)
// ---------------------------------------------------------------------------
__global__ void concat_kernel(const float* __restrict__ mem,
                              const float* __restrict__ inp) {
    size_t i = (size_t)blockIdx.x * blockDim.x + threadIdx.x;   // float4 index
    const size_t total4 = (size_t)BB * KL * UU / 4;
    if (i >= total4) return;
    size_t elem = i * 4;
    int b = (int)(elem / ((size_t)KL * UU));
    size_t rem = elem % ((size_t)KL * UU);
    int t = (int)(rem / UU);
    int u = (int)(rem % UU);
    float4 v;
    if (t < MEMN) v = *(const float4*)(mem + ((size_t)b * MEMN + t) * UU + u);
    else          v = *(const float4*)(inp + ((size_t)b * QQ + (t - MEMN)) * UU + u);
    __half2* o = (__half2*)(g_fullh + elem);
    o[0] = __floats2half2_rn(v.x, v.y);
    o[1] = __floats2half2_rn(v.z, v.w);
}

__global__ void tohalf_kernel(const float* __restrict__ in, __half* __restrict__ out,
                              size_t total4) {
    size_t i = (size_t)blockIdx.x * blockDim.x + threadIdx.x;
    if (i >= total4) return;
    float4 v = ((const float4*)in)[i];
    __half2* o = (__half2*)(out + i * 4);
    o[0] = __floats2half2_rn(v.x, v.y);
    o[1] = __floats2half2_rn(v.z, v.w);
}

// ---------------------------------------------------------------------------
// Batched strided transpose: out[c, r] = cvt(in[r, c])
// ---------------------------------------------------------------------------
template <typename Tin>
__global__ void transpose_kernel(const Tin* __restrict__ in, __half* __restrict__ out,
                                 int ld_in, int ld_out,
                                 long long sIn1, long long sIn2,
                                 long long sOut1, long long sOut2, int innerB) {
    __shared__ float t[32][33];
    int z = blockIdx.z, z1 = z / innerB, z2 = z % innerB;
    in  += (size_t)z1 * sIn1  + (size_t)z2 * sIn2;
    out += (size_t)z1 * sOut1 + (size_t)z2 * sOut2;
    int r0 = blockIdx.y * 32, c0 = blockIdx.x * 32;
    int tx = threadIdx.x, ty = threadIdx.y;
#pragma unroll
    for (int i = 0; i < 32; i += 8)
        t[ty + i][tx] = (float)in[(size_t)(r0 + ty + i) * ld_in + c0 + tx];
    __syncthreads();
#pragma unroll
    for (int i = 0; i < 32; i += 8)
        out[(size_t)(c0 + ty + i) * ld_out + r0 + tx] = __float2half(t[tx][ty + i]);
}

// ---------------------------------------------------------------------------
// fp16 mma.sync GEMM:  C[m,n] = sum_k A[m,k] * B[n,k]; fp32 accumulate.
//   EPI: 0 fp32 out | 2 dual fp16 +bias (C=qc bc, C2=qr br) | 3 fp16 out
//        4 kv-split: col<U -> fp16 K (C2), col>=U -> fp16 V (C)
//        5 shifted fp16 store: C[r, cidx-(QQ-1-r)] (relative-shift pre-applied)
// ---------------------------------------------------------------------------
template <int BM, int BN, int WM, int WN, int EPI>
__global__ void __launch_bounds__(256)
hgemm(const __half* __restrict__ A, int lda, long long sA1, long long sA2,
      const __half* __restrict__ B, int ldb, long long sB1, long long sB2,
      void* __restrict__ Cv, int ldc, long long sC1, long long sC2,
      int K, int innerB,
      void* __restrict__ C2v, const float* __restrict__ bc, const float* __restrict__ br) {
    constexpr int KC = 32;
    constexpr int LDSS = 40;   // halfs; conflict-free fragment access
    constexpr int WARPS_M = BM / WM;
    constexpr int MFRAG = WM / 16;
    constexpr int NFRAG = WN / 8;
    static_assert((BM / WM) * (BN / WN) * 32 == 256, "warp layout");

    const int bm = blockIdx.y * BM;
    const int bn = blockIdx.x * BN;
    // EPI 5: skip tiles whose whole shifted k-range is negative (never read)
    if (EPI == 5) {
        if (bn + bm + BM + BN - 2 - (QQ - 1) < 0) return;
    }

    extern __shared__ __half smh[];
    __half* As = smh;
    __half* Bs = smh + 3 * BM * LDSS;
    const uint32_t sA_base = smem_to_u32(As);
    const uint32_t sB_base = smem_to_u32(Bs);

    const int tid = threadIdx.x;
    const int lane = tid & 31;
    const int warp = tid >> 5;
    const int wm = warp % WARPS_M;
    const int wn = warp / WARPS_M;

    const int z = blockIdx.z;
    const int z1 = z / innerB, z2 = z % innerB;
    A += (size_t)z1 * sA1 + (size_t)z2 * sA2;
    B += (size_t)z1 * sB1 + (size_t)z2 * sB2;
    float* C = nullptr;
    __half* Ch = nullptr;
    __half* C2h = nullptr;
    if (EPI == 0) C = (float*)Cv + (size_t)z1 * sC1 + (size_t)z2 * sC2;
    else          Ch = (__half*)Cv + (size_t)z1 * sC1 + (size_t)z2 * sC2;
    if (EPI == 2) C2h = (__half*)C2v + (size_t)z1 * sC1 + (size_t)z2 * sC2;
    if (EPI == 4) C2h = (__half*)C2v;
    const __half* Ag = A + (size_t)bm * lda;
    const __half* Bg = B + (size_t)bn * ldb;

    const int nIter = K / KC;

    auto load_stage = [&](int stage, int buf) {
#pragma unroll
        for (int i = 0; i < (BM * 4) / 256; i++) {
            int idx = tid + i * 256;
            int row = idx >> 2, ch = idx & 3;        // 4 chunks x 8 halfs = 32
            uint32_t s = sA_base + (uint32_t)(buf * BM * LDSS + row * LDSS + ch * 8) * 2u;
            cp_async16(s, Ag + (size_t)row * lda + stage * KC + ch * 8);
        }
#pragma unroll
        for (int i = 0; i < (BN * 4) / 256; i++) {
            int idx = tid + i * 256;
            int row = idx >> 2, ch = idx & 3;
            uint32_t s = sB_base + (uint32_t)(buf * BN * LDSS + row * LDSS + ch * 8) * 2u;
            cp_async16(s, Bg + (size_t)row * ldb + stage * KC + ch * 8);
        }
    };

    float acc[MFRAG][NFRAG][4];
#pragma unroll
    for (int i = 0; i < MFRAG; i++)
#pragma unroll
        for (int j = 0; j < NFRAG; j++)
#pragma unroll
            for (int v = 0; v < 4; v++) acc[i][j][v] = 0.0f;

    load_stage(0, 0); CP_COMMIT();
    if (nIter > 1) load_stage(1, 1);
    CP_COMMIT();

    const int r4 = lane >> 2;
    const int c4 = lane & 3;

    for (int it = 0; it < nIter; ++it) {
        CP_WAIT1();
        __syncthreads();
        if (it + 2 < nIter) load_stage(it + 2, (it + 2) % 3);
        CP_COMMIT();

        const __half* a_ = As + (it % 3) * BM * LDSS + (wm * WM) * LDSS;
        const __half* b_ = Bs + (it % 3) * BN * LDSS + (wn * WN) * LDSS;

#pragma unroll
        for (int ks = 0; ks < 2; ks++) {            // 2 x k16 per KC=32
            uint32_t af[MFRAG][4];
            uint32_t bf[NFRAG][2];
#pragma unroll
            for (int fm = 0; fm < MFRAG; fm++) {
                const __half* ap = a_ + (fm * 16 + r4) * LDSS + ks * 16 + 2 * c4;
                af[fm][0] = *(const uint32_t*)(ap);
                af[fm][1] = *(const uint32_t*)(ap + 8 * LDSS);
                af[fm][2] = *(const uint32_t*)(ap + 8);
                af[fm][3] = *(const uint32_t*)(ap + 8 * LDSS + 8);
            }
#pragma unroll
            for (int fn = 0; fn < NFRAG; fn++) {
                const __half* bp = b_ + (fn * 8 + r4) * LDSS + ks * 16 + 2 * c4;
                bf[fn][0] = *(const uint32_t*)(bp);
                bf[fn][1] = *(const uint32_t*)(bp + 8);
            }
#pragma unroll
            for (int fm = 0; fm < MFRAG; fm++)
#pragma unroll
                for (int fn = 0; fn < NFRAG; fn++)
                    mma_f16(acc[fm][fn], af[fm], bf[fn]);
        }
    }

    const int m0 = bm + wm * WM;
    const int n0 = bn + wn * WN;
#pragma unroll
    for (int fm = 0; fm < MFRAG; fm++) {
#pragma unroll
        for (int fn = 0; fn < NFRAG; fn++) {
            int r = m0 + fm * 16 + r4;
            int cidx = n0 + fn * 8 + c4 * 2;
            float a0 = acc[fm][fn][0], a1 = acc[fm][fn][1];
            float a2 = acc[fm][fn][2], a3 = acc[fm][fn][3];
            if (EPI == 0) {
                *(float2*)(C + (size_t)r * ldc + cidx) = make_float2(a0, a1);
                *(float2*)(C + (size_t)(r + 8) * ldc + cidx) = make_float2(a2, a3);
            } else if (EPI == 2) {
                float b0 = bc[cidx], b1 = bc[cidx + 1];
                float r0 = br[cidx], r1 = br[cidx + 1];
                *(__half2*)(Ch + (size_t)r * ldc + cidx) = __floats2half2_rn(a0 + b0, a1 + b1);
                *(__half2*)(Ch + (size_t)(r + 8) * ldc + cidx) = __floats2half2_rn(a2 + b0, a3 + b1);
                *(__half2*)(C2h + (size_t)r * ldc + cidx) = __floats2half2_rn(a0 + r0, a1 + r1);
                *(__half2*)(C2h + (size_t)(r + 8) * ldc + cidx) = __floats2half2_rn(a2 + r0, a3 + r1);
            } else if (EPI == 3) {
                *(__half2*)(Ch + (size_t)r * ldc + cidx) = __floats2half2_rn(a0, a1);
                *(__half2*)(Ch + (size_t)(r + 8) * ldc + cidx) = __floats2half2_rn(a2, a3);
            } else if (EPI == 4) {
                if (cidx < UU) {
                    *(__half2*)(C2h + (size_t)r * UU + cidx) = __floats2half2_rn(a0, a1);
                    *(__half2*)(C2h + (size_t)(r + 8) * UU + cidx) = __floats2half2_rn(a2, a3);
                } else {
                    *(__half2*)(Ch + (size_t)r * UU + cidx - UU) = __floats2half2_rn(a0, a1);
                    *(__half2*)(Ch + (size_t)(r + 8) * UU + cidx - UU) = __floats2half2_rn(a2, a3);
                }
            } else {   // EPI == 5: shifted store SrShift[q, k] = Sr[q, j], k = j-(Q-1-q)
                int k0s = cidx - (QQ - 1) + r;
                __half h0 = __float2half(a0), h1 = __float2half(a1);
                if (k0s >= 0 && (k0s & 1) == 0) {
                    *(__half2*)(Ch + (size_t)r * ldc + k0s) = __halves2half2(h0, h1);
                } else {
                    if (k0s >= 0)     Ch[(size_t)r * ldc + k0s]     = h0;
                    if (k0s + 1 >= 0) Ch[(size_t)r * ldc + k0s + 1] = h1;
                }
                int r2 = r + 8;
                int k1s = cidx - (QQ - 1) + r2;
                __half h2 = __float2half(a2), h3 = __float2half(a3);
                if (k1s >= 0 && (k1s & 1) == 0) {
                    *(__half2*)(Ch + (size_t)r2 * ldc + k1s) = __halves2half2(h2, h3);
                } else {
                    if (k1s >= 0)     Ch[(size_t)r2 * ldc + k1s]     = h2;
                    if (k1s + 1 >= 0) Ch[(size_t)r2 * ldc + k1s + 1] = h3;
                }
            }
        }
    }
}

// ---------------------------------------------------------------------------
// Split-K fused fp16 flash attention. Sr pre-shifted -> staged via cp.async
// into the sP buffer (Sr values sit exactly where P is written in place).
// Grid (8*KSPLIT, H, B), 256 threads, 2 CTAs/SM.
// ---------------------------------------------------------------------------
__global__ void __launch_bounds__(256, 2) flash_kernel() {
    extern __shared__ __half smh[];
    __half* sQ  = smh;                  // [128][72]
    __half* sKa = sQ  + 128 * 72;       // [128][72]
    __half* sKb = sKa + 128 * 72;       // [128][72]
    __half* sV  = sKb + 128 * 72;       // [64][136]
    __half* sP  = sV  + 64 * 136;       // [128][136]  (Sr stage, then P)
    const uint32_t uQ  = smem_to_u32(sQ);
    const uint32_t uKa = smem_to_u32(sKa);
    const uint32_t uKb = smem_to_u32(sKb);
    const uint32_t uV  = smem_to_u32(sV);
    const uint32_t uP  = smem_to_u32(sP);

    const int tid = threadIdx.x, lane = tid & 31, warp = tid >> 5;
    const int r4 = lane >> 2, c4 = lane & 3;
    const int qs = (int)blockIdx.x;
    const int qt = 7 - (qs / KSPLIT);
    const int split = qs % KSPLIT;
    const int h = blockIdx.y, b = blockIdx.z;
    const int q0 = qt * 128;
    const int nT = 9 + qt;
    const int t0 = (split * nT) / KSPLIT;
    const int t1 = ((split + 1) * nT) / KSPLIT;

    const __half* gQ = g_qch + ((size_t)b * QQ + q0) * UU + h * 64;
    const __half* gK = g_kh  + (size_t)b * KL * UU + h * 64;
    const __half* gV = g_vth + ((size_t)b * HH + h) * DHH * KL;
    const __half* gS = g_srh + (((size_t)b * HH + h) * QQ + q0) * KL;  // shifted rows

    auto load_k = [&](int t, uint32_t dK) {
        const __half* src = gK + (size_t)t * 128 * UU;
        int i = tid;
#pragma unroll
        for (int rep = 0; rep < 4; rep++, i += 256) {
            int r = i >> 3, c = i & 7;
            cp_async16(dK + (uint32_t)(r * 72 + c * 8) * 2u, src + (size_t)r * UU + c * 8);
        }
    };
    auto load_v = [&](int t) {
        const __half* src = gV + (size_t)t * 128;
        int i = tid;
#pragma unroll
        for (int rep = 0; rep < 4; rep++, i += 256) {
            int r = i >> 4, c = i & 15;
            cp_async16(uV + (uint32_t)(r * 136 + c * 8) * 2u, src + (size_t)r * KL + c * 8);
        }
    };
    auto load_sr = [&](int t) {
        const __half* src = gS + (size_t)t * 128;   // row q0+r, cols k0..k0+127
        int i = tid;
#pragma unroll
        for (int rep = 0; rep < 8; rep++, i += 256) {
            int r = i >> 4, c = i & 15;
            cp_async16(uP + (uint32_t)(r * 136 + c * 8) * 2u, src + (size_t)r * KL + c * 8);
        }
    };

    // Prologue: G0 = {Q, K(t0)} ; G1 = {Sr(t0), V(t0)}
    {
        int i = tid;
#pragma unroll
        for (int rep = 0; rep < 4; rep++, i += 256) {
            int r = i >> 3, c = i & 7;
            cp_async16(uQ + (uint32_t)(r * 72 + c * 8) * 2u, gQ + (size_t)r * UU + c * 8);
        }
        load_k(t0, uKa);
        CP_COMMIT();
        load_sr(t0);
        load_v(t0);
        CP_COMMIT();
    }

    const int lr0 = warp * 16 + r4;
    const int qg0 = q0 + lr0, qg1 = qg0 + 8;

    float m0 = -1e30f, m1 = -1e30f, l0 = 0.f, l1 = 0.f;
    float accO[8][4];
#pragma unroll
    for (int f = 0; f < 8; f++)
#pragma unroll
        for (int v = 0; v < 4; v++) accO[f][v] = 0.f;

    for (int it = t0; it < t1; ++it) {
        const int li = it - t0;
        const __half* sK = (li & 1) ? sKb : sKa;
        CP_WAIT1();            // K(it) (and older) ready
        __syncthreads();

        // ---- phase 1: Sc = Qc @ K^T ----
        float accS[16][4];
#pragma unroll
        for (int f = 0; f < 16; f++)
#pragma unroll
            for (int v = 0; v < 4; v++) accS[f][v] = 0.f;
#pragma unroll
        for (int ks = 0; ks < 4; ks++) {
            uint32_t a[4];
            const __half* ap = sQ + lr0 * 72 + ks * 16 + 2 * c4;
            a[0] = *(const uint32_t*)(ap);
            a[1] = *(const uint32_t*)(ap + 8 * 72);
            a[2] = *(const uint32_t*)(ap + 8);
            a[3] = *(const uint32_t*)(ap + 8 * 72 + 8);
#pragma unroll
            for (int fn = 0; fn < 16; fn++) {
                const __half* bp = sK + (fn * 8 + r4) * 72 + ks * 16 + 2 * c4;
                uint32_t bb[2] = {*(const uint32_t*)(bp), *(const uint32_t*)(bp + 8)};
                mma_f16(accS[fn], a, bb);
            }
        }

        // ---- prefetch next K ----
        {
            int kn = (it + 1 < t1) ? (it + 1) : (t1 - 1);
            load_k(kn, ((li + 1) & 1) ? uKb : uKa);
            CP_COMMIT();
        }

        CP_WAIT1();            // Sr(it) + V(it) ready (leaves K(it+1) pending)
        __syncthreads();

        // ---- add staged shifted Sr, scale, mask; online softmax ----
        const int k0 = it * 128;
        const bool lastT = (it == nT - 1);
        const int lim0 = MEMN + qg0 - k0;
        const int lim1 = lim0 + 8;

        __half* p0 = sP + lr0 * 136;
        __half* p1 = p0 + 8 * 136;

        float rm0 = -1e30f, rm1 = -1e30f;
#pragma unroll
        for (int fn = 0; fn < 16; fn++) {
            int kc = fn * 8 + 2 * c4;
            float2 f0 = __half22float2(*(const __half2*)(p0 + kc));
            float2 f1 = __half22float2(*(const __half2*)(p1 + kc));
            float s0, s1, s2, s3;
            s0 = (!lastT || kc     <= lim0) ? (accS[fn][0] + f0.x) * 0.125f : -1e30f;
            s1 = (!lastT || kc + 1 <= lim0) ? (accS[fn][1] + f0.y) * 0.125f : -1e30f;
            s2 = (!lastT || kc     <= lim1) ? (accS[fn][2] + f1.x) * 0.125f : -1e30f;
            s3 = (!lastT || kc + 1 <= lim1) ? (accS[fn][3] + f1.y) * 0.125f : -1e30f;
            accS[fn][0] = s0; accS[fn][1] = s1; accS[fn][2] = s2; accS[fn][3] = s3;
            rm0 = fmaxf(rm0, fmaxf(s0, s1));
            rm1 = fmaxf(rm1, fmaxf(s2, s3));
        }
        rm0 = fmaxf(rm0, __shfl_xor_sync(~0u, rm0, 1));
        rm0 = fmaxf(rm0, __shfl_xor_sync(~0u, rm0, 2));
        rm1 = fmaxf(rm1, __shfl_xor_sync(~0u, rm1, 1));
        rm1 = fmaxf(rm1, __shfl_xor_sync(~0u, rm1, 2));
        float mN0 = fmaxf(m0, rm0), mN1 = fmaxf(m1, rm1);
        float al0 = __expf(m0 - mN0), al1 = __expf(m1 - mN1);
        m0 = mN0; m1 = mN1;

        float ps0 = 0.f, ps1 = 0.f;
#pragma unroll
        for (int fn = 0; fn < 16; fn++) {
            int kc = fn * 8 + 2 * c4;
            float e0 = __expf(accS[fn][0] - m0);
            float e1 = __expf(accS[fn][1] - m0);
            float e2 = __expf(accS[fn][2] - m1);
            float e3 = __expf(accS[fn][3] - m1);
            ps0 += e0 + e1; ps1 += e2 + e3;
            *(__half2*)(p0 + kc) = __floats2half2_rn(e0, e1);
            *(__half2*)(p1 + kc) = __floats2half2_rn(e2, e3);
        }
        ps0 += __shfl_xor_sync(~0u, ps0, 1); ps0 += __shfl_xor_sync(~0u, ps0, 2);
        ps1 += __shfl_xor_sync(~0u, ps1, 1); ps1 += __shfl_xor_sync(~0u, ps1, 2);
        l0 = l0 * al0 + ps0;
        l1 = l1 * al1 + ps1;
#pragma unroll
        for (int f = 0; f < 8; f++) {
            accO[f][0] *= al0; accO[f][1] *= al0;
            accO[f][2] *= al1; accO[f][3] *= al1;
        }
        __syncwarp();          // P rows are per-warp private

        // ---- phase 2: O += P @ V ----
#pragma unroll
        for (int ks = 0; ks < 8; ks++) {
            uint32_t a[4];
            const __half* ap = sP + lr0 * 136 + ks * 16 + 2 * c4;
            a[0] = *(const uint32_t*)(ap);
            a[1] = *(const uint32_t*)(ap + 8 * 136);
            a[2] = *(const uint32_t*)(ap + 8);
            a[3] = *(const uint32_t*)(ap + 8 * 136 + 8);
#pragma unroll
            for (int fn = 0; fn < 8; fn++) {
                const __half* bp = sV + (fn * 8 + r4) * 136 + ks * 16 + 2 * c4;
                uint32_t bb[2] = {*(const uint32_t*)(bp), *(const uint32_t*)(bp + 8)};
                mma_f16(accO[fn], a, bb);
            }
        }
        __syncthreads();       // everyone done with sP / sV

        // ---- prefetch next Sr + V (into sP / sV) ----
        {
            int vn = (it + 1 < t1) ? (it + 1) : (t1 - 1);
            load_sr(vn);
            load_v(vn);
            CP_COMMIT();
        }
    }

    // ---- epilogue ----
    const size_t base0 = ((size_t)b * HH + h) * QQ + qg0;
    const size_t base1 = base0 + 8;
    float* o0 = g_opart + (base0 * KSPLIT + split) * DHH;
    float* o1 = g_opart + (base1 * KSPLIT + split) * DHH;
#pragma unroll
    for (int fn = 0; fn < 8; fn++) {
        int col = fn * 8 + 2 * c4;
        *(float2*)(o0 + col) = make_float2(accO[fn][0], accO[fn][1]);
        *(float2*)(o1 + col) = make_float2(accO[fn][2], accO[fn][3]);
    }
    if (c4 == 0) {
        float* ml0 = g_ml + (base0 * KSPLIT + split) * 2;
        float* ml1 = g_ml + (base1 * KSPLIT + split) * 2;
        ml0[0] = m0; ml0[1] = l0;
        ml1[0] = m1; ml1[1] = l1;
    }
}

// ---------------------------------------------------------------------------
// Combine split-K partials -> ctx (fp16)
// ---------------------------------------------------------------------------
__global__ void __launch_bounds__(256) combine_kernel() {
    const int col = threadIdx.x & 63;
    const int rloc = threadIdx.x >> 6;
    const int q = blockIdx.x * 4 + rloc;
    const int h = blockIdx.y, b = blockIdx.z;
    const size_t base = ((size_t)b * HH + h) * QQ + q;

    float m[KSPLIT], l[KSPLIT];
#pragma unroll
    for (int s = 0; s < KSPLIT; s++) {
        m[s] = g_ml[(base * KSPLIT + s) * 2 + 0];
        l[s] = g_ml[(base * KSPLIT + s) * 2 + 1];
    }
    float mx = m[0];
#pragma unroll
    for (int s = 1; s < KSPLIT; s++) mx = fmaxf(mx, m[s]);
    float w[KSPLIT], L = 0.f;
#pragma unroll
    for (int s = 0; s < KSPLIT; s++) { w[s] = __expf(m[s] - mx); L += l[s] * w[s]; }
    const float inv = 1.0f / L;

    float o = 0.f;
#pragma unroll
    for (int s = 0; s < KSPLIT; s++)
        o += g_opart[(base * KSPLIT + s) * DHH + col] * w[s];
    g_ctxh[((size_t)b * QQ + q) * UU + h * 64 + col] = __float2half(o * inv);
}

// ---------------------------------------------------------------------------
// Launch
// ---------------------------------------------------------------------------
extern "C" void kernel_launch(void* const* d_in, const int* in_sizes, int n_in,
                              void* d_out, int out_size) {
    const float* inputs    = (const float*)d_in[0];
    const float* relatives = (const float*)d_in[1];
    const float* memories  = (const float*)d_in[2];
    const float* bias_c    = (const float*)d_in[3];
    const float* bias_r    = (const float*)d_in[4];
    const float* Wq        = (const float*)d_in[5];
    const float* Wkv       = (const float*)d_in[6];
    const float* Wr        = (const float*)d_in[7];
    const float* Wo        = (const float*)d_in[8];
    float* out             = (float*)d_out;

    __half *p_fullh, *p_relrh, *p_qch, *p_qrh, *p_kh, *p_vh, *p_wrh, *p_srh, *p_ctxh;
    __half *p_wqTh, *p_wkvTh, *p_wrTh, *p_woTh, *p_vth;
    cudaGetSymbolAddress((void**)&p_fullh, g_fullh);
    cudaGetSymbolAddress((void**)&p_relrh, g_relrh);
    cudaGetSymbolAddress((void**)&p_qch,   g_qch);
    cudaGetSymbolAddress((void**)&p_qrh,   g_qrh);
    cudaGetSymbolAddress((void**)&p_kh,    g_kh);
    cudaGetSymbolAddress((void**)&p_vh,    g_vh);
    cudaGetSymbolAddress((void**)&p_wrh,   g_wrh);
    cudaGetSymbolAddress((void**)&p_srh,   g_srh);
    cudaGetSymbolAddress((void**)&p_ctxh,  g_ctxh);
    cudaGetSymbolAddress((void**)&p_wqTh,  g_wqTh);
    cudaGetSymbolAddress((void**)&p_wkvTh, g_wkvTh);
    cudaGetSymbolAddress((void**)&p_wrTh,  g_wrTh);
    cudaGetSymbolAddress((void**)&p_woTh,  g_woTh);
    cudaGetSymbolAddress((void**)&p_vth,   g_vth);

    constexpr int SMEM_G = 3 * (128 + 128) * 40 * 2;                   // 61440
    constexpr int SMEM_F = (3 * 128 * 72 + 64 * 136 + 128 * 136) * 2;  // 107520
    cudaFuncSetAttribute((const void*)hgemm<128,128,64,32,0>,
                         cudaFuncAttributeMaxDynamicSharedMemorySize, SMEM_G);
    cudaFuncSetAttribute((const void*)hgemm<128,128,64,32,2>,
                         cudaFuncAttributeMaxDynamicSharedMemorySize, SMEM_G);
    cudaFuncSetAttribute((const void*)hgemm<128,128,64,32,3>,
                         cudaFuncAttributeMaxDynamicSharedMemorySize, SMEM_G);
    cudaFuncSetAttribute((const void*)hgemm<128,128,64,32,4>,
                         cudaFuncAttributeMaxDynamicSharedMemorySize, SMEM_G);
    cudaFuncSetAttribute((const void*)hgemm<128,128,64,32,5>,
                         cudaFuncAttributeMaxDynamicSharedMemorySize, SMEM_G);
    cudaFuncSetAttribute((const void*)flash_kernel,
                         cudaFuncAttributeMaxDynamicSharedMemorySize, SMEM_F);

    dim3 tblk(32, 8);

    // 0. transposed fp16 weights -> [N, K] K-major
    transpose_kernel<float><<<dim3(UU / 32, UU / 32, 1), tblk>>>(Wq, p_wqTh, UU, UU, 0, 0, 0, 0, 1);
    transpose_kernel<float><<<dim3((2 * UU) / 32, UU / 32, 1), tblk>>>(Wkv, p_wkvTh, 2 * UU, UU, 0, 0, 0, 0, 1);
    transpose_kernel<float><<<dim3(UU / 32, UU / 32, 1), tblk>>>(Wr, p_wrTh, UU, UU, 0, 0, 0, 0, 1);
    transpose_kernel<float><<<dim3(UU / 32, UU / 32, 1), tblk>>>(Wo, p_woTh, UU, UU, 0, 0, 0, 0, 1);

    // 1. fullh = fp16(concat);  relrh = fp16(relatives)
    {
        size_t total4 = (size_t)BB * KL * UU / 4;
        concat_kernel<<<(unsigned)((total4 + 255) / 256), 256>>>(memories, inputs);
        tohalf_kernel<<<(unsigned)((total4 + 255) / 256), 256>>>(relatives, p_relrh, total4);
    }

    // 2. qc / qr = fp16(inputs @ Wq + bias_{c,r})
    hgemm<128,128,64,32,2><<<dim3(UU/128, QQ/128, BB), 256, SMEM_G>>>(
        p_fullh + (size_t)MEMN * UU, UU, (long long)KL * UU, 0,
        p_wqTh, UU, 0, 0,
        p_qch, UU, (long long)QQ * UU, 0, UU, 1,
        p_qrh, bias_c, bias_r);

    // 3. w_kv = full @ Wkv : K -> g_kh, V -> g_vh
    hgemm<128,128,64,32,4><<<dim3((2*UU)/128, (BB*KL)/128, 1), 256, SMEM_G>>>(
        p_fullh, UU, 0, 0, p_wkvTh, UU, 0, 0,
        p_vh, UU, 0, 0, UU, 1,
        p_kh, nullptr, nullptr);

    // 4. w_r = relatives @ Wr  (fp16)
    hgemm<128,128,64,32,3><<<dim3(UU/128, (BB*KL)/128, 1), 256, SMEM_G>>>(
        p_relrh, UU, 0, 0, p_wrTh, UU, 0, 0, p_wrh, UU, 0, 0, UU, 1,
        nullptr, nullptr, nullptr);

    // 5. V^T per head (fp16)
    transpose_kernel<__half><<<dim3(DHH / 32, KL / 32, BB * HH), tblk>>>(
        p_vh, p_vth, UU, KL,
        (long long)KL * UU, 64,
        (long long)HH * DHH * KL, (long long)DHH * KL, HH);

    // 6. SrShift[b,h,q,k] = (qr @ wr^T)[q, k + Q-1-q]  (shifted fp16 store)
    hgemm<128,128,64,32,5><<<dim3(KL/128, QQ/128, BB*HH), 256, SMEM_G>>>(
        p_qrh, UU, (long long)QQ * UU, 64,
        p_wrh, UU, (long long)KL * UU, 64,
        p_srh, KL, (long long)HH * QQ * KL, (long long)QQ * KL,
        DHH, HH, nullptr, nullptr, nullptr);

    // 7. split-K fused fp16 flash -> partials
    flash_kernel<<<dim3(8 * KSPLIT, HH, BB), 256, SMEM_F>>>();

    // 8. combine partials -> ctx (fp16)
    combine_kernel<<<dim3(QQ / 4, HH, BB), 256>>>();

    // 9. out = ctx @ Wo (fp32 out)
    hgemm<128,128,64,32,0><<<dim3(UU/128, (BB*QQ)/128, 1), 256, SMEM_G>>>(
        p_ctxh, UU, 0, 0, p_woTh, UU, 0, 0, out, UU, 0, 0, UU, 1,
        nullptr, nullptr, nullptr);
}

// round 10
// speedup vs baseline: 1.9882x; 1.0508x over previous
#include <cuda_runtime.h>
#include <cuda_fp16.h>
#include <cstdint>

// Problem constants
#define BB   2
#define QQ   1024
#define MEMN 1024
#define UU   1024
#define HH   16
#define DHH  64
#define KL   2048   // MEM + Q
#define KSPLIT 3

// ---------------------------------------------------------------------------
// Scratch (allocation-free: __device__ globals, 16B-aligned for cp.async)
// ---------------------------------------------------------------------------
__device__ __align__(16) __half g_fullh[(size_t)BB * KL * UU];     // fp16 concat
__device__ __align__(16) __half g_relrh[(size_t)BB * KL * UU];     // fp16 relatives
__device__ __align__(16) __half g_qch [(size_t)BB * QQ * UU];      // fp16 q + bias_c
__device__ __align__(16) __half g_qrh [(size_t)BB * QQ * UU];      // fp16 q + bias_r
__device__ __align__(16) __half g_kh  [(size_t)BB * KL * UU];      // fp16 K
__device__ __align__(16) __half g_vh  [(size_t)BB * KL * UU];      // fp16 V  [b,t,u]
__device__ __align__(16) __half g_wrh [(size_t)BB * KL * UU];      // fp16 w_r
__device__ __align__(16) __half g_srh [(size_t)BB * HH * QQ * KL]; // fp16 Sr SHIFTED
__device__ __align__(16) __half g_ctxh[(size_t)BB * QQ * UU];      // fp16 attention out
__device__ __align__(16) __half g_wqTh [(size_t)UU * UU];
__device__ __align__(16) __half g_wkvTh[(size_t)2 * UU * UU];
__device__ __align__(16) __half g_wrTh [(size_t)UU * UU];
__device__ __align__(16) __half g_woTh [(size_t)UU * UU];
__device__ float g_opart[(size_t)BB * HH * QQ * KSPLIT * DHH];
__device__ float g_ml   [(size_t)BB * HH * QQ * KSPLIT * 2];

// ---------------------------------------------------------------------------
// Helpers
// ---------------------------------------------------------------------------
__device__ __forceinline__ uint32_t smem_to_u32(const void* p) {
    uint32_t a;
    asm("{ .reg .u64 t; cvta.to.shared.u64 t, %1; cvt.u32.u64 %0, t; }" : "=r"(a) : "l"(p));
    return a;
}
__device__ __forceinline__ void cp_async16(uint32_t saddr, const void* gaddr) {
    asm volatile("cp.async.cg.shared.global [%0], [%1], 16;" :: "r"(saddr), "l"(gaddr));
}
#define CP_COMMIT() asm volatile("cp.async.commit_group;" ::: "memory")
#define CP_WAIT1()  asm volatile("cp.async.wait_group 1;" ::: "memory")

__device__ __forceinline__ void mma_f16(float acc[4], const uint32_t a[4], const uint32_t b[2]) {
    asm volatile("mma.sync.aligned.m16n8k16.row.col.f32.f16.f16.f32 "
        "{%0,%1,%2,%3}, {%4,%5,%6,%7}, {%8,%9}, {%0,%1,%2,%3};"
        : "+f"(acc[0]), "+f"(acc[1]), "+f"(acc[2]), "+f"(acc[3])
        : "r"(a[0]), "r"(a[1]), "r"(a[2]), "r"(a[3]), "r"(b[0]), "r"(b[1]));
}
__device__ __forceinline__ void ldsm_x4(uint32_t* r, uint32_t addr) {
    asm volatile("ldmatrix.sync.aligned.m8n8.x4.shared.b16 {%0,%1,%2,%3}, [%4];"
        : "=r"(r[0]), "=r"(r[1]), "=r"(r[2]), "=r"(r[3]) : "r"(addr));
}
__device__ __forceinline__ void ldsm_x4t(uint32_t* r, uint32_t addr) {
    asm volatile("ldmatrix.sync.aligned.m8n8.x4.trans.shared.b16 {%0,%1,%2,%3}, [%4];"
        : "=r"(r[0]), "=r"(r[1]), "=r"(r[2]), "=r"(r[3]) : "r"(addr));
}

// ---------------------------------------------------------------------------
// prep: concat(memories, inputs) -> g_fullh ; relatives -> g_relrh (fp16)
// ---------------------------------------------------------------------------
__global__ void prep_kernel(const float* __restrict__ mem,
                            const float* __restrict__ inp,
                            const float* __restrict__ rel) {
    const size_t total4 = (size_t)BB * KL * UU / 4;
    size_t i = (size_t)blockIdx.x * blockDim.x + threadIdx.x;
    if (i < total4) {
        size_t elem = i * 4;
        int b = (int)(elem / ((size_t)KL * UU));
        size_t rem = elem % ((size_t)KL * UU);
        int t = (int)(rem / UU);
        int u = (int)(rem % UU);
        float4 v;
        if (t < MEMN) v = *(const float4*)(mem + ((size_t)b * MEMN + t) * UU + u);
        else          v = *(const float4*)(inp + ((size_t)b * QQ + (t - MEMN)) * UU + u);
        __half2* o = (__half2*)(g_fullh + elem);
        o[0] = __floats2half2_rn(v.x, v.y);
        o[1] = __floats2half2_rn(v.z, v.w);
    } else if (i < 2 * total4) {
        size_t j = i - total4;
        float4 v = ((const float4*)rel)[j];
        __half2* o = (__half2*)(g_relrh + j * 4);
        o[0] = __floats2half2_rn(v.x, v.y);
        o[1] = __floats2half2_rn(v.z, v.w);
    }
}

// ---------------------------------------------------------------------------
// Fused weight transposes: W[K=1024, N] row-major -> W^T[N, 1024] fp16
// ---------------------------------------------------------------------------
__global__ void wtrans_kernel(const float* __restrict__ Wq, const float* __restrict__ Wkv,
                              const float* __restrict__ Wr, const float* __restrict__ Wo) {
    __shared__ float t[32][33];
    int bid = blockIdx.x;
    const float* in; __half* out; int cols;
    if (bid < 1024)      { in = Wq;  out = g_wqTh;  cols = 1024; }
    else if (bid < 3072) { in = Wkv; out = g_wkvTh; cols = 2048; bid -= 1024; }
    else if (bid < 4096) { in = Wr;  out = g_wrTh;  cols = 1024; bid -= 3072; }
    else                 { in = Wo;  out = g_woTh;  cols = 1024; bid -= 4096; }
    int tilesX = cols / 32;
    int c0 = (bid % tilesX) * 32;
    int r0 = (bid / tilesX) * 32;
    int tx = threadIdx.x, ty = threadIdx.y;
#pragma unroll
    for (int i = 0; i < 32; i += 8)
        t[ty + i][tx] = in[(size_t)(r0 + ty + i) * cols + c0 + tx];
    __syncthreads();
#pragma unroll
    for (int i = 0; i < 32; i += 8)
        out[(size_t)(c0 + ty + i) * 1024 + r0 + tx] = __float2half(t[tx][ty + i]);
}

// ---------------------------------------------------------------------------
// fp16 mma.sync GEMM (ldmatrix fragments):  C[m,n] = sum_k A[m,k] * B[n,k]
//   EPI: 0 fp32 out | 2 dual fp16 +bias (C=qc bc, C2=qr br) | 3 fp16 out
//        4 kv-split: col<U -> fp16 K (C2), col>=U -> fp16 V (C)
//        5 shifted fp16 store: C[r, cidx-(QQ-1-r)]
// ---------------------------------------------------------------------------
template <int BM, int BN, int WM, int WN, int EPI>
__global__ void __launch_bounds__(256)
hgemm(const __half* __restrict__ A, int lda, long long sA1, long long sA2,
      const __half* __restrict__ B, int ldb, long long sB1, long long sB2,
      void* __restrict__ Cv, int ldc, long long sC1, long long sC2,
      int K, int innerB,
      void* __restrict__ C2v, const float* __restrict__ bc, const float* __restrict__ br) {
    constexpr int KC = 32;
    constexpr int LDSS = 40;   // halfs
    constexpr int WARPS_M = BM / WM;
    constexpr int MFRAG = WM / 16;
    constexpr int NFRAG = WN / 8;
    static_assert((BM / WM) * (BN / WN) * 32 == 256, "warp layout");

    const int bm = blockIdx.y * BM;
    const int bn = blockIdx.x * BN;
    if (EPI == 5) {
        if (bn + bm + BM + BN - 2 - (QQ - 1) < 0) return;  // fully below diagonal
    }

    extern __shared__ __half smh[];
    __half* As = smh;
    __half* Bs = smh + 3 * BM * LDSS;
    const uint32_t sA_base = smem_to_u32(As);
    const uint32_t sB_base = smem_to_u32(Bs);

    const int tid = threadIdx.x;
    const int lane = tid & 31;
    const int warp = tid >> 5;
    const int wm = warp % WARPS_M;
    const int wn = warp / WARPS_M;

    const int z = blockIdx.z;
    const int z1 = z / innerB, z2 = z % innerB;
    A += (size_t)z1 * sA1 + (size_t)z2 * sA2;
    B += (size_t)z1 * sB1 + (size_t)z2 * sB2;
    float* C = nullptr;
    __half* Ch = nullptr;
    __half* C2h = nullptr;
    if (EPI == 0) C = (float*)Cv + (size_t)z1 * sC1 + (size_t)z2 * sC2;
    else          Ch = (__half*)Cv + (size_t)z1 * sC1 + (size_t)z2 * sC2;
    if (EPI == 2) C2h = (__half*)C2v + (size_t)z1 * sC1 + (size_t)z2 * sC2;
    if (EPI == 4) C2h = (__half*)C2v;
    const __half* Ag = A + (size_t)bm * lda;
    const __half* Bg = B + (size_t)bn * ldb;

    const int nIter = K / KC;

    auto load_stage = [&](int stage, int buf) {
#pragma unroll
        for (int i = 0; i < (BM * 4) / 256; i++) {
            int idx = tid + i * 256;
            int row = idx >> 2, ch = idx & 3;
            uint32_t s = sA_base + (uint32_t)(buf * BM * LDSS + row * LDSS + ch * 8) * 2u;
            cp_async16(s, Ag + (size_t)row * lda + stage * KC + ch * 8);
        }
#pragma unroll
        for (int i = 0; i < (BN * 4) / 256; i++) {
            int idx = tid + i * 256;
            int row = idx >> 2, ch = idx & 3;
            uint32_t s = sB_base + (uint32_t)(buf * BN * LDSS + row * LDSS + ch * 8) * 2u;
            cp_async16(s, Bg + (size_t)row * ldb + stage * KC + ch * 8);
        }
    };

    float acc[MFRAG][NFRAG][4];
#pragma unroll
    for (int i = 0; i < MFRAG; i++)
#pragma unroll
        for (int j = 0; j < NFRAG; j++)
#pragma unroll
            for (int v = 0; v < 4; v++) acc[i][j][v] = 0.0f;

    load_stage(0, 0); CP_COMMIT();
    if (nIter > 1) load_stage(1, 1);
    CP_COMMIT();

    // ldmatrix per-lane address components (halfs)
    const uint32_t aOff = (uint32_t)((wm * WM + (lane & 15)) * LDSS + (lane >> 4) * 8);
    const uint32_t bOff = (uint32_t)((wn * WN + (lane & 7) + (lane >> 4) * 8) * LDSS +
                                     ((lane >> 3) & 1) * 8);

    const int r4 = lane >> 2;
    const int c4 = lane & 3;

    for (int it = 0; it < nIter; ++it) {
        CP_WAIT1();
        __syncthreads();
        if (it + 2 < nIter) load_stage(it + 2, (it + 2) % 3);
        CP_COMMIT();

        const uint32_t aBuf = sA_base + (uint32_t)((it % 3) * BM * LDSS) * 2u;
        const uint32_t bBuf = sB_base + (uint32_t)((it % 3) * BN * LDSS) * 2u;

#pragma unroll
        for (int ks = 0; ks < 2; ks++) {            // 2 x k16 per KC=32
            uint32_t af[MFRAG][4];
            uint32_t bf[NFRAG][2];
#pragma unroll
            for (int fm = 0; fm < MFRAG; fm++)
                ldsm_x4(af[fm], aBuf + (aOff + fm * 16 * LDSS + ks * 16) * 2u);
#pragma unroll
            for (int fp = 0; fp < NFRAG / 2; fp++) {
                uint32_t r[4];
                ldsm_x4(r, bBuf + (bOff + fp * 16 * LDSS + ks * 16) * 2u);
                bf[2 * fp][0] = r[0]; bf[2 * fp][1] = r[1];
                bf[2 * fp + 1][0] = r[2]; bf[2 * fp + 1][1] = r[3];
            }
#pragma unroll
            for (int fm = 0; fm < MFRAG; fm++)
#pragma unroll
                for (int fn = 0; fn < NFRAG; fn++)
                    mma_f16(acc[fm][fn], af[fm], bf[fn]);
        }
    }

    const int m0 = bm + wm * WM;
    const int n0 = bn + wn * WN;
#pragma unroll
    for (int fm = 0; fm < MFRAG; fm++) {
#pragma unroll
        for (int fn = 0; fn < NFRAG; fn++) {
            int r = m0 + fm * 16 + r4;
            int cidx = n0 + fn * 8 + c4 * 2;
            float a0 = acc[fm][fn][0], a1 = acc[fm][fn][1];
            float a2 = acc[fm][fn][2], a3 = acc[fm][fn][3];
            if (EPI == 0) {
                *(float2*)(C + (size_t)r * ldc + cidx) = make_float2(a0, a1);
                *(float2*)(C + (size_t)(r + 8) * ldc + cidx) = make_float2(a2, a3);
            } else if (EPI == 2) {
                float b0 = bc[cidx], b1 = bc[cidx + 1];
                float r0 = br[cidx], r1 = br[cidx + 1];
                *(__half2*)(Ch + (size_t)r * ldc + cidx) = __floats2half2_rn(a0 + b0, a1 + b1);
                *(__half2*)(Ch + (size_t)(r + 8) * ldc + cidx) = __floats2half2_rn(a2 + b0, a3 + b1);
                *(__half2*)(C2h + (size_t)r * ldc + cidx) = __floats2half2_rn(a0 + r0, a1 + r1);
                *(__half2*)(C2h + (size_t)(r + 8) * ldc + cidx) = __floats2half2_rn(a2 + r0, a3 + r1);
            } else if (EPI == 3) {
                *(__half2*)(Ch + (size_t)r * ldc + cidx) = __floats2half2_rn(a0, a1);
                *(__half2*)(Ch + (size_t)(r + 8) * ldc + cidx) = __floats2half2_rn(a2, a3);
            } else if (EPI == 4) {
                if (cidx < UU) {
                    *(__half2*)(C2h + (size_t)r * UU + cidx) = __floats2half2_rn(a0, a1);
                    *(__half2*)(C2h + (size_t)(r + 8) * UU + cidx) = __floats2half2_rn(a2, a3);
                } else {
                    *(__half2*)(Ch + (size_t)r * UU + cidx - UU) = __floats2half2_rn(a0, a1);
                    *(__half2*)(Ch + (size_t)(r + 8) * UU + cidx - UU) = __floats2half2_rn(a2, a3);
                }
            } else {   // EPI == 5: shifted store
                int k0s = cidx - (QQ - 1) + r;
                __half h0 = __float2half(a0), h1 = __float2half(a1);
                if (k0s >= 0 && (k0s & 1) == 0) {
                    *(__half2*)(Ch + (size_t)r * ldc + k0s) = __halves2half2(h0, h1);
                } else {
                    if (k0s >= 0)     Ch[(size_t)r * ldc + k0s]     = h0;
                    if (k0s + 1 >= 0) Ch[(size_t)r * ldc + k0s + 1] = h1;
                }
                int r2 = r + 8;
                int k1s = cidx - (QQ - 1) + r2;
                __half h2 = __float2half(a2), h3 = __float2half(a3);
                if (k1s >= 0 && (k1s & 1) == 0) {
                    *(__half2*)(Ch + (size_t)r2 * ldc + k1s) = __halves2half2(h2, h3);
                } else {
                    if (k1s >= 0)     Ch[(size_t)r2 * ldc + k1s]     = h2;
                    if (k1s + 1 >= 0) Ch[(size_t)r2 * ldc + k1s + 1] = h3;
                }
            }
        }
    }
}

// ---------------------------------------------------------------------------
// Split-K fused fp16 flash attention (ldmatrix fragments; V loaded [t][d]
// straight from g_vh and fed via ldmatrix.trans).
// Grid (8*KSPLIT, H, B), 256 threads, 2 CTAs/SM.
// ---------------------------------------------------------------------------
__global__ void __launch_bounds__(256, 2) flash_kernel() {
    extern __shared__ __half smh[];
    __half* sQ  = smh;                  // [128][72]
    __half* sKa = sQ  + 128 * 72;       // [128][72]
    __half* sKb = sKa + 128 * 72;       // [128][72]
    __half* sV  = sKb + 128 * 72;       // [128 t][72 d]
    __half* sP  = sV  + 128 * 72;       // [128][136]  (Sr stage, then P)
    const uint32_t uQ  = smem_to_u32(sQ);
    const uint32_t uKa = smem_to_u32(sKa);
    const uint32_t uKb = smem_to_u32(sKb);
    const uint32_t uV  = smem_to_u32(sV);
    const uint32_t uP  = smem_to_u32(sP);

    const int tid = threadIdx.x, lane = tid & 31, warp = tid >> 5;
    const int r4 = lane >> 2, c4 = lane & 3;
    const int qs = (int)blockIdx.x;
    const int qt = 7 - (qs / KSPLIT);
    const int split = qs % KSPLIT;
    const int h = blockIdx.y, b = blockIdx.z;
    const int q0 = qt * 128;
    const int nT = 9 + qt;
    const int t0 = (split * nT) / KSPLIT;
    const int t1 = ((split + 1) * nT) / KSPLIT;

    const __half* gQ = g_qch + ((size_t)b * QQ + q0) * UU + h * 64;
    const __half* gK = g_kh  + (size_t)b * KL * UU + h * 64;
    const __half* gV = g_vh  + (size_t)b * KL * UU + h * 64;   // rows t, 64 d
    const __half* gS = g_srh + (((size_t)b * HH + h) * QQ + q0) * KL;

    auto load_k = [&](int t, uint32_t dK) {
        const __half* src = gK + (size_t)t * 128 * UU;
        int i = tid;
#pragma unroll
        for (int rep = 0; rep < 4; rep++, i += 256) {
            int r = i >> 3, c = i & 7;
            cp_async16(dK + (uint32_t)(r * 72 + c * 8) * 2u, src + (size_t)r * UU + c * 8);
        }
    };
    auto load_v = [&](int t) {
        const __half* src = gV + (size_t)t * 128 * UU;
        int i = tid;
#pragma unroll
        for (int rep = 0; rep < 4; rep++, i += 256) {
            int r = i >> 3, c = i & 7;
            cp_async16(uV + (uint32_t)(r * 72 + c * 8) * 2u, src + (size_t)r * UU + c * 8);
        }
    };
    auto load_sr = [&](int t) {
        const __half* src = gS + (size_t)t * 128;
        int i = tid;
#pragma unroll
        for (int rep = 0; rep < 8; rep++, i += 256) {
            int r = i >> 4, c = i & 15;
            cp_async16(uP + (uint32_t)(r * 136 + c * 8) * 2u, src + (size_t)r * KL + c * 8);
        }
    };

    // Prologue: G0 = {Q, K(t0)} ; G1 = {Sr(t0), V(t0)}
    {
        int i = tid;
#pragma unroll
        for (int rep = 0; rep < 4; rep++, i += 256) {
            int r = i >> 3, c = i & 7;
            cp_async16(uQ + (uint32_t)(r * 72 + c * 8) * 2u, gQ + (size_t)r * UU + c * 8);
        }
        load_k(t0, uKa);
        CP_COMMIT();
        load_sr(t0);
        load_v(t0);
        CP_COMMIT();
    }

    const int lr0 = warp * 16 + r4;
    const int qg0 = q0 + lr0, qg1 = qg0 + 8;

    // ldmatrix per-lane address components (halfs)
    const uint32_t aOffQ = (uint32_t)((warp * 16 + (lane & 15)) * 72 + (lane >> 4) * 8);
    const uint32_t aOffP = (uint32_t)((warp * 16 + (lane & 15)) * 136 + (lane >> 4) * 8);
    const uint32_t bOffK = (uint32_t)(((lane & 7) + (lane >> 4) * 8) * 72 + ((lane >> 3) & 1) * 8);
    const uint32_t bOffV = (uint32_t)((lane & 15) * 72 + (lane >> 4) * 8);  // trans: rows t, cols d

    float m0 = -1e30f, m1 = -1e30f, l0 = 0.f, l1 = 0.f;
    float accO[8][4];
#pragma unroll
    for (int f = 0; f < 8; f++)
#pragma unroll
        for (int v = 0; v < 4; v++) accO[f][v] = 0.f;

    for (int it = t0; it < t1; ++it) {
        const int li = it - t0;
        const uint32_t uK = (li & 1) ? uKb : uKa;
        CP_WAIT1();            // K(it) ready
        __syncthreads();

        // ---- phase 1: Sc = Qc @ K^T ----
        float accS[16][4];
#pragma unroll
        for (int f = 0; f < 16; f++)
#pragma unroll
            for (int v = 0; v < 4; v++) accS[f][v] = 0.f;
#pragma unroll
        for (int ks = 0; ks < 4; ks++) {
            uint32_t a[4];
            ldsm_x4(a, uQ + (aOffQ + ks * 16) * 2u);
#pragma unroll
            for (int fp = 0; fp < 8; fp++) {
                uint32_t r[4];
                ldsm_x4(r, uK + (bOffK + fp * 16 * 72 + ks * 16) * 2u);
                uint32_t b0[2] = {r[0], r[1]};
                uint32_t b1[2] = {r[2], r[3]};
                mma_f16(accS[2 * fp], a, b0);
                mma_f16(accS[2 * fp + 1], a, b1);
            }
        }

        // ---- prefetch next K ----
        {
            int kn = (it + 1 < t1) ? (it + 1) : (t1 - 1);
            load_k(kn, ((li + 1) & 1) ? uKb : uKa);
            CP_COMMIT();
        }

        CP_WAIT1();            // Sr(it) + V(it) ready
        __syncthreads();

        // ---- add staged shifted Sr, scale, mask; online softmax ----
        const int k0 = it * 128;
        const bool lastT = (it == nT - 1);
        const int lim0 = MEMN + qg0 - k0;
        const int lim1 = lim0 + 8;

        __half* p0 = sP + lr0 * 136;
        __half* p1 = p0 + 8 * 136;

        float rm0 = -1e30f, rm1 = -1e30f;
#pragma unroll
        for (int fn = 0; fn < 16; fn++) {
            int kc = fn * 8 + 2 * c4;
            float2 f0 = __half22float2(*(const __half2*)(p0 + kc));
            float2 f1 = __half22float2(*(const __half2*)(p1 + kc));
            float s0, s1, s2, s3;
            s0 = (!lastT || kc     <= lim0) ? (accS[fn][0] + f0.x) * 0.125f : -1e30f;
            s1 = (!lastT || kc + 1 <= lim0) ? (accS[fn][1] + f0.y) * 0.125f : -1e30f;
            s2 = (!lastT || kc     <= lim1) ? (accS[fn][2] + f1.x) * 0.125f : -1e30f;
            s3 = (!lastT || kc + 1 <= lim1) ? (accS[fn][3] + f1.y) * 0.125f : -1e30f;
            accS[fn][0] = s0; accS[fn][1] = s1; accS[fn][2] = s2; accS[fn][3] = s3;
            rm0 = fmaxf(rm0, fmaxf(s0, s1));
            rm1 = fmaxf(rm1, fmaxf(s2, s3));
        }
        rm0 = fmaxf(rm0, __shfl_xor_sync(~0u, rm0, 1));
        rm0 = fmaxf(rm0, __shfl_xor_sync(~0u, rm0, 2));
        rm1 = fmaxf(rm1, __shfl_xor_sync(~0u, rm1, 1));
        rm1 = fmaxf(rm1, __shfl_xor_sync(~0u, rm1, 2));
        float mN0 = fmaxf(m0, rm0), mN1 = fmaxf(m1, rm1);
        float al0 = __expf(m0 - mN0), al1 = __expf(m1 - mN1);
        m0 = mN0; m1 = mN1;

        float ps0 = 0.f, ps1 = 0.f;
#pragma unroll
        for (int fn = 0; fn < 16; fn++) {
            int kc = fn * 8 + 2 * c4;
            float e0 = __expf(accS[fn][0] - m0);
            float e1 = __expf(accS[fn][1] - m0);
            float e2 = __expf(accS[fn][2] - m1);
            float e3 = __expf(accS[fn][3] - m1);
            ps0 += e0 + e1; ps1 += e2 + e3;
            *(__half2*)(p0 + kc) = __floats2half2_rn(e0, e1);
            *(__half2*)(p1 + kc) = __floats2half2_rn(e2, e3);
        }
        ps0 += __shfl_xor_sync(~0u, ps0, 1); ps0 += __shfl_xor_sync(~0u, ps0, 2);
        ps1 += __shfl_xor_sync(~0u, ps1, 1); ps1 += __shfl_xor_sync(~0u, ps1, 2);
        l0 = l0 * al0 + ps0;
        l1 = l1 * al1 + ps1;
#pragma unroll
        for (int f = 0; f < 8; f++) {
            accO[f][0] *= al0; accO[f][1] *= al0;
            accO[f][2] *= al1; accO[f][3] *= al1;
        }
        __syncwarp();          // P rows are per-warp private

        // ---- phase 2: O += P @ V (V via ldmatrix.trans from [t][d]) ----
#pragma unroll
        for (int ks = 0; ks < 8; ks++) {
            uint32_t a[4];
            ldsm_x4(a, uP + (aOffP + ks * 16) * 2u);
#pragma unroll
            for (int fp = 0; fp < 4; fp++) {
                uint32_t r[4];
                ldsm_x4t(r, uV + (bOffV + ks * 16 * 72 + fp * 16) * 2u);
                uint32_t b0[2] = {r[0], r[1]};
                uint32_t b1[2] = {r[2], r[3]};
                mma_f16(accO[2 * fp], a, b0);
                mma_f16(accO[2 * fp + 1], a, b1);
            }
        }
        __syncthreads();       // everyone done with sP / sV

        // ---- prefetch next Sr + V ----
        {
            int vn = (it + 1 < t1) ? (it + 1) : (t1 - 1);
            load_sr(vn);
            load_v(vn);
            CP_COMMIT();
        }
    }

    // ---- epilogue ----
    const size_t base0 = ((size_t)b * HH + h) * QQ + qg0;
    const size_t base1 = base0 + 8;
    float* o0 = g_opart + (base0 * KSPLIT + split) * DHH;
    float* o1 = g_opart + (base1 * KSPLIT + split) * DHH;
#pragma unroll
    for (int fn = 0; fn < 8; fn++) {
        int col = fn * 8 + 2 * c4;
        *(float2*)(o0 + col) = make_float2(accO[fn][0], accO[fn][1]);
        *(float2*)(o1 + col) = make_float2(accO[fn][2], accO[fn][3]);
    }
    if (c4 == 0) {
        float* ml0 = g_ml + (base0 * KSPLIT + split) * 2;
        float* ml1 = g_ml + (base1 * KSPLIT + split) * 2;
        ml0[0] = m0; ml0[1] = l0;
        ml1[0] = m1; ml1[1] = l1;
    }
}

// ---------------------------------------------------------------------------
// Combine split-K partials -> ctx (fp16)
// ---------------------------------------------------------------------------
__global__ void __launch_bounds__(256) combine_kernel() {
    const int col = threadIdx.x & 63;
    const int rloc = threadIdx.x >> 6;
    const int q = blockIdx.x * 4 + rloc;
    const int h = blockIdx.y, b = blockIdx.z;
    const size_t base = ((size_t)b * HH + h) * QQ + q;

    float m[KSPLIT], l[KSPLIT];
#pragma unroll
    for (int s = 0; s < KSPLIT; s++) {
        m[s] = g_ml[(base * KSPLIT + s) * 2 + 0];
        l[s] = g_ml[(base * KSPLIT + s) * 2 + 1];
    }
    float mx = m[0];
#pragma unroll
    for (int s = 1; s < KSPLIT; s++) mx = fmaxf(mx, m[s]);
    float w[KSPLIT], L = 0.f;
#pragma unroll
    for (int s = 0; s < KSPLIT; s++) { w[s] = __expf(m[s] - mx); L += l[s] * w[s]; }
    const float inv = 1.0f / L;

    float o = 0.f;
#pragma unroll
    for (int s = 0; s < KSPLIT; s++)
        o += g_opart[(base * KSPLIT + s) * DHH + col] * w[s];
    g_ctxh[((size_t)b * QQ + q) * UU + h * 64 + col] = __float2half(o * inv);
}

// ---------------------------------------------------------------------------
// Launch
// ---------------------------------------------------------------------------
extern "C" void kernel_launch(void* const* d_in, const int* in_sizes, int n_in,
                              void* d_out, int out_size) {
    const float* inputs    = (const float*)d_in[0];
    const float* relatives = (const float*)d_in[1];
    const float* memories  = (const float*)d_in[2];
    const float* bias_c    = (const float*)d_in[3];
    const float* bias_r    = (const float*)d_in[4];
    const float* Wq        = (const float*)d_in[5];
    const float* Wkv       = (const float*)d_in[6];
    const float* Wr        = (const float*)d_in[7];
    const float* Wo        = (const float*)d_in[8];
    float* out             = (float*)d_out;

    __half *p_fullh, *p_relrh, *p_qch, *p_qrh, *p_kh, *p_vh, *p_wrh, *p_srh, *p_ctxh;
    __half *p_wqTh, *p_wkvTh, *p_wrTh, *p_woTh;
    cudaGetSymbolAddress((void**)&p_fullh, g_fullh);
    cudaGetSymbolAddress((void**)&p_relrh, g_relrh);
    cudaGetSymbolAddress((void**)&p_qch,   g_qch);
    cudaGetSymbolAddress((void**)&p_qrh,   g_qrh);
    cudaGetSymbolAddress((void**)&p_kh,    g_kh);
    cudaGetSymbolAddress((void**)&p_vh,    g_vh);
    cudaGetSymbolAddress((void**)&p_wrh,   g_wrh);
    cudaGetSymbolAddress((void**)&p_srh,   g_srh);
    cudaGetSymbolAddress((void**)&p_ctxh,  g_ctxh);
    cudaGetSymbolAddress((void**)&p_wqTh,  g_wqTh);
    cudaGetSymbolAddress((void**)&p_wkvTh, g_wkvTh);
    cudaGetSymbolAddress((void**)&p_wrTh,  g_wrTh);
    cudaGetSymbolAddress((void**)&p_woTh,  g_woTh);

    constexpr int SMEM_G = 3 * (128 + 128) * 40 * 2;                    // 61440
    constexpr int SMEM_F = (3 * 128 * 72 + 128 * 72 + 128 * 136) * 2;   // 108544
    cudaFuncSetAttribute((const void*)hgemm<128,128,64,32,0>,
                         cudaFuncAttributeMaxDynamicSharedMemorySize, SMEM_G);
    cudaFuncSetAttribute((const void*)hgemm<128,128,64,32,2>,
                         cudaFuncAttributeMaxDynamicSharedMemorySize, SMEM_G);
    cudaFuncSetAttribute((const void*)hgemm<128,128,64,32,3>,
                         cudaFuncAttributeMaxDynamicSharedMemorySize, SMEM_G);
    cudaFuncSetAttribute((const void*)hgemm<128,128,64,32,4>,
                         cudaFuncAttributeMaxDynamicSharedMemorySize, SMEM_G);
    cudaFuncSetAttribute((const void*)hgemm<128,128,64,32,5>,
                         cudaFuncAttributeMaxDynamicSharedMemorySize, SMEM_G);
    cudaFuncSetAttribute((const void*)flash_kernel,
                         cudaFuncAttributeMaxDynamicSharedMemorySize, SMEM_F);

    // 0. all weight transposes in one launch
    wtrans_kernel<<<5120, dim3(32, 8)>>>(Wq, Wkv, Wr, Wo);

    // 1. fullh = fp16(concat); relrh = fp16(relatives) (one launch)
    {
        size_t total4 = (size_t)BB * KL * UU / 4;
        prep_kernel<<<(unsigned)((2 * total4 + 255) / 256), 256>>>(memories, inputs, relatives);
    }

    // 2. qc / qr = fp16(inputs @ Wq + bias_{c,r})
    hgemm<128,128,64,32,2><<<dim3(UU/128, QQ/128, BB), 256, SMEM_G>>>(
        p_fullh + (size_t)MEMN * UU, UU, (long long)KL * UU, 0,
        p_wqTh, UU, 0, 0,
        p_qch, UU, (long long)QQ * UU, 0, UU, 1,
        p_qrh, bias_c, bias_r);

    // 3. w_kv = full @ Wkv : K -> g_kh, V -> g_vh
    hgemm<128,128,64,32,4><<<dim3((2*UU)/128, (BB*KL)/128, 1), 256, SMEM_G>>>(
        p_fullh, UU, 0, 0, p_wkvTh, UU, 0, 0,
        p_vh, UU, 0, 0, UU, 1,
        p_kh, nullptr, nullptr);

    // 4. w_r = relatives @ Wr  (fp16)
    hgemm<128,128,64,32,3><<<dim3(UU/128, (BB*KL)/128, 1), 256, SMEM_G>>>(
        p_relrh, UU, 0, 0, p_wrTh, UU, 0, 0, p_wrh, UU, 0, 0, UU, 1,
        nullptr, nullptr, nullptr);

    // 5. SrShift[b,h,q,k] = (qr @ wr^T)[q, k + Q-1-q]  (shifted fp16 store)
    hgemm<128,128,64,32,5><<<dim3(KL/128, QQ/128, BB*HH), 256, SMEM_G>>>(
        p_qrh, UU, (long long)QQ * UU, 64,
        p_wrh, UU, (long long)KL * UU, 64,
        p_srh, KL, (long long)HH * QQ * KL, (long long)QQ * KL,
        DHH, HH, nullptr, nullptr, nullptr);

    // 6. split-K fused fp16 flash -> partials
    flash_kernel<<<dim3(8 * KSPLIT, HH, BB), 256, SMEM_F>>>();

    // 7. combine partials -> ctx (fp16)
    combine_kernel<<<dim3(QQ / 4, HH, BB), 256>>>();

    // 8. out = ctx @ Wo (fp32 out)
    hgemm<128,128,64,32,0><<<dim3(UU/128, (BB*QQ)/128, 1), 256, SMEM_G>>>(
        p_ctxh, UU, 0, 0, p_woTh, UU, 0, 0, out, UU, 0, 0, UU, 1,
        nullptr, nullptr, nullptr);
}

// round 11
// speedup vs baseline: 2.1745x; 1.0937x over previous
#include <cuda_runtime.h>
#include <cuda_fp16.h>
#include <cstdint>

// Problem constants
#define BB   2
#define QQ   1024
#define MEMN 1024
#define UU   1024
#define HH   16
#define DHH  64
#define KL   2048   // MEM + Q
#define KSPLIT 3

// ---------------------------------------------------------------------------
// Scratch (allocation-free: __device__ globals, 16B-aligned for cp.async)
// ---------------------------------------------------------------------------
__device__ __align__(16) __half g_fullh[(size_t)BB * KL * UU];     // fp16 concat
__device__ __align__(16) __half g_relrh[(size_t)BB * KL * UU];     // fp16 relatives
__device__ __align__(16) __half g_qch [(size_t)BB * QQ * UU];      // fp16 q + bias_c
__device__ __align__(16) __half g_qrh [(size_t)BB * QQ * UU];      // fp16 q + bias_r
__device__ __align__(16) __half g_kh  [(size_t)BB * KL * UU];      // fp16 K
__device__ __align__(16) __half g_vh  [(size_t)BB * KL * UU];      // fp16 V  [b,t,u]
__device__ __align__(16) __half g_wrh [(size_t)BB * KL * UU];      // fp16 w_r
__device__ __align__(16) __half g_srh [(size_t)BB * HH * QQ * KL]; // fp16 Sr SHIFTED
__device__ __align__(16) __half g_ctxh[(size_t)BB * QQ * UU];      // fp16 attention out
__device__ __align__(16) __half g_wqTh [(size_t)UU * UU];
__device__ __align__(16) __half g_wkvTh[(size_t)2 * UU * UU];
__device__ __align__(16) __half g_wrTh [(size_t)UU * UU];
__device__ __align__(16) __half g_woTh [(size_t)UU * UU];
__device__ float g_opart[(size_t)BB * HH * QQ * KSPLIT * DHH];
__device__ float g_ml   [(size_t)BB * HH * QQ * KSPLIT * 2];

// ---------------------------------------------------------------------------
// Helpers
// ---------------------------------------------------------------------------
__device__ __forceinline__ uint32_t smem_to_u32(const void* p) {
    uint32_t a;
    asm("{ .reg .u64 t; cvta.to.shared.u64 t, %1; cvt.u32.u64 %0, t; }" : "=r"(a) : "l"(p));
    return a;
}
__device__ __forceinline__ void cp_async16(uint32_t saddr, const void* gaddr) {
    asm volatile("cp.async.cg.shared.global [%0], [%1], 16;" :: "r"(saddr), "l"(gaddr));
}
#define CP_COMMIT() asm volatile("cp.async.commit_group;" ::: "memory")
#define CP_WAIT1()  asm volatile("cp.async.wait_group 1;" ::: "memory")
#define CP_WAIT2()  asm volatile("cp.async.wait_group 2;" ::: "memory")

__device__ __forceinline__ void mma_f16(float acc[4], const uint32_t a[4], const uint32_t b[2]) {
    asm volatile("mma.sync.aligned.m16n8k16.row.col.f32.f16.f16.f32 "
        "{%0,%1,%2,%3}, {%4,%5,%6,%7}, {%8,%9}, {%0,%1,%2,%3};"
        : "+f"(acc[0]), "+f"(acc[1]), "+f"(acc[2]), "+f"(acc[3])
        : "r"(a[0]), "r"(a[1]), "r"(a[2]), "r"(a[3]), "r"(b[0]), "r"(b[1]));
}
__device__ __forceinline__ void ldsm_x4(uint32_t* r, uint32_t addr) {
    asm volatile("ldmatrix.sync.aligned.m8n8.x4.shared.b16 {%0,%1,%2,%3}, [%4];"
        : "=r"(r[0]), "=r"(r[1]), "=r"(r[2]), "=r"(r[3]) : "r"(addr));
}
__device__ __forceinline__ void ldsm_x4t(uint32_t* r, uint32_t addr) {
    asm volatile("ldmatrix.sync.aligned.m8n8.x4.trans.shared.b16 {%0,%1,%2,%3}, [%4];"
        : "=r"(r[0]), "=r"(r[1]), "=r"(r[2]), "=r"(r[3]) : "r"(addr));
}

// ---------------------------------------------------------------------------
// prep: concat(memories, inputs) -> g_fullh ; relatives -> g_relrh (fp16)
// ---------------------------------------------------------------------------
__global__ void prep_kernel(const float* __restrict__ mem,
                            const float* __restrict__ inp,
                            const float* __restrict__ rel) {
    const size_t total4 = (size_t)BB * KL * UU / 4;
    size_t i = (size_t)blockIdx.x * blockDim.x + threadIdx.x;
    if (i < total4) {
        size_t elem = i * 4;
        int b = (int)(elem / ((size_t)KL * UU));
        size_t rem = elem % ((size_t)KL * UU);
        int t = (int)(rem / UU);
        int u = (int)(rem % UU);
        float4 v;
        if (t < MEMN) v = *(const float4*)(mem + ((size_t)b * MEMN + t) * UU + u);
        else          v = *(const float4*)(inp + ((size_t)b * QQ + (t - MEMN)) * UU + u);
        __half2* o = (__half2*)(g_fullh + elem);
        o[0] = __floats2half2_rn(v.x, v.y);
        o[1] = __floats2half2_rn(v.z, v.w);
    } else if (i < 2 * total4) {
        size_t j = i - total4;
        float4 v = ((const float4*)rel)[j];
        __half2* o = (__half2*)(g_relrh + j * 4);
        o[0] = __floats2half2_rn(v.x, v.y);
        o[1] = __floats2half2_rn(v.z, v.w);
    }
}

// ---------------------------------------------------------------------------
// Fused weight transposes: W[K=1024, N] row-major -> W^T[N, 1024] fp16
// ---------------------------------------------------------------------------
__global__ void wtrans_kernel(const float* __restrict__ Wq, const float* __restrict__ Wkv,
                              const float* __restrict__ Wr, const float* __restrict__ Wo) {
    __shared__ float t[32][33];
    int bid = blockIdx.x;
    const float* in; __half* out; int cols;
    if (bid < 1024)      { in = Wq;  out = g_wqTh;  cols = 1024; }
    else if (bid < 3072) { in = Wkv; out = g_wkvTh; cols = 2048; bid -= 1024; }
    else if (bid < 4096) { in = Wr;  out = g_wrTh;  cols = 1024; bid -= 3072; }
    else                 { in = Wo;  out = g_woTh;  cols = 1024; bid -= 4096; }
    int tilesX = cols / 32;
    int c0 = (bid % tilesX) * 32;
    int r0 = (bid / tilesX) * 32;
    int tx = threadIdx.x, ty = threadIdx.y;
#pragma unroll
    for (int i = 0; i < 32; i += 8)
        t[ty + i][tx] = in[(size_t)(r0 + ty + i) * cols + c0 + tx];
    __syncthreads();
#pragma unroll
    for (int i = 0; i < 32; i += 8)
        out[(size_t)(c0 + ty + i) * 1024 + r0 + tx] = __float2half(t[tx][ty + i]);
}

// ===========================================================================
// Shared GEMM mainloop machinery (BM=BN=128, WM=64, WN=32, KC=32, 4 stages)
// ===========================================================================
#define G_LDSS 40
#define G_KC   32

// ---------------------------------------------------------------------------
// Merged projection GEMM: one launch covers wkv (EPI4), wr (EPI3), wq (EPI2).
// Flat grid: [0,512) wkv | [512,768) wr | [768,896) wq.
// ---------------------------------------------------------------------------
__global__ void __launch_bounds__(256)
proj_kernel(const float* __restrict__ bc, const float* __restrict__ br) {
    constexpr int BM = 128, BN = 128, WM = 64, WN = 32;
    constexpr int MFRAG = WM / 16, NFRAG = WN / 8;

    int cta = blockIdx.x;
    int epi;
    const __half* A;
    const __half* Bw;
    __half *Ch = nullptr, *C2h = nullptr;
    int bm, bn;
    if (cta < 512) {               // wkv: 16 bx x 32 by, M = BB*KL
        epi = 4;
        int bx = cta & 15, by = cta >> 4;
        A = g_fullh; Bw = g_wkvTh;
        Ch = g_vh; C2h = g_kh;
        bm = by * BM; bn = bx * BN;
    } else if (cta < 768) {        // wr: 8 bx x 32 by
        epi = 3;
        int c = cta - 512;
        int bx = c & 7, by = c >> 3;
        A = g_relrh; Bw = g_wrTh;
        Ch = g_wrh;
        bm = by * BM; bn = bx * BN;
    } else {                       // wq: 8 bx x 8 by x 2 z
        epi = 2;
        int c = cta - 768;
        int bx = c & 7, by = (c >> 3) & 7, zz = c >> 6;
        A = g_fullh + (size_t)MEMN * UU + (size_t)zz * KL * UU;
        Bw = g_wqTh;
        Ch = g_qch + (size_t)zz * QQ * UU;
        C2h = g_qrh + (size_t)zz * QQ * UU;
        bm = by * BM; bn = bx * BN;
    }
    const int lda = UU, ldb = UU, ldc = (epi == 4) ? UU : UU;  // all 1024 (kv split handled below)
    const int ldcO = (epi == 4) ? UU : UU;
    (void)ldcO;
    const int K = UU;
    const int nIter = K / G_KC;    // 32

    extern __shared__ __half smh[];
    __half* As = smh;
    __half* Bs = smh + 4 * BM * G_LDSS;
    const uint32_t sA_base = smem_to_u32(As);
    const uint32_t sB_base = smem_to_u32(Bs);

    const int tid = threadIdx.x;
    const int lane = tid & 31;
    const int warp = tid >> 5;
    const int wm = warp & 1;       // WARPS_M = 2
    const int wn = warp >> 1;      // WARPS_N = 4
    const __half* Ag = A + (size_t)bm * lda;
    const __half* Bg = Bw + (size_t)bn * ldb;

    auto load_stage = [&](int stage, int buf) {
#pragma unroll
        for (int i = 0; i < 2; i++) {
            int idx = tid + i * 256;
            int row = idx >> 2, ch = idx & 3;
            uint32_t s = sA_base + (uint32_t)(buf * BM * G_LDSS + row * G_LDSS + ch * 8) * 2u;
            cp_async16(s, Ag + (size_t)row * lda + stage * G_KC + ch * 8);
        }
#pragma unroll
        for (int i = 0; i < 2; i++) {
            int idx = tid + i * 256;
            int row = idx >> 2, ch = idx & 3;
            uint32_t s = sB_base + (uint32_t)(buf * BN * G_LDSS + row * G_LDSS + ch * 8) * 2u;
            cp_async16(s, Bg + (size_t)row * ldb + stage * G_KC + ch * 8);
        }
    };

    float acc[MFRAG][NFRAG][4];
#pragma unroll
    for (int i = 0; i < MFRAG; i++)
#pragma unroll
        for (int j = 0; j < NFRAG; j++)
#pragma unroll
            for (int v = 0; v < 4; v++) acc[i][j][v] = 0.0f;

    load_stage(0, 0); CP_COMMIT();
    load_stage(1, 1); CP_COMMIT();
    load_stage(2, 2); CP_COMMIT();

    const uint32_t aOff = (uint32_t)((wm * WM + (lane & 15)) * G_LDSS + (lane >> 4) * 8);
    const uint32_t bOff = (uint32_t)((wn * WN + (lane & 7) + (lane >> 4) * 8) * G_LDSS +
                                     ((lane >> 3) & 1) * 8);
    const int r4 = lane >> 2;
    const int c4 = lane & 3;

    for (int it = 0; it < nIter; ++it) {
        CP_WAIT2();
        __syncthreads();
        if (it + 3 < nIter) load_stage(it + 3, (it + 3) & 3);
        CP_COMMIT();

        const uint32_t aBuf = sA_base + (uint32_t)((it & 3) * BM * G_LDSS) * 2u;
        const uint32_t bBuf = sB_base + (uint32_t)((it & 3) * BN * G_LDSS) * 2u;

#pragma unroll
        for (int ks = 0; ks < 2; ks++) {
            uint32_t af[MFRAG][4];
            uint32_t bf[NFRAG][2];
#pragma unroll
            for (int fm = 0; fm < MFRAG; fm++)
                ldsm_x4(af[fm], aBuf + (aOff + fm * 16 * G_LDSS + ks * 16) * 2u);
#pragma unroll
            for (int fp = 0; fp < NFRAG / 2; fp++) {
                uint32_t r[4];
                ldsm_x4(r, bBuf + (bOff + fp * 16 * G_LDSS + ks * 16) * 2u);
                bf[2 * fp][0] = r[0]; bf[2 * fp][1] = r[1];
                bf[2 * fp + 1][0] = r[2]; bf[2 * fp + 1][1] = r[3];
            }
#pragma unroll
            for (int fm = 0; fm < MFRAG; fm++)
#pragma unroll
                for (int fn = 0; fn < NFRAG; fn++)
                    mma_f16(acc[fm][fn], af[fm], bf[fn]);
        }
    }

    const int m0 = bm + wm * WM;
    const int n0 = bn + wn * WN;
#pragma unroll
    for (int fm = 0; fm < MFRAG; fm++) {
#pragma unroll
        for (int fn = 0; fn < NFRAG; fn++) {
            int r = m0 + fm * 16 + r4;
            int cidx = n0 + fn * 8 + c4 * 2;
            float a0 = acc[fm][fn][0], a1 = acc[fm][fn][1];
            float a2 = acc[fm][fn][2], a3 = acc[fm][fn][3];
            if (epi == 4) {
                if (cidx < UU) {
                    *(__half2*)(C2h + (size_t)r * UU + cidx) = __floats2half2_rn(a0, a1);
                    *(__half2*)(C2h + (size_t)(r + 8) * UU + cidx) = __floats2half2_rn(a2, a3);
                } else {
                    *(__half2*)(Ch + (size_t)r * UU + cidx - UU) = __floats2half2_rn(a0, a1);
                    *(__half2*)(Ch + (size_t)(r + 8) * UU + cidx - UU) = __floats2half2_rn(a2, a3);
                }
            } else if (epi == 3) {
                *(__half2*)(Ch + (size_t)r * ldc + cidx) = __floats2half2_rn(a0, a1);
                *(__half2*)(Ch + (size_t)(r + 8) * ldc + cidx) = __floats2half2_rn(a2, a3);
            } else {  // epi == 2
                float b0 = bc[cidx], b1 = bc[cidx + 1];
                float r0 = br[cidx], r1 = br[cidx + 1];
                *(__half2*)(Ch + (size_t)r * ldc + cidx) = __floats2half2_rn(a0 + b0, a1 + b1);
                *(__half2*)(Ch + (size_t)(r + 8) * ldc + cidx) = __floats2half2_rn(a2 + b0, a3 + b1);
                *(__half2*)(C2h + (size_t)r * ldc + cidx) = __floats2half2_rn(a0 + r0, a1 + r1);
                *(__half2*)(C2h + (size_t)(r + 8) * ldc + cidx) = __floats2half2_rn(a2 + r0, a3 + r1);
            }
        }
    }
}

// ---------------------------------------------------------------------------
// Templated GEMM (4-stage) for Sr shifted store (EPI 5) and Wo (EPI 0).
// ---------------------------------------------------------------------------
template <int EPI>
__global__ void __launch_bounds__(256)
hgemm(const __half* __restrict__ A, int lda, long long sA1, long long sA2,
      const __half* __restrict__ B, int ldb, long long sB1, long long sB2,
      void* __restrict__ Cv, int ldc, long long sC1, long long sC2,
      int K, int innerB) {
    constexpr int BM = 128, BN = 128, WM = 64, WN = 32;
    constexpr int MFRAG = WM / 16, NFRAG = WN / 8;

    const int bm = blockIdx.y * BM;
    const int bn = blockIdx.x * BN;
    if (EPI == 5) {
        if (bn + bm + BM + BN - 2 - (QQ - 1) < 0) return;  // fully below diagonal
    }

    extern __shared__ __half smh[];
    __half* As = smh;
    __half* Bs = smh + 4 * BM * G_LDSS;
    const uint32_t sA_base = smem_to_u32(As);
    const uint32_t sB_base = smem_to_u32(Bs);

    const int tid = threadIdx.x;
    const int lane = tid & 31;
    const int warp = tid >> 5;
    const int wm = warp & 1;
    const int wn = warp >> 1;

    const int z = blockIdx.z;
    const int z1 = z / innerB, z2 = z % innerB;
    A += (size_t)z1 * sA1 + (size_t)z2 * sA2;
    B += (size_t)z1 * sB1 + (size_t)z2 * sB2;
    float* C = nullptr;
    __half* Ch = nullptr;
    if (EPI == 0) C = (float*)Cv + (size_t)z1 * sC1 + (size_t)z2 * sC2;
    else          Ch = (__half*)Cv + (size_t)z1 * sC1 + (size_t)z2 * sC2;
    const __half* Ag = A + (size_t)bm * lda;
    const __half* Bg = B + (size_t)bn * ldb;

    const int nIter = K / G_KC;

    auto load_stage = [&](int stage, int buf) {
#pragma unroll
        for (int i = 0; i < 2; i++) {
            int idx = tid + i * 256;
            int row = idx >> 2, ch = idx & 3;
            uint32_t s = sA_base + (uint32_t)(buf * BM * G_LDSS + row * G_LDSS + ch * 8) * 2u;
            cp_async16(s, Ag + (size_t)row * lda + stage * G_KC + ch * 8);
        }
#pragma unroll
        for (int i = 0; i < 2; i++) {
            int idx = tid + i * 256;
            int row = idx >> 2, ch = idx & 3;
            uint32_t s = sB_base + (uint32_t)(buf * BN * G_LDSS + row * G_LDSS + ch * 8) * 2u;
            cp_async16(s, Bg + (size_t)row * ldb + stage * G_KC + ch * 8);
        }
    };

    float acc[MFRAG][NFRAG][4];
#pragma unroll
    for (int i = 0; i < MFRAG; i++)
#pragma unroll
        for (int j = 0; j < NFRAG; j++)
#pragma unroll
            for (int v = 0; v < 4; v++) acc[i][j][v] = 0.0f;

    load_stage(0, 0); CP_COMMIT();
    if (nIter > 1) load_stage(1, 1);
    CP_COMMIT();
    if (nIter > 2) load_stage(2, 2);
    CP_COMMIT();

    const uint32_t aOff = (uint32_t)((wm * WM + (lane & 15)) * G_LDSS + (lane >> 4) * 8);
    const uint32_t bOff = (uint32_t)((wn * WN + (lane & 7) + (lane >> 4) * 8) * G_LDSS +
                                     ((lane >> 3) & 1) * 8);
    const int r4 = lane >> 2;
    const int c4 = lane & 3;

    for (int it = 0; it < nIter; ++it) {
        CP_WAIT2();
        __syncthreads();
        if (it + 3 < nIter) load_stage(it + 3, (it + 3) & 3);
        CP_COMMIT();

        const uint32_t aBuf = sA_base + (uint32_t)((it & 3) * BM * G_LDSS) * 2u;
        const uint32_t bBuf = sB_base + (uint32_t)((it & 3) * BN * G_LDSS) * 2u;

#pragma unroll
        for (int ks = 0; ks < 2; ks++) {
            uint32_t af[MFRAG][4];
            uint32_t bf[NFRAG][2];
#pragma unroll
            for (int fm = 0; fm < MFRAG; fm++)
                ldsm_x4(af[fm], aBuf + (aOff + fm * 16 * G_LDSS + ks * 16) * 2u);
#pragma unroll
            for (int fp = 0; fp < NFRAG / 2; fp++) {
                uint32_t r[4];
                ldsm_x4(r, bBuf + (bOff + fp * 16 * G_LDSS + ks * 16) * 2u);
                bf[2 * fp][0] = r[0]; bf[2 * fp][1] = r[1];
                bf[2 * fp + 1][0] = r[2]; bf[2 * fp + 1][1] = r[3];
            }
#pragma unroll
            for (int fm = 0; fm < MFRAG; fm++)
#pragma unroll
                for (int fn = 0; fn < NFRAG; fn++)
                    mma_f16(acc[fm][fn], af[fm], bf[fn]);
        }
    }

    const int m0 = bm + wm * WM;
    const int n0 = bn + wn * WN;
#pragma unroll
    for (int fm = 0; fm < MFRAG; fm++) {
#pragma unroll
        for (int fn = 0; fn < NFRAG; fn++) {
            int r = m0 + fm * 16 + r4;
            int cidx = n0 + fn * 8 + c4 * 2;
            float a0 = acc[fm][fn][0], a1 = acc[fm][fn][1];
            float a2 = acc[fm][fn][2], a3 = acc[fm][fn][3];
            if (EPI == 0) {
                *(float2*)(C + (size_t)r * ldc + cidx) = make_float2(a0, a1);
                *(float2*)(C + (size_t)(r + 8) * ldc + cidx) = make_float2(a2, a3);
            } else {   // EPI == 5: shifted store
                int k0s = cidx - (QQ - 1) + r;
                __half h0 = __float2half(a0), h1 = __float2half(a1);
                if (k0s >= 0 && (k0s & 1) == 0) {
                    *(__half2*)(Ch + (size_t)r * ldc + k0s) = __halves2half2(h0, h1);
                } else {
                    if (k0s >= 0)     Ch[(size_t)r * ldc + k0s]     = h0;
                    if (k0s + 1 >= 0) Ch[(size_t)r * ldc + k0s + 1] = h1;
                }
                int r2 = r + 8;
                int k1s = cidx - (QQ - 1) + r2;
                __half h2 = __float2half(a2), h3 = __float2half(a3);
                if (k1s >= 0 && (k1s & 1) == 0) {
                    *(__half2*)(Ch + (size_t)r2 * ldc + k1s) = __halves2half2(h2, h3);
                } else {
                    if (k1s >= 0)     Ch[(size_t)r2 * ldc + k1s]     = h2;
                    if (k1s + 1 >= 0) Ch[(size_t)r2 * ldc + k1s + 1] = h3;
                }
            }
        }
    }
}

// ---------------------------------------------------------------------------
// Split-K fused fp16 flash attention (unchanged from R10).
// ---------------------------------------------------------------------------
__global__ void __launch_bounds__(256, 2) flash_kernel() {
    extern __shared__ __half smh[];
    __half* sQ  = smh;                  // [128][72]
    __half* sKa = sQ  + 128 * 72;
    __half* sKb = sKa + 128 * 72;
    __half* sV  = sKb + 128 * 72;       // [128 t][72 d]
    __half* sP  = sV  + 128 * 72;       // [128][136]
    const uint32_t uQ  = smem_to_u32(sQ);
    const uint32_t uKa = smem_to_u32(sKa);
    const uint32_t uKb = smem_to_u32(sKb);
    const uint32_t uV  = smem_to_u32(sV);
    const uint32_t uP  = smem_to_u32(sP);

    const int tid = threadIdx.x, lane = tid & 31, warp = tid >> 5;
    const int r4 = lane >> 2, c4 = lane & 3;
    const int qs = (int)blockIdx.x;
    const int qt = 7 - (qs / KSPLIT);
    const int split = qs % KSPLIT;
    const int h = blockIdx.y, b = blockIdx.z;
    const int q0 = qt * 128;
    const int nT = 9 + qt;
    const int t0 = (split * nT) / KSPLIT;
    const int t1 = ((split + 1) * nT) / KSPLIT;

    const __half* gQ = g_qch + ((size_t)b * QQ + q0) * UU + h * 64;
    const __half* gK = g_kh  + (size_t)b * KL * UU + h * 64;
    const __half* gV = g_vh  + (size_t)b * KL * UU + h * 64;
    const __half* gS = g_srh + (((size_t)b * HH + h) * QQ + q0) * KL;

    auto load_k = [&](int t, uint32_t dK) {
        const __half* src = gK + (size_t)t * 128 * UU;
        int i = tid;
#pragma unroll
        for (int rep = 0; rep < 4; rep++, i += 256) {
            int r = i >> 3, c = i & 7;
            cp_async16(dK + (uint32_t)(r * 72 + c * 8) * 2u, src + (size_t)r * UU + c * 8);
        }
    };
    auto load_v = [&](int t) {
        const __half* src = gV + (size_t)t * 128 * UU;
        int i = tid;
#pragma unroll
        for (int rep = 0; rep < 4; rep++, i += 256) {
            int r = i >> 3, c = i & 7;
            cp_async16(uV + (uint32_t)(r * 72 + c * 8) * 2u, src + (size_t)r * UU + c * 8);
        }
    };
    auto load_sr = [&](int t) {
        const __half* src = gS + (size_t)t * 128;
        int i = tid;
#pragma unroll
        for (int rep = 0; rep < 8; rep++, i += 256) {
            int r = i >> 4, c = i & 15;
            cp_async16(uP + (uint32_t)(r * 136 + c * 8) * 2u, src + (size_t)r * KL + c * 8);
        }
    };

    {
        int i = tid;
#pragma unroll
        for (int rep = 0; rep < 4; rep++, i += 256) {
            int r = i >> 3, c = i & 7;
            cp_async16(uQ + (uint32_t)(r * 72 + c * 8) * 2u, gQ + (size_t)r * UU + c * 8);
        }
        load_k(t0, uKa);
        CP_COMMIT();
        load_sr(t0);
        load_v(t0);
        CP_COMMIT();
    }

    const int lr0 = warp * 16 + r4;
    const int qg0 = q0 + lr0, qg1 = qg0 + 8;

    const uint32_t aOffQ = (uint32_t)((warp * 16 + (lane & 15)) * 72 + (lane >> 4) * 8);
    const uint32_t aOffP = (uint32_t)((warp * 16 + (lane & 15)) * 136 + (lane >> 4) * 8);
    const uint32_t bOffK = (uint32_t)(((lane & 7) + (lane >> 4) * 8) * 72 + ((lane >> 3) & 1) * 8);
    const uint32_t bOffV = (uint32_t)((lane & 15) * 72 + (lane >> 4) * 8);

    float m0 = -1e30f, m1 = -1e30f, l0 = 0.f, l1 = 0.f;
    float accO[8][4];
#pragma unroll
    for (int f = 0; f < 8; f++)
#pragma unroll
        for (int v = 0; v < 4; v++) accO[f][v] = 0.f;

    for (int it = t0; it < t1; ++it) {
        const int li = it - t0;
        const uint32_t uK = (li & 1) ? uKb : uKa;
        CP_WAIT1();
        __syncthreads();

        float accS[16][4];
#pragma unroll
        for (int f = 0; f < 16; f++)
#pragma unroll
            for (int v = 0; v < 4; v++) accS[f][v] = 0.f;
#pragma unroll
        for (int ks = 0; ks < 4; ks++) {
            uint32_t a[4];
            ldsm_x4(a, uQ + (aOffQ + ks * 16) * 2u);
#pragma unroll
            for (int fp = 0; fp < 8; fp++) {
                uint32_t r[4];
                ldsm_x4(r, uK + (bOffK + fp * 16 * 72 + ks * 16) * 2u);
                uint32_t b0[2] = {r[0], r[1]};
                uint32_t b1[2] = {r[2], r[3]};
                mma_f16(accS[2 * fp], a, b0);
                mma_f16(accS[2 * fp + 1], a, b1);
            }
        }

        {
            int kn = (it + 1 < t1) ? (it + 1) : (t1 - 1);
            load_k(kn, ((li + 1) & 1) ? uKb : uKa);
            CP_COMMIT();
        }

        CP_WAIT1();
        __syncthreads();

        const int k0 = it * 128;
        const bool lastT = (it == nT - 1);
        const int lim0 = MEMN + qg0 - k0;
        const int lim1 = lim0 + 8;

        __half* p0 = sP + lr0 * 136;
        __half* p1 = p0 + 8 * 136;

        float rm0 = -1e30f, rm1 = -1e30f;
#pragma unroll
        for (int fn = 0; fn < 16; fn++) {
            int kc = fn * 8 + 2 * c4;
            float2 f0 = __half22float2(*(const __half2*)(p0 + kc));
            float2 f1 = __half22float2(*(const __half2*)(p1 + kc));
            float s0, s1, s2, s3;
            s0 = (!lastT || kc     <= lim0) ? (accS[fn][0] + f0.x) * 0.125f : -1e30f;
            s1 = (!lastT || kc + 1 <= lim0) ? (accS[fn][1] + f0.y) * 0.125f : -1e30f;
            s2 = (!lastT || kc     <= lim1) ? (accS[fn][2] + f1.x) * 0.125f : -1e30f;
            s3 = (!lastT || kc + 1 <= lim1) ? (accS[fn][3] + f1.y) * 0.125f : -1e30f;
            accS[fn][0] = s0; accS[fn][1] = s1; accS[fn][2] = s2; accS[fn][3] = s3;
            rm0 = fmaxf(rm0, fmaxf(s0, s1));
            rm1 = fmaxf(rm1, fmaxf(s2, s3));
        }
        rm0 = fmaxf(rm0, __shfl_xor_sync(~0u, rm0, 1));
        rm0 = fmaxf(rm0, __shfl_xor_sync(~0u, rm0, 2));
        rm1 = fmaxf(rm1, __shfl_xor_sync(~0u, rm1, 1));
        rm1 = fmaxf(rm1, __shfl_xor_sync(~0u, rm1, 2));
        float mN0 = fmaxf(m0, rm0), mN1 = fmaxf(m1, rm1);
        float al0 = __expf(m0 - mN0), al1 = __expf(m1 - mN1);
        m0 = mN0; m1 = mN1;

        float ps0 = 0.f, ps1 = 0.f;
#pragma unroll
        for (int fn = 0; fn < 16; fn++) {
            int kc = fn * 8 + 2 * c4;
            float e0 = __expf(accS[fn][0] - m0);
            float e1 = __expf(accS[fn][1] - m0);
            float e2 = __expf(accS[fn][2] - m1);
            float e3 = __expf(accS[fn][3] - m1);
            ps0 += e0 + e1; ps1 += e2 + e3;
            *(__half2*)(p0 + kc) = __floats2half2_rn(e0, e1);
            *(__half2*)(p1 + kc) = __floats2half2_rn(e2, e3);
        }
        ps0 += __shfl_xor_sync(~0u, ps0, 1); ps0 += __shfl_xor_sync(~0u, ps0, 2);
        ps1 += __shfl_xor_sync(~0u, ps1, 1); ps1 += __shfl_xor_sync(~0u, ps1, 2);
        l0 = l0 * al0 + ps0;
        l1 = l1 * al1 + ps1;
#pragma unroll
        for (int f = 0; f < 8; f++) {
            accO[f][0] *= al0; accO[f][1] *= al0;
            accO[f][2] *= al1; accO[f][3] *= al1;
        }
        __syncwarp();

#pragma unroll
        for (int ks = 0; ks < 8; ks++) {
            uint32_t a[4];
            ldsm_x4(a, uP + (aOffP + ks * 16) * 2u);
#pragma unroll
            for (int fp = 0; fp < 4; fp++) {
                uint32_t r[4];
                ldsm_x4t(r, uV + (bOffV + ks * 16 * 72 + fp * 16) * 2u);
                uint32_t b0[2] = {r[0], r[1]};
                uint32_t b1[2] = {r[2], r[3]};
                mma_f16(accO[2 * fp], a, b0);
                mma_f16(accO[2 * fp + 1], a, b1);
            }
        }
        __syncthreads();

        {
            int vn = (it + 1 < t1) ? (it + 1) : (t1 - 1);
            load_sr(vn);
            load_v(vn);
            CP_COMMIT();
        }
    }

    const size_t base0 = ((size_t)b * HH + h) * QQ + qg0;
    const size_t base1 = base0 + 8;
    float* o0 = g_opart + (base0 * KSPLIT + split) * DHH;
    float* o1 = g_opart + (base1 * KSPLIT + split) * DHH;
#pragma unroll
    for (int fn = 0; fn < 8; fn++) {
        int col = fn * 8 + 2 * c4;
        *(float2*)(o0 + col) = make_float2(accO[fn][0], accO[fn][1]);
        *(float2*)(o1 + col) = make_float2(accO[fn][2], accO[fn][3]);
    }
    if (c4 == 0) {
        float* ml0 = g_ml + (base0 * KSPLIT + split) * 2;
        float* ml1 = g_ml + (base1 * KSPLIT + split) * 2;
        ml0[0] = m0; ml0[1] = l0;
        ml1[0] = m1; ml1[1] = l1;
    }
}

// ---------------------------------------------------------------------------
// Combine split-K partials -> ctx (fp16)
// ---------------------------------------------------------------------------
__global__ void __launch_bounds__(256) combine_kernel() {
    const int col = threadIdx.x & 63;
    const int rloc = threadIdx.x >> 6;
    const int q = blockIdx.x * 4 + rloc;
    const int h = blockIdx.y, b = blockIdx.z;
    const size_t base = ((size_t)b * HH + h) * QQ + q;

    float m[KSPLIT], l[KSPLIT];
#pragma unroll
    for (int s = 0; s < KSPLIT; s++) {
        m[s] = g_ml[(base * KSPLIT + s) * 2 + 0];
        l[s] = g_ml[(base * KSPLIT + s) * 2 + 1];
    }
    float mx = m[0];
#pragma unroll
    for (int s = 1; s < KSPLIT; s++) mx = fmaxf(mx, m[s]);
    float w[KSPLIT], L = 0.f;
#pragma unroll
    for (int s = 0; s < KSPLIT; s++) { w[s] = __expf(m[s] - mx); L += l[s] * w[s]; }
    const float inv = 1.0f / L;

    float o = 0.f;
#pragma unroll
    for (int s = 0; s < KSPLIT; s++)
        o += g_opart[(base * KSPLIT + s) * DHH + col] * w[s];
    g_ctxh[((size_t)b * QQ + q) * UU + h * 64 + col] = __float2half(o * inv);
}

// ---------------------------------------------------------------------------
// Launch
// ---------------------------------------------------------------------------
extern "C" void kernel_launch(void* const* d_in, const int* in_sizes, int n_in,
                              void* d_out, int out_size) {
    const float* inputs    = (const float*)d_in[0];
    const float* relatives = (const float*)d_in[1];
    const float* memories  = (const float*)d_in[2];
    const float* bias_c    = (const float*)d_in[3];
    const float* bias_r    = (const float*)d_in[4];
    const float* Wq        = (const float*)d_in[5];
    const float* Wkv       = (const float*)d_in[6];
    const float* Wr        = (const float*)d_in[7];
    const float* Wo        = (const float*)d_in[8];
    float* out             = (float*)d_out;

    __half *p_qrh, *p_wrh, *p_srh, *p_ctxh, *p_woTh;
    cudaGetSymbolAddress((void**)&p_qrh,   g_qrh);
    cudaGetSymbolAddress((void**)&p_wrh,   g_wrh);
    cudaGetSymbolAddress((void**)&p_srh,   g_srh);
    cudaGetSymbolAddress((void**)&p_ctxh,  g_ctxh);
    cudaGetSymbolAddress((void**)&p_woTh,  g_woTh);

    constexpr int SMEM_G = 4 * (128 + 128) * G_LDSS * 2;                // 81920
    constexpr int SMEM_F = (3 * 128 * 72 + 128 * 72 + 128 * 136) * 2;   // 108544
    cudaFuncSetAttribute((const void*)proj_kernel,
                         cudaFuncAttributeMaxDynamicSharedMemorySize, SMEM_G);
    cudaFuncSetAttribute((const void*)hgemm<0>,
                         cudaFuncAttributeMaxDynamicSharedMemorySize, SMEM_G);
    cudaFuncSetAttribute((const void*)hgemm<5>,
                         cudaFuncAttributeMaxDynamicSharedMemorySize, SMEM_G);
    cudaFuncSetAttribute((const void*)flash_kernel,
                         cudaFuncAttributeMaxDynamicSharedMemorySize, SMEM_F);

    // 0. all weight transposes in one launch
    wtrans_kernel<<<5120, dim3(32, 8)>>>(Wq, Wkv, Wr, Wo);

    // 1. fullh = fp16(concat); relrh = fp16(relatives)
    {
        size_t total4 = (size_t)BB * KL * UU / 4;
        prep_kernel<<<(unsigned)((2 * total4 + 255) / 256), 256>>>(memories, inputs, relatives);
    }

    // 2. merged projections: wkv | wr | wq  (896 CTAs, one launch)
    proj_kernel<<<896, 256, SMEM_G>>>(bias_c, bias_r);

    // 3. SrShift[b,h,q,k] = (qr @ wr^T)[q, k + Q-1-q]  (shifted fp16 store)
    hgemm<5><<<dim3(KL/128, QQ/128, BB*HH), 256, SMEM_G>>>(
        p_qrh, UU, (long long)QQ * UU, 64,
        p_wrh, UU, (long long)KL * UU, 64,
        p_srh, KL, (long long)HH * QQ * KL, (long long)QQ * KL,
        DHH, HH);

    // 4. split-K fused fp16 flash -> partials
    flash_kernel<<<dim3(8 * KSPLIT, HH, BB), 256, SMEM_F>>>();

    // 5. combine partials -> ctx (fp16)
    combine_kernel<<<dim3(QQ / 4, HH, BB), 256>>>();

    // 6. out = ctx @ Wo (fp32 out)
    hgemm<0><<<dim3(UU/128, (BB*QQ)/128, 1), 256, SMEM_G>>>(
        p_ctxh, UU, 0, 0, p_woTh, UU, 0, 0, out, UU, 0, 0, UU, 1);
}

// round 12
// speedup vs baseline: 2.4669x; 1.1344x over previous
#include <cuda_runtime.h>
#include <cuda_fp16.h>
#include <cstdint>

// Problem constants
#define BB   2
#define QQ   1024
#define MEMN 1024
#define UU   1024
#define HH   16
#define DHH  64
#define KL   2048   // MEM + Q
#define KSPLIT 3

// ---------------------------------------------------------------------------
// Scratch (allocation-free: __device__ globals, 16B-aligned for cp.async)
// ---------------------------------------------------------------------------
__device__ __align__(16) __half g_fullh[(size_t)BB * KL * UU];     // fp16 concat
__device__ __align__(16) __half g_relrh[(size_t)BB * KL * UU];     // fp16 relatives
__device__ __align__(16) __half g_qch [(size_t)BB * QQ * UU];      // fp16 q + bias_c
__device__ __align__(16) __half g_qrh [(size_t)BB * QQ * UU];      // fp16 q + bias_r
__device__ __align__(16) __half g_kh  [(size_t)BB * KL * UU];      // fp16 K
__device__ __align__(16) __half g_vh  [(size_t)BB * KL * UU];      // fp16 V  [b,t,u]
__device__ __align__(16) __half g_wrh [(size_t)BB * KL * UU];      // fp16 w_r
__device__ __align__(16) __half g_srh [(size_t)BB * HH * QQ * KL]; // fp16 Sr SHIFTED
__device__ __align__(16) __half g_ctxh[(size_t)BB * QQ * UU];      // fp16 attention out
__device__ __align__(16) __half g_wqTh [(size_t)UU * UU];
__device__ __align__(16) __half g_wkvTh[(size_t)2 * UU * UU];
__device__ __align__(16) __half g_wrTh [(size_t)UU * UU];
__device__ __align__(16) __half g_woTh [(size_t)UU * UU];
__device__ float g_opart[(size_t)BB * HH * QQ * KSPLIT * DHH];
__device__ float g_ml   [(size_t)BB * HH * QQ * KSPLIT * 2];

// ---------------------------------------------------------------------------
// Helpers
// ---------------------------------------------------------------------------
__device__ __forceinline__ uint32_t smem_to_u32(const void* p) {
    uint32_t a;
    asm("{ .reg .u64 t; cvta.to.shared.u64 t, %1; cvt.u32.u64 %0, t; }" : "=r"(a) : "l"(p));
    return a;
}
__device__ __forceinline__ void cp_async16(uint32_t saddr, const void* gaddr) {
    asm volatile("cp.async.cg.shared.global [%0], [%1], 16;" :: "r"(saddr), "l"(gaddr));
}
#define CP_COMMIT() asm volatile("cp.async.commit_group;" ::: "memory")
#define CP_WAIT0()  asm volatile("cp.async.wait_group 0;" ::: "memory")
#define CP_WAIT1()  asm volatile("cp.async.wait_group 1;" ::: "memory")
#define CP_WAIT2()  asm volatile("cp.async.wait_group 2;" ::: "memory")

__device__ __forceinline__ void mma_f16(float acc[4], const uint32_t a[4], const uint32_t b[2]) {
    asm volatile("mma.sync.aligned.m16n8k16.row.col.f32.f16.f16.f32 "
        "{%0,%1,%2,%3}, {%4,%5,%6,%7}, {%8,%9}, {%0,%1,%2,%3};"
        : "+f"(acc[0]), "+f"(acc[1]), "+f"(acc[2]), "+f"(acc[3])
        : "r"(a[0]), "r"(a[1]), "r"(a[2]), "r"(a[3]), "r"(b[0]), "r"(b[1]));
}
__device__ __forceinline__ void ldsm_x4(uint32_t* r, uint32_t addr) {
    asm volatile("ldmatrix.sync.aligned.m8n8.x4.shared.b16 {%0,%1,%2,%3}, [%4];"
        : "=r"(r[0]), "=r"(r[1]), "=r"(r[2]), "=r"(r[3]) : "r"(addr));
}
__device__ __forceinline__ void ldsm_x4t(uint32_t* r, uint32_t addr) {
    asm volatile("ldmatrix.sync.aligned.m8n8.x4.trans.shared.b16 {%0,%1,%2,%3}, [%4];"
        : "=r"(r[0]), "=r"(r[1]), "=r"(r[2]), "=r"(r[3]) : "r"(addr));
}

// ---------------------------------------------------------------------------
// prep: concat(memories, inputs) -> g_fullh ; relatives -> g_relrh (fp16)
// ---------------------------------------------------------------------------
__global__ void prep_kernel(const float* __restrict__ mem,
                            const float* __restrict__ inp,
                            const float* __restrict__ rel) {
    const size_t total4 = (size_t)BB * KL * UU / 4;
    size_t i = (size_t)blockIdx.x * blockDim.x + threadIdx.x;
    if (i < total4) {
        size_t elem = i * 4;
        int b = (int)(elem / ((size_t)KL * UU));
        size_t rem = elem % ((size_t)KL * UU);
        int t = (int)(rem / UU);
        int u = (int)(rem % UU);
        float4 v;
        if (t < MEMN) v = *(const float4*)(mem + ((size_t)b * MEMN + t) * UU + u);
        else          v = *(const float4*)(inp + ((size_t)b * QQ + (t - MEMN)) * UU + u);
        __half2* o = (__half2*)(g_fullh + elem);
        o[0] = __floats2half2_rn(v.x, v.y);
        o[1] = __floats2half2_rn(v.z, v.w);
    } else if (i < 2 * total4) {
        size_t j = i - total4;
        float4 v = ((const float4*)rel)[j];
        __half2* o = (__half2*)(g_relrh + j * 4);
        o[0] = __floats2half2_rn(v.x, v.y);
        o[1] = __floats2half2_rn(v.z, v.w);
    }
}

// ---------------------------------------------------------------------------
// Fused weight transposes: W[K=1024, N] row-major -> W^T[N, 1024] fp16
// ---------------------------------------------------------------------------
__global__ void wtrans_kernel(const float* __restrict__ Wq, const float* __restrict__ Wkv,
                              const float* __restrict__ Wr, const float* __restrict__ Wo) {
    __shared__ float t[32][33];
    int bid = blockIdx.x;
    const float* in; __half* out; int cols;
    if (bid < 1024)      { in = Wq;  out = g_wqTh;  cols = 1024; }
    else if (bid < 3072) { in = Wkv; out = g_wkvTh; cols = 2048; bid -= 1024; }
    else if (bid < 4096) { in = Wr;  out = g_wrTh;  cols = 1024; bid -= 3072; }
    else                 { in = Wo;  out = g_woTh;  cols = 1024; bid -= 4096; }
    int tilesX = cols / 32;
    int c0 = (bid % tilesX) * 32;
    int r0 = (bid / tilesX) * 32;
    int tx = threadIdx.x, ty = threadIdx.y;
#pragma unroll
    for (int i = 0; i < 32; i += 8)
        t[ty + i][tx] = in[(size_t)(r0 + ty + i) * cols + c0 + tx];
    __syncthreads();
#pragma unroll
    for (int i = 0; i < 32; i += 8)
        out[(size_t)(c0 + ty + i) * 1024 + r0 + tx] = __float2half(t[tx][ty + i]);
}

// ===========================================================================
// Shared GEMM constants (BM=BN=128, WM=64, WN=32, KC=32)
// ===========================================================================
#define G_LDSS 40
#define G_KC   32

// ---------------------------------------------------------------------------
// Merged projection GEMM: one launch covers wkv (EPI4), wr (EPI3), wq (EPI2).
// Flat grid: [0,512) wkv | [512,768) wr | [768,896) wq. 4-stage pipeline.
// ---------------------------------------------------------------------------
__global__ void __launch_bounds__(256)
proj_kernel(const float* __restrict__ bc, const float* __restrict__ br) {
    constexpr int BM = 128, BN = 128, WM = 64, WN = 32;
    constexpr int MFRAG = WM / 16, NFRAG = WN / 8;

    int cta = blockIdx.x;
    int epi;
    const __half* A;
    const __half* Bw;
    __half *Ch = nullptr, *C2h = nullptr;
    int bm, bn;
    if (cta < 512) {               // wkv
        epi = 4;
        int bx = cta & 15, by = cta >> 4;
        A = g_fullh; Bw = g_wkvTh;
        Ch = g_vh; C2h = g_kh;
        bm = by * BM; bn = bx * BN;
    } else if (cta < 768) {        // wr
        epi = 3;
        int c = cta - 512;
        int bx = c & 7, by = c >> 3;
        A = g_relrh; Bw = g_wrTh;
        Ch = g_wrh;
        bm = by * BM; bn = bx * BN;
    } else {                       // wq
        epi = 2;
        int c = cta - 768;
        int bx = c & 7, by = (c >> 3) & 7, zz = c >> 6;
        A = g_fullh + (size_t)MEMN * UU + (size_t)zz * KL * UU;
        Bw = g_wqTh;
        Ch = g_qch + (size_t)zz * QQ * UU;
        C2h = g_qrh + (size_t)zz * QQ * UU;
        bm = by * BM; bn = bx * BN;
    }
    const int lda = UU, ldb = UU, ldc = UU;
    const int nIter = UU / G_KC;   // 32

    extern __shared__ __half smh[];
    __half* As = smh;
    __half* Bs = smh + 4 * BM * G_LDSS;
    const uint32_t sA_base = smem_to_u32(As);
    const uint32_t sB_base = smem_to_u32(Bs);

    const int tid = threadIdx.x;
    const int lane = tid & 31;
    const int warp = tid >> 5;
    const int wm = warp & 1;
    const int wn = warp >> 1;
    const __half* Ag = A + (size_t)bm * lda;
    const __half* Bg = Bw + (size_t)bn * ldb;

    auto load_stage = [&](int stage, int buf) {
#pragma unroll
        for (int i = 0; i < 2; i++) {
            int idx = tid + i * 256;
            int row = idx >> 2, ch = idx & 3;
            uint32_t s = sA_base + (uint32_t)(buf * BM * G_LDSS + row * G_LDSS + ch * 8) * 2u;
            cp_async16(s, Ag + (size_t)row * lda + stage * G_KC + ch * 8);
        }
#pragma unroll
        for (int i = 0; i < 2; i++) {
            int idx = tid + i * 256;
            int row = idx >> 2, ch = idx & 3;
            uint32_t s = sB_base + (uint32_t)(buf * BN * G_LDSS + row * G_LDSS + ch * 8) * 2u;
            cp_async16(s, Bg + (size_t)row * ldb + stage * G_KC + ch * 8);
        }
    };

    float acc[MFRAG][NFRAG][4];
#pragma unroll
    for (int i = 0; i < MFRAG; i++)
#pragma unroll
        for (int j = 0; j < NFRAG; j++)
#pragma unroll
            for (int v = 0; v < 4; v++) acc[i][j][v] = 0.0f;

    load_stage(0, 0); CP_COMMIT();
    load_stage(1, 1); CP_COMMIT();
    load_stage(2, 2); CP_COMMIT();

    const uint32_t aOff = (uint32_t)((wm * WM + (lane & 15)) * G_LDSS + (lane >> 4) * 8);
    const uint32_t bOff = (uint32_t)((wn * WN + (lane & 7) + (lane >> 4) * 8) * G_LDSS +
                                     ((lane >> 3) & 1) * 8);
    const int r4 = lane >> 2;
    const int c4 = lane & 3;

    for (int it = 0; it < nIter; ++it) {
        CP_WAIT2();
        __syncthreads();
        if (it + 3 < nIter) load_stage(it + 3, (it + 3) & 3);
        CP_COMMIT();

        const uint32_t aBuf = sA_base + (uint32_t)((it & 3) * BM * G_LDSS) * 2u;
        const uint32_t bBuf = sB_base + (uint32_t)((it & 3) * BN * G_LDSS) * 2u;

#pragma unroll
        for (int ks = 0; ks < 2; ks++) {
            uint32_t af[MFRAG][4];
            uint32_t bf[NFRAG][2];
#pragma unroll
            for (int fm = 0; fm < MFRAG; fm++)
                ldsm_x4(af[fm], aBuf + (aOff + fm * 16 * G_LDSS + ks * 16) * 2u);
#pragma unroll
            for (int fp = 0; fp < NFRAG / 2; fp++) {
                uint32_t r[4];
                ldsm_x4(r, bBuf + (bOff + fp * 16 * G_LDSS + ks * 16) * 2u);
                bf[2 * fp][0] = r[0]; bf[2 * fp][1] = r[1];
                bf[2 * fp + 1][0] = r[2]; bf[2 * fp + 1][1] = r[3];
            }
#pragma unroll
            for (int fm = 0; fm < MFRAG; fm++)
#pragma unroll
                for (int fn = 0; fn < NFRAG; fn++)
                    mma_f16(acc[fm][fn], af[fm], bf[fn]);
        }
    }

    const int m0 = bm + wm * WM;
    const int n0 = bn + wn * WN;
#pragma unroll
    for (int fm = 0; fm < MFRAG; fm++) {
#pragma unroll
        for (int fn = 0; fn < NFRAG; fn++) {
            int r = m0 + fm * 16 + r4;
            int cidx = n0 + fn * 8 + c4 * 2;
            float a0 = acc[fm][fn][0], a1 = acc[fm][fn][1];
            float a2 = acc[fm][fn][2], a3 = acc[fm][fn][3];
            if (epi == 4) {
                if (cidx < UU) {
                    *(__half2*)(C2h + (size_t)r * UU + cidx) = __floats2half2_rn(a0, a1);
                    *(__half2*)(C2h + (size_t)(r + 8) * UU + cidx) = __floats2half2_rn(a2, a3);
                } else {
                    *(__half2*)(Ch + (size_t)r * UU + cidx - UU) = __floats2half2_rn(a0, a1);
                    *(__half2*)(Ch + (size_t)(r + 8) * UU + cidx - UU) = __floats2half2_rn(a2, a3);
                }
            } else if (epi == 3) {
                *(__half2*)(Ch + (size_t)r * ldc + cidx) = __floats2half2_rn(a0, a1);
                *(__half2*)(Ch + (size_t)(r + 8) * ldc + cidx) = __floats2half2_rn(a2, a3);
            } else {  // epi == 2
                float b0 = bc[cidx], b1 = bc[cidx + 1];
                float r0 = br[cidx], r1 = br[cidx + 1];
                *(__half2*)(Ch + (size_t)r * ldc + cidx) = __floats2half2_rn(a0 + b0, a1 + b1);
                *(__half2*)(Ch + (size_t)(r + 8) * ldc + cidx) = __floats2half2_rn(a2 + b0, a3 + b1);
                *(__half2*)(C2h + (size_t)r * ldc + cidx) = __floats2half2_rn(a0 + r0, a1 + r1);
                *(__half2*)(C2h + (size_t)(r + 8) * ldc + cidx) = __floats2half2_rn(a2 + r0, a3 + r1);
            }
        }
    }
}

// ---------------------------------------------------------------------------
// Sr shifted GEMM, K=64 specialized: 2 flat K-chunks, SMEM-staged coalesced
// shifted store. Grid (KL/128, QQ/128, BB*HH). SMEM 40 KB.
// ---------------------------------------------------------------------------
__global__ void __launch_bounds__(256)
sr_kernel() {
    constexpr int BM = 128, BN = 128, WM = 64, WN = 32;
    constexpr int MFRAG = WM / 16, NFRAG = WN / 8;

    const int bm = blockIdx.y * BM;
    const int bn = blockIdx.x * BN;
    if (bn + bm + BM + BN - 2 - (QQ - 1) < 0) return;  // fully below shift diagonal

    const int z = blockIdx.z;          // b*HH + h
    const int z1 = z / HH, z2 = z % HH;
    const __half* A = g_qrh + (size_t)z1 * QQ * UU + (size_t)z2 * 64;
    const __half* B = g_wrh + (size_t)z1 * KL * UU + (size_t)z2 * 64;
    __half* C = g_srh + (size_t)z * QQ * KL;

    extern __shared__ __half smh[];
    __half* As = smh;                       // [2][128][40]
    __half* Bs = smh + 2 * BM * G_LDSS;     // [2][128][40]
    const uint32_t sA_base = smem_to_u32(As);
    const uint32_t sB_base = smem_to_u32(Bs);

    const int tid = threadIdx.x;
    const int lane = tid & 31;
    const int warp = tid >> 5;
    const int wm = warp & 1;
    const int wn = warp >> 1;
    const __half* Ag = A + (size_t)bm * UU;
    const __half* Bg = B + (size_t)bn * UU;

    // load both K chunks
#pragma unroll
    for (int st = 0; st < 2; st++) {
#pragma unroll
        for (int i = 0; i < 2; i++) {
            int idx = tid + i * 256;
            int row = idx >> 2, ch = idx & 3;
            cp_async16(sA_base + (uint32_t)(st * BM * G_LDSS + row * G_LDSS + ch * 8) * 2u,
                       Ag + (size_t)row * UU + st * G_KC + ch * 8);
        }
#pragma unroll
        for (int i = 0; i < 2; i++) {
            int idx = tid + i * 256;
            int row = idx >> 2, ch = idx & 3;
            cp_async16(sB_base + (uint32_t)(st * BN * G_LDSS + row * G_LDSS + ch * 8) * 2u,
                       Bg + (size_t)row * UU + st * G_KC + ch * 8);
        }
        CP_COMMIT();
    }
    CP_WAIT0();
    __syncthreads();

    const uint32_t aOff = (uint32_t)((wm * WM + (lane & 15)) * G_LDSS + (lane >> 4) * 8);
    const uint32_t bOff = (uint32_t)((wn * WN + (lane & 7) + (lane >> 4) * 8) * G_LDSS +
                                     ((lane >> 3) & 1) * 8);
    const int r4 = lane >> 2;
    const int c4 = lane & 3;

    float acc[MFRAG][NFRAG][4];
#pragma unroll
    for (int i = 0; i < MFRAG; i++)
#pragma unroll
        for (int j = 0; j < NFRAG; j++)
#pragma unroll
            for (int v = 0; v < 4; v++) acc[i][j][v] = 0.0f;

#pragma unroll
    for (int st = 0; st < 2; st++) {
        const uint32_t aBuf = sA_base + (uint32_t)(st * BM * G_LDSS) * 2u;
        const uint32_t bBuf = sB_base + (uint32_t)(st * BN * G_LDSS) * 2u;
#pragma unroll
        for (int ks = 0; ks < 2; ks++) {
            uint32_t af[MFRAG][4];
            uint32_t bf[NFRAG][2];
#pragma unroll
            for (int fm = 0; fm < MFRAG; fm++)
                ldsm_x4(af[fm], aBuf + (aOff + fm * 16 * G_LDSS + ks * 16) * 2u);
#pragma unroll
            for (int fp = 0; fp < NFRAG / 2; fp++) {
                uint32_t r[4];
                ldsm_x4(r, bBuf + (bOff + fp * 16 * G_LDSS + ks * 16) * 2u);
                bf[2 * fp][0] = r[0]; bf[2 * fp][1] = r[1];
                bf[2 * fp + 1][0] = r[2]; bf[2 * fp + 1][1] = r[3];
            }
#pragma unroll
            for (int fm = 0; fm < MFRAG; fm++)
#pragma unroll
                for (int fn = 0; fn < NFRAG; fn++)
                    mma_f16(acc[fm][fn], af[fm], bf[fn]);
        }
    }

    // ---- stage C tile in SMEM [128][136] (reuse A/B buffers) ----
    __syncthreads();
    __half* Cs = smh;
    const int m0l = wm * WM;
    const int n0l = wn * WN;
#pragma unroll
    for (int fm = 0; fm < MFRAG; fm++) {
#pragma unroll
        for (int fn = 0; fn < NFRAG; fn++) {
            int lr = m0l + fm * 16 + r4;
            int lc = n0l + fn * 8 + 2 * c4;
            *(__half2*)(Cs + lr * 136 + lc) =
                __floats2half2_rn(acc[fm][fn][0], acc[fm][fn][1]);
            *(__half2*)(Cs + (lr + 8) * 136 + lc) =
                __floats2half2_rn(acc[fm][fn][2], acc[fm][fn][3]);
        }
    }
    __syncthreads();

    // ---- coalesced shifted store: 2 rows per pass, 128 threads per row ----
    const int col = tid & 127;
    const int off = bn - (QQ - 1) + bm;   // k of (row 0, col 0)
#pragma unroll 4
    for (int r = tid >> 7; r < 128; r += 2) {
        int k = off + r + col;            // k = bn + col - (Q-1) + (bm + r)
        if (k >= 0)
            C[(size_t)(bm + r) * KL + k] = Cs[r * 136 + col];
    }
}

// ---------------------------------------------------------------------------
// Wo GEMM (4-stage, fp32 out). Grid (8, 16, 1).
// ---------------------------------------------------------------------------
__global__ void __launch_bounds__(256)
wo_kernel(float* __restrict__ out) {
    constexpr int BM = 128, BN = 128, WM = 64, WN = 32;
    constexpr int MFRAG = WM / 16, NFRAG = WN / 8;

    const int bm = blockIdx.y * BM;
    const int bn = blockIdx.x * BN;

    extern __shared__ __half smh[];
    __half* As = smh;
    __half* Bs = smh + 4 * BM * G_LDSS;
    const uint32_t sA_base = smem_to_u32(As);
    const uint32_t sB_base = smem_to_u32(Bs);

    const int tid = threadIdx.x;
    const int lane = tid & 31;
    const int warp = tid >> 5;
    const int wm = warp & 1;
    const int wn = warp >> 1;
    const __half* Ag = g_ctxh + (size_t)bm * UU;
    const __half* Bg = g_woTh + (size_t)bn * UU;
    const int nIter = UU / G_KC;

    auto load_stage = [&](int stage, int buf) {
#pragma unroll
        for (int i = 0; i < 2; i++) {
            int idx = tid + i * 256;
            int row = idx >> 2, ch = idx & 3;
            cp_async16(sA_base + (uint32_t)(buf * BM * G_LDSS + row * G_LDSS + ch * 8) * 2u,
                       Ag + (size_t)row * UU + stage * G_KC + ch * 8);
        }
#pragma unroll
        for (int i = 0; i < 2; i++) {
            int idx = tid + i * 256;
            int row = idx >> 2, ch = idx & 3;
            cp_async16(sB_base + (uint32_t)(buf * BN * G_LDSS + row * G_LDSS + ch * 8) * 2u,
                       Bg + (size_t)row * UU + stage * G_KC + ch * 8);
        }
    };

    float acc[MFRAG][NFRAG][4];
#pragma unroll
    for (int i = 0; i < MFRAG; i++)
#pragma unroll
        for (int j = 0; j < NFRAG; j++)
#pragma unroll
            for (int v = 0; v < 4; v++) acc[i][j][v] = 0.0f;

    load_stage(0, 0); CP_COMMIT();
    load_stage(1, 1); CP_COMMIT();
    load_stage(2, 2); CP_COMMIT();

    const uint32_t aOff = (uint32_t)((wm * WM + (lane & 15)) * G_LDSS + (lane >> 4) * 8);
    const uint32_t bOff = (uint32_t)((wn * WN + (lane & 7) + (lane >> 4) * 8) * G_LDSS +
                                     ((lane >> 3) & 1) * 8);
    const int r4 = lane >> 2;
    const int c4 = lane & 3;

    for (int it = 0; it < nIter; ++it) {
        CP_WAIT2();
        __syncthreads();
        if (it + 3 < nIter) load_stage(it + 3, (it + 3) & 3);
        CP_COMMIT();

        const uint32_t aBuf = sA_base + (uint32_t)((it & 3) * BM * G_LDSS) * 2u;
        const uint32_t bBuf = sB_base + (uint32_t)((it & 3) * BN * G_LDSS) * 2u;

#pragma unroll
        for (int ks = 0; ks < 2; ks++) {
            uint32_t af[MFRAG][4];
            uint32_t bf[NFRAG][2];
#pragma unroll
            for (int fm = 0; fm < MFRAG; fm++)
                ldsm_x4(af[fm], aBuf + (aOff + fm * 16 * G_LDSS + ks * 16) * 2u);
#pragma unroll
            for (int fp = 0; fp < NFRAG / 2; fp++) {
                uint32_t r[4];
                ldsm_x4(r, bBuf + (bOff + fp * 16 * G_LDSS + ks * 16) * 2u);
                bf[2 * fp][0] = r[0]; bf[2 * fp][1] = r[1];
                bf[2 * fp + 1][0] = r[2]; bf[2 * fp + 1][1] = r[3];
            }
#pragma unroll
            for (int fm = 0; fm < MFRAG; fm++)
#pragma unroll
                for (int fn = 0; fn < NFRAG; fn++)
                    mma_f16(acc[fm][fn], af[fm], bf[fn]);
        }
    }

    const int m0 = bm + wm * WM;
    const int n0 = bn + wn * WN;
#pragma unroll
    for (int fm = 0; fm < MFRAG; fm++) {
#pragma unroll
        for (int fn = 0; fn < NFRAG; fn++) {
            int r = m0 + fm * 16 + r4;
            int cidx = n0 + fn * 8 + c4 * 2;
            *(float2*)(out + (size_t)r * UU + cidx) =
                make_float2(acc[fm][fn][0], acc[fm][fn][1]);
            *(float2*)(out + (size_t)(r + 8) * UU + cidx) =
                make_float2(acc[fm][fn][2], acc[fm][fn][3]);
        }
    }
}

// ---------------------------------------------------------------------------
// Split-K fused fp16 flash attention (unchanged from R11).
// ---------------------------------------------------------------------------
__global__ void __launch_bounds__(256, 2) flash_kernel() {
    extern __shared__ __half smh[];
    __half* sQ  = smh;                  // [128][72]
    __half* sKa = sQ  + 128 * 72;
    __half* sKb = sKa + 128 * 72;
    __half* sV  = sKb + 128 * 72;       // [128 t][72 d]
    __half* sP  = sV  + 128 * 72;       // [128][136]
    const uint32_t uQ  = smem_to_u32(sQ);
    const uint32_t uKa = smem_to_u32(sKa);
    const uint32_t uKb = smem_to_u32(sKb);
    const uint32_t uV  = smem_to_u32(sV);
    const uint32_t uP  = smem_to_u32(sP);

    const int tid = threadIdx.x, lane = tid & 31, warp = tid >> 5;
    const int r4 = lane >> 2, c4 = lane & 3;
    const int qs = (int)blockIdx.x;
    const int qt = 7 - (qs / KSPLIT);
    const int split = qs % KSPLIT;
    const int h = blockIdx.y, b = blockIdx.z;
    const int q0 = qt * 128;
    const int nT = 9 + qt;
    const int t0 = (split * nT) / KSPLIT;
    const int t1 = ((split + 1) * nT) / KSPLIT;

    const __half* gQ = g_qch + ((size_t)b * QQ + q0) * UU + h * 64;
    const __half* gK = g_kh  + (size_t)b * KL * UU + h * 64;
    const __half* gV = g_vh  + (size_t)b * KL * UU + h * 64;
    const __half* gS = g_srh + (((size_t)b * HH + h) * QQ + q0) * KL;

    auto load_k = [&](int t, uint32_t dK) {
        const __half* src = gK + (size_t)t * 128 * UU;
        int i = tid;
#pragma unroll
        for (int rep = 0; rep < 4; rep++, i += 256) {
            int r = i >> 3, c = i & 7;
            cp_async16(dK + (uint32_t)(r * 72 + c * 8) * 2u, src + (size_t)r * UU + c * 8);
        }
    };
    auto load_v = [&](int t) {
        const __half* src = gV + (size_t)t * 128 * UU;
        int i = tid;
#pragma unroll
        for (int rep = 0; rep < 4; rep++, i += 256) {
            int r = i >> 3, c = i & 7;
            cp_async16(uV + (uint32_t)(r * 72 + c * 8) * 2u, src + (size_t)r * UU + c * 8);
        }
    };
    auto load_sr = [&](int t) {
        const __half* src = gS + (size_t)t * 128;
        int i = tid;
#pragma unroll
        for (int rep = 0; rep < 8; rep++, i += 256) {
            int r = i >> 4, c = i & 15;
            cp_async16(uP + (uint32_t)(r * 136 + c * 8) * 2u, src + (size_t)r * KL + c * 8);
        }
    };

    {
        int i = tid;
#pragma unroll
        for (int rep = 0; rep < 4; rep++, i += 256) {
            int r = i >> 3, c = i & 7;
            cp_async16(uQ + (uint32_t)(r * 72 + c * 8) * 2u, gQ + (size_t)r * UU + c * 8);
        }
        load_k(t0, uKa);
        CP_COMMIT();
        load_sr(t0);
        load_v(t0);
        CP_COMMIT();
    }

    const int lr0 = warp * 16 + r4;
    const int qg0 = q0 + lr0, qg1 = qg0 + 8;

    const uint32_t aOffQ = (uint32_t)((warp * 16 + (lane & 15)) * 72 + (lane >> 4) * 8);
    const uint32_t aOffP = (uint32_t)((warp * 16 + (lane & 15)) * 136 + (lane >> 4) * 8);
    const uint32_t bOffK = (uint32_t)(((lane & 7) + (lane >> 4) * 8) * 72 + ((lane >> 3) & 1) * 8);
    const uint32_t bOffV = (uint32_t)((lane & 15) * 72 + (lane >> 4) * 8);

    float m0 = -1e30f, m1 = -1e30f, l0 = 0.f, l1 = 0.f;
    float accO[8][4];
#pragma unroll
    for (int f = 0; f < 8; f++)
#pragma unroll
        for (int v = 0; v < 4; v++) accO[f][v] = 0.f;

    for (int it = t0; it < t1; ++it) {
        const int li = it - t0;
        const uint32_t uK = (li & 1) ? uKb : uKa;
        CP_WAIT1();
        __syncthreads();

        float accS[16][4];
#pragma unroll
        for (int f = 0; f < 16; f++)
#pragma unroll
            for (int v = 0; v < 4; v++) accS[f][v] = 0.f;
#pragma unroll
        for (int ks = 0; ks < 4; ks++) {
            uint32_t a[4];
            ldsm_x4(a, uQ + (aOffQ + ks * 16) * 2u);
#pragma unroll
            for (int fp = 0; fp < 8; fp++) {
                uint32_t r[4];
                ldsm_x4(r, uK + (bOffK + fp * 16 * 72 + ks * 16) * 2u);
                uint32_t b0[2] = {r[0], r[1]};
                uint32_t b1[2] = {r[2], r[3]};
                mma_f16(accS[2 * fp], a, b0);
                mma_f16(accS[2 * fp + 1], a, b1);
            }
        }

        {
            int kn = (it + 1 < t1) ? (it + 1) : (t1 - 1);
            load_k(kn, ((li + 1) & 1) ? uKb : uKa);
            CP_COMMIT();
        }

        CP_WAIT1();
        __syncthreads();

        const int k0 = it * 128;
        const bool lastT = (it == nT - 1);
        const int lim0 = MEMN + qg0 - k0;
        const int lim1 = lim0 + 8;

        __half* p0 = sP + lr0 * 136;
        __half* p1 = p0 + 8 * 136;

        float rm0 = -1e30f, rm1 = -1e30f;
#pragma unroll
        for (int fn = 0; fn < 16; fn++) {
            int kc = fn * 8 + 2 * c4;
            float2 f0 = __half22float2(*(const __half2*)(p0 + kc));
            float2 f1 = __half22float2(*(const __half2*)(p1 + kc));
            float s0, s1, s2, s3;
            s0 = (!lastT || kc     <= lim0) ? (accS[fn][0] + f0.x) * 0.125f : -1e30f;
            s1 = (!lastT || kc + 1 <= lim0) ? (accS[fn][1] + f0.y) * 0.125f : -1e30f;
            s2 = (!lastT || kc     <= lim1) ? (accS[fn][2] + f1.x) * 0.125f : -1e30f;
            s3 = (!lastT || kc + 1 <= lim1) ? (accS[fn][3] + f1.y) * 0.125f : -1e30f;
            accS[fn][0] = s0; accS[fn][1] = s1; accS[fn][2] = s2; accS[fn][3] = s3;
            rm0 = fmaxf(rm0, fmaxf(s0, s1));
            rm1 = fmaxf(rm1, fmaxf(s2, s3));
        }
        rm0 = fmaxf(rm0, __shfl_xor_sync(~0u, rm0, 1));
        rm0 = fmaxf(rm0, __shfl_xor_sync(~0u, rm0, 2));
        rm1 = fmaxf(rm1, __shfl_xor_sync(~0u, rm1, 1));
        rm1 = fmaxf(rm1, __shfl_xor_sync(~0u, rm1, 2));
        float mN0 = fmaxf(m0, rm0), mN1 = fmaxf(m1, rm1);
        float al0 = __expf(m0 - mN0), al1 = __expf(m1 - mN1);
        m0 = mN0; m1 = mN1;

        float ps0 = 0.f, ps1 = 0.f;
#pragma unroll
        for (int fn = 0; fn < 16; fn++) {
            int kc = fn * 8 + 2 * c4;
            float e0 = __expf(accS[fn][0] - m0);
            float e1 = __expf(accS[fn][1] - m0);
            float e2 = __expf(accS[fn][2] - m1);
            float e3 = __expf(accS[fn][3] - m1);
            ps0 += e0 + e1; ps1 += e2 + e3;
            *(__half2*)(p0 + kc) = __floats2half2_rn(e0, e1);
            *(__half2*)(p1 + kc) = __floats2half2_rn(e2, e3);
        }
        ps0 += __shfl_xor_sync(~0u, ps0, 1); ps0 += __shfl_xor_sync(~0u, ps0, 2);
        ps1 += __shfl_xor_sync(~0u, ps1, 1); ps1 += __shfl_xor_sync(~0u, ps1, 2);
        l0 = l0 * al0 + ps0;
        l1 = l1 * al1 + ps1;
#pragma unroll
        for (int f = 0; f < 8; f++) {
            accO[f][0] *= al0; accO[f][1] *= al0;
            accO[f][2] *= al1; accO[f][3] *= al1;
        }
        __syncwarp();

#pragma unroll
        for (int ks = 0; ks < 8; ks++) {
            uint32_t a[4];
            ldsm_x4(a, uP + (aOffP + ks * 16) * 2u);
#pragma unroll
            for (int fp = 0; fp < 4; fp++) {
                uint32_t r[4];
                ldsm_x4t(r, uV + (bOffV + ks * 16 * 72 + fp * 16) * 2u);
                uint32_t b0[2] = {r[0], r[1]};
                uint32_t b1[2] = {r[2], r[3]};
                mma_f16(accO[2 * fp], a, b0);
                mma_f16(accO[2 * fp + 1], a, b1);
            }
        }
        __syncthreads();

        {
            int vn = (it + 1 < t1) ? (it + 1) : (t1 - 1);
            load_sr(vn);
            load_v(vn);
            CP_COMMIT();
        }
    }

    const size_t base0 = ((size_t)b * HH + h) * QQ + qg0;
    const size_t base1 = base0 + 8;
    float* o0 = g_opart + (base0 * KSPLIT + split) * DHH;
    float* o1 = g_opart + (base1 * KSPLIT + split) * DHH;
#pragma unroll
    for (int fn = 0; fn < 8; fn++) {
        int col = fn * 8 + 2 * c4;
        *(float2*)(o0 + col) = make_float2(accO[fn][0], accO[fn][1]);
        *(float2*)(o1 + col) = make_float2(accO[fn][2], accO[fn][3]);
    }
    if (c4 == 0) {
        float* ml0 = g_ml + (base0 * KSPLIT + split) * 2;
        float* ml1 = g_ml + (base1 * KSPLIT + split) * 2;
        ml0[0] = m0; ml0[1] = l0;
        ml1[0] = m1; ml1[1] = l1;
    }
}

// ---------------------------------------------------------------------------
// Combine split-K partials -> ctx (fp16)
// ---------------------------------------------------------------------------
__global__ void __launch_bounds__(256) combine_kernel() {
    const int col = threadIdx.x & 63;
    const int rloc = threadIdx.x >> 6;
    const int q = blockIdx.x * 4 + rloc;
    const int h = blockIdx.y, b = blockIdx.z;
    const size_t base = ((size_t)b * HH + h) * QQ + q;

    float m[KSPLIT], l[KSPLIT];
#pragma unroll
    for (int s = 0; s < KSPLIT; s++) {
        m[s] = g_ml[(base * KSPLIT + s) * 2 + 0];
        l[s] = g_ml[(base * KSPLIT + s) * 2 + 1];
    }
    float mx = m[0];
#pragma unroll
    for (int s = 1; s < KSPLIT; s++) mx = fmaxf(mx, m[s]);
    float w[KSPLIT], L = 0.f;
#pragma unroll
    for (int s = 0; s < KSPLIT; s++) { w[s] = __expf(m[s] - mx); L += l[s] * w[s]; }
    const float inv = 1.0f / L;

    float o = 0.f;
#pragma unroll
    for (int s = 0; s < KSPLIT; s++)
        o += g_opart[(base * KSPLIT + s) * DHH + col] * w[s];
    g_ctxh[((size_t)b * QQ + q) * UU + h * 64 + col] = __float2half(o * inv);
}

// ---------------------------------------------------------------------------
// Launch
// ---------------------------------------------------------------------------
extern "C" void kernel_launch(void* const* d_in, const int* in_sizes, int n_in,
                              void* d_out, int out_size) {
    const float* inputs    = (const float*)d_in[0];
    const float* relatives = (const float*)d_in[1];
    const float* memories  = (const float*)d_in[2];
    const float* bias_c    = (const float*)d_in[3];
    const float* bias_r    = (const float*)d_in[4];
    const float* Wq        = (const float*)d_in[5];
    const float* Wkv       = (const float*)d_in[6];
    const float* Wr        = (const float*)d_in[7];
    const float* Wo        = (const float*)d_in[8];
    float* out             = (float*)d_out;

    constexpr int SMEM_G  = 4 * (128 + 128) * G_LDSS * 2;                // 81920
    constexpr int SMEM_SR = 2 * (128 + 128) * G_LDSS * 2;                // 40960
    constexpr int SMEM_F  = (3 * 128 * 72 + 128 * 72 + 128 * 136) * 2;   // 108544
    cudaFuncSetAttribute((const void*)proj_kernel,
                         cudaFuncAttributeMaxDynamicSharedMemorySize, SMEM_G);
    cudaFuncSetAttribute((const void*)wo_kernel,
                         cudaFuncAttributeMaxDynamicSharedMemorySize, SMEM_G);
    cudaFuncSetAttribute((const void*)sr_kernel,
                         cudaFuncAttributeMaxDynamicSharedMemorySize, SMEM_SR);
    cudaFuncSetAttribute((const void*)flash_kernel,
                         cudaFuncAttributeMaxDynamicSharedMemorySize, SMEM_F);

    // 0. all weight transposes in one launch
    wtrans_kernel<<<5120, dim3(32, 8)>>>(Wq, Wkv, Wr, Wo);

    // 1. fullh = fp16(concat); relrh = fp16(relatives)
    {
        size_t total4 = (size_t)BB * KL * UU / 4;
        prep_kernel<<<(unsigned)((2 * total4 + 255) / 256), 256>>>(memories, inputs, relatives);
    }

    // 2. merged projections: wkv | wr | wq  (896 CTAs, one launch)
    proj_kernel<<<896, 256, SMEM_G>>>(bias_c, bias_r);

    // 3. SrShift = shifted (qr @ wr^T), SMEM-staged coalesced store
    sr_kernel<<<dim3(KL / 128, QQ / 128, BB * HH), 256, SMEM_SR>>>();

    // 4. split-K fused fp16 flash -> partials
    flash_kernel<<<dim3(8 * KSPLIT, HH, BB), 256, SMEM_F>>>();

    // 5. combine partials -> ctx (fp16)
    combine_kernel<<<dim3(QQ / 4, HH, BB), 256>>>();

    // 6. out = ctx @ Wo (fp32 out)
    wo_kernel<<<dim3(UU / 128, (BB * QQ) / 128, 1), 256, SMEM_G>>>(out);
}